// round 5
// baseline (speedup 1.0000x reference)
#include <cuda_runtime.h>
#include <cuda_bf16.h>
#include <cstdint>

// Problem constants (fixed by the reference)
#define N_NODES 500000
#define N_EDGES 1000000
#define D       32
#define CD      64
#define HID     128
#define NCEN    20
#define RBF_GAMMA 10.0f

#define TAB_INTERVALS 2048        // PWL intervals over len in [0,2)
#define TAB_SCALE     1024.0f     // intervals per unit length

#define FULLMASK 0xffffffffu

typedef unsigned long long ull;

// ---- device-global precomputed tables (allowed scratch) --------------------
__device__ float  g_ct[512 * 32];              // combined cat embedding [(dir*16+type)*4+ring][ch]
__device__ float4 g_tab[TAB_INTERVALS * 16];   // PWL rbf: per (interval, ch-pair): (v0,v1,dv0,dv1)

// ---- packed f32x2 helpers (sm_103a) ---------------------------------------
__device__ __forceinline__ ull ffma2(ull a, ull b, ull c) {
    ull d;
    asm("fma.rn.f32x2 %0, %1, %2, %3;" : "=l"(d) : "l"(a), "l"(b), "l"(c));
    return d;
}
__device__ __forceinline__ ull pack2(float lo, float hi) {
    ull d;
    asm("mov.b64 %0, {%1, %2};" : "=l"(d) : "f"(lo), "f"(hi));
    return d;
}
__device__ __forceinline__ void unpack2(ull v, float& lo, float& hi) {
    asm("mov.b64 {%0, %1}, %2;" : "=f"(lo), "=f"(hi) : "l"(v));
}

// ---------------------------------------------------------------------------
// Setup kernel A: combined categorical embedding table (512 combos x 32 ch)
// ---------------------------------------------------------------------------
__global__ void build_ct_kernel(const float* __restrict__ emb_dir,
                                const float* __restrict__ emb_type,
                                const float* __restrict__ emb_ring) {
    int idx = blockIdx.x * blockDim.x + threadIdx.x;
    if (idx >= 512 * 32) return;
    int l = idx & 31;
    int comb = idx >> 5;
    int ring = comb & 3;
    int type = (comb >> 2) & 15;
    int dir  = comb >> 6;
    g_ct[idx] = emb_dir[dir * 32 + l] + emb_type[type * 32 + l] + emb_ring[ring * 32 + l];
}

// ---------------------------------------------------------------------------
// Setup kernel B: PWL table for g(x) = rbf(x) @ rbf_W + rbf_b
// ---------------------------------------------------------------------------
__global__ void build_tab_kernel(const float* __restrict__ rbf_W,
                                 const float* __restrict__ rbf_b) {
    int idx = blockIdx.x * blockDim.x + threadIdx.x;
    if (idx >= TAB_INTERVALS * 16) return;
    int p = idx & 15;       // channel pair: channels 2p, 2p+1
    int i = idx >> 4;       // interval
    float x0 = (float)i / TAB_SCALE;
    float x1 = (float)(i + 1) / TAB_SCALE;
    float v00 = rbf_b[2 * p], v01 = rbf_b[2 * p + 1];
    float v10 = v00, v11 = v01;
#pragma unroll
    for (int k = 0; k < NCEN; k++) {
        float c = 0.1f * (float)k;
        float w0 = rbf_W[k * 32 + 2 * p];
        float w1 = rbf_W[k * 32 + 2 * p + 1];
        float d0 = x0 - c, d1 = x1 - c;
        float e0 = expf(-RBF_GAMMA * d0 * d0);
        float e1 = expf(-RBF_GAMMA * d1 * d1);
        v00 = fmaf(e0, w0, v00);
        v01 = fmaf(e0, w1, v01);
        v10 = fmaf(e1, w0, v10);
        v11 = fmaf(e1, w1, v11);
    }
    g_tab[idx] = make_float4(v00, v01, v10 - v00, v11 - v01);
}

// ---------------------------------------------------------------------------
// Kernel 1: zero the aggregation buffer (we reuse d_out as agg scratch)
// ---------------------------------------------------------------------------
__global__ void zero_kernel(float4* __restrict__ p, int n4) {
    int i = blockIdx.x * blockDim.x + threadIdx.x;
    int stride = gridDim.x * blockDim.x;
    float4 z = make_float4(0.f, 0.f, 0.f, 0.f);
    for (; i < n4; i += stride) p[i] = z;
}

// ---------------------------------------------------------------------------
// Kernel 2: edge message + scatter. TWO edges per warp (lanes 0-15 / 16-31),
// lane m owns channels 4m..4m+3. Manual 2-way software pipeline: all loads
// for two strided edge-pairs are issued before either REDG, and the REDG has
// NO memory clobber so the compiler can overlap across iterations.
// ---------------------------------------------------------------------------
struct EdgeVals {
    float4 a;             // gathered atom channels
    float ad0, ad1, ad2, ad3;
    long  qoff;           // agg offset
};

__device__ __forceinline__ void edge_compute(
    int e, int m, int cb, int pb, bool upper,
    const float* __restrict__ atom,
    const int* __restrict__ src,  const int* __restrict__ dst,
    const int* __restrict__ rdir, const int* __restrict__ rtype, const int* __restrict__ rring,
    const int* __restrict__ pdir, const int* __restrict__ ptype, const int* __restrict__ pring,
    const float* __restrict__ rlen, const float* __restrict__ plen,
    EdgeVals& V)
{
    const int s  = src[e];
    const int dn = dst[e];
    const int icr = (rdir[e] * 16 + rtype[e]) * 4 + rring[e];
    const int icp = (pdir[e] * 16 + ptype[e]) * 4 + pring[e];

    float xr = rlen[e] * TAB_SCALE;
    int   ir = min((int)xr, TAB_INTERVALS - 1);
    float fr = xr - (float)ir;
    float xp = plen[e] * TAB_SCALE;
    int   ip = min((int)xp, TAB_INTERVALS - 1);
    float fp_ = xp - (float)ip;

    float4 ctr = *reinterpret_cast<const float4*>(&g_ct[icr * 32 + cb]);
    float4 ctp = *reinterpret_cast<const float4*>(&g_ct[icp * 32 + cb]);
    float4 t0r = g_tab[ir * 16 + pb];
    float4 t1r = g_tab[ir * 16 + pb + 1];
    float4 t0p = g_tab[ip * 16 + pb];
    float4 t1p = g_tab[ip * 16 + pb + 1];

    V.a = *reinterpret_cast<const float4*>(&atom[(size_t)s * CD + 4 * m]);

    float re0 = ctr.x + fmaf(fr, t0r.z, t0r.x);
    float re1 = ctr.y + fmaf(fr, t0r.w, t0r.y);
    float re2 = ctr.z + fmaf(fr, t1r.z, t1r.x);
    float re3 = ctr.w + fmaf(fr, t1r.w, t1r.y);

    float pe0 = ctp.x + fmaf(fp_, t0p.z, t0p.x);
    float pe1 = ctp.y + fmaf(fp_, t0p.w, t0p.y);
    float pe2 = ctp.z + fmaf(fp_, t1p.z, t1p.x);
    float pe3 = ctp.w + fmaf(fp_, t1p.w, t1p.y);

    V.ad0 = upper ? (pe0 - re0) : re0;
    V.ad1 = upper ? (pe1 - re1) : re1;
    V.ad2 = upper ? (pe2 - re2) : re2;
    V.ad3 = upper ? (pe3 - re3) : re3;
    V.qoff = (long)dn * CD + 4 * m;
}

__device__ __forceinline__ void edge_commit(float* agg, const EdgeVals& V) {
    float v0 = V.a.x + V.ad0;
    float v1 = V.a.y + V.ad1;
    float v2 = V.a.z + V.ad2;
    float v3 = V.a.w + V.ad3;
    float* q = agg + V.qoff;
    asm volatile("red.global.add.v4.f32 [%0], {%1,%2,%3,%4};"
                 :: "l"(q), "f"(v0), "f"(v1), "f"(v2), "f"(v3));
}

__global__ void edge_kernel(
    const float* __restrict__ atom,
    const int*   __restrict__ src,  const int* __restrict__ dst,
    const int*   __restrict__ rdir, const int* __restrict__ rtype, const int* __restrict__ rring,
    const int*   __restrict__ pdir, const int* __restrict__ ptype, const int* __restrict__ pring,
    const float* __restrict__ rlen, const float* __restrict__ plen,
    float* __restrict__ agg)
{
    const int l = threadIdx.x & 31;
    const int g = l >> 4;                 // edge group within warp
    const int m = l & 15;                 // lane within group
    const bool upper = (m >= 8);          // owns channels 32..63 (the p-r half)
    const int cb = (4 * m) & 31;          // channel base within 32-wide embed
    const int pb = cb >> 1;               // pair base (even, 0..14)
    const int warp = (blockIdx.x * blockDim.x + threadIdx.x) >> 5;
    const int nwarps = (gridDim.x * blockDim.x) >> 5;
    const int stride = nwarps * 2;

    for (int e = warp * 2 + g; e < N_EDGES; e += 2 * stride) {
        int e1 = e + stride;
        EdgeVals V0, V1;
        edge_compute(e, m, cb, pb, upper, atom, src, dst,
                     rdir, rtype, rring, pdir, ptype, pring, rlen, plen, V0);
        bool has1 = (e1 < N_EDGES);
        if (has1)
            edge_compute(e1, m, cb, pb, upper, atom, src, dst,
                         rdir, rtype, rring, pdir, ptype, pring, rlen, plen, V1);
        edge_commit(agg, V0);
        if (has1) edge_commit(agg, V1);
    }
}

// ---------------------------------------------------------------------------
// Kernel 3: per-node MLP, in place. FOUR threads per node: quarter q owns
// channels 16q..16q+15 for inputs and outputs. Two shfl.xor (1,2) combine
// stage-1 partials. ~60 regs/thread -> 256-thread blocks, 3 blocks/SM by
// smem -> 24 warps/SM. Quarter-panels skewed 16B so the 4 broadcast
// addresses per LDS.128 are bank-disjoint.
// ---------------------------------------------------------------------------
#define QPANEL (HID * 16 + 4)   // 2052 floats per quarter panel (16B skew)

__global__ __launch_bounds__(256) void mlp_kernel(
    float* __restrict__ inout,           // [N_NODES, CD], agg in, out out
    const float* __restrict__ W1,        // [CD, HID]
    const float* __restrict__ b1,        // [HID]
    const float* __restrict__ W2,        // [HID, CD]
    const float* __restrict__ b2)        // [CD]
{
    extern __shared__ float sm[];
    float* sW1 = sm;                     // 4 quarter panels [128][16], W1[j][i] at [q][i*16+jj]
    float* sW2 = sW1 + 4 * QPANEL;       // 4 quarter panels [128][16], W2[i][c] at [q][i*16+cc]
    float* sb1 = sW2 + 4 * QPANEL;       // [128]
    float* sb2 = sb1 + HID;              // [64]

    const int tid = threadIdx.x;

    // Stage weights into quarter panels.
    for (int idx = tid; idx < CD * HID; idx += blockDim.x) {
        int j = idx >> 7;        // 0..63
        int i = idx & 127;       // 0..127
        sW1[(j >> 4) * QPANEL + i * 16 + (j & 15)] = W1[idx];
    }
    for (int idx = tid; idx < HID * CD; idx += blockDim.x) {
        int i = idx >> 6;        // 0..127
        int c = idx & 63;        // 0..63
        sW2[(c >> 4) * QPANEL + i * 16 + (c & 15)] = W2[idx];
    }
    if (tid < HID) sb1[tid] = b1[tid];
    if (tid < CD)  sb2[tid] = b2[tid];
    __syncthreads();

    const int q4   = tid & 3;            // quarter: channels 16q..16q+15
    const int slot = tid >> 2;           // node slot within block (0..63)
    const float* w1p = sW1 + q4 * QPANEL;
    const float* w2p = sW2 + q4 * QPANEL;

    for (long n = (long)blockIdx.x * 64 + slot; n < N_NODES;
         n += (long)gridDim.x * 64) {
        float* row = inout + n * CD + q4 * 16;   // this thread's 16 channels

        // activations (my quarter): 16 floats = 8 packed pairs
        ull a[8];
        {
            const ulonglong2* ar = reinterpret_cast<const ulonglong2*>(row);
#pragma unroll
            for (int k = 0; k < 4; k++) {
                ulonglong2 v = ar[k];
                a[2 * k]     = v.x;
                a[2 * k + 1] = v.y;
            }
        }
        // output accumulators init = my quarter of b2
        ull o[8];
        {
            const ulonglong2* bp =
                reinterpret_cast<const ulonglong2*>(sb2 + q4 * 16);
#pragma unroll
            for (int k = 0; k < 4; k++) {
                ulonglong2 v = bp[k];
                o[2 * k]     = v.x;
                o[2 * k + 1] = v.y;
            }
        }

#pragma unroll 4
        for (int i = 0; i < HID; i++) {
            // partial_i = sum over my 16 j of a[j]*W1[j][i]
            const ulonglong2* w1r =
                reinterpret_cast<const ulonglong2*>(w1p + i * 16);
            ull acc0 = 0ull, acc1 = 0ull;
#pragma unroll
            for (int k = 0; k < 2; k++) {
                ulonglong2 wA = w1r[2 * k];
                ulonglong2 wB = w1r[2 * k + 1];
                acc0 = ffma2(a[4 * k],     wA.x, acc0);
                acc1 = ffma2(a[4 * k + 1], wA.y, acc1);
                acc0 = ffma2(a[4 * k + 2], wB.x, acc0);
                acc1 = ffma2(a[4 * k + 3], wB.y, acc1);
            }
            float x0, x1, y0, y1;
            unpack2(acc0, x0, x1);
            unpack2(acc1, y0, y1);
            float part = (x0 + y0) + (x1 + y1);
            part += __shfl_xor_sync(FULLMASK, part, 1);
            part += __shfl_xor_sync(FULLMASK, part, 2);
            float h = fmaxf(part + sb1[i], 0.f);
            ull hh = pack2(h, h);

            // out[my 16 c] += h * W2[i][c]
            const ulonglong2* w2r =
                reinterpret_cast<const ulonglong2*>(w2p + i * 16);
#pragma unroll
            for (int k = 0; k < 4; k++) {
                ulonglong2 w = w2r[k];
                o[2 * k]     = ffma2(hh, w.x, o[2 * k]);
                o[2 * k + 1] = ffma2(hh, w.y, o[2 * k + 1]);
            }
        }

        // relu + store my quarter
        float4* outv = reinterpret_cast<float4*>(row);
#pragma unroll
        for (int k = 0; k < 4; k++) {
            float x0, x1, x2, x3;
            unpack2(o[2 * k],     x0, x1);
            unpack2(o[2 * k + 1], x2, x3);
            float4 r;
            r.x = fmaxf(x0, 0.f);
            r.y = fmaxf(x1, 0.f);
            r.z = fmaxf(x2, 0.f);
            r.w = fmaxf(x3, 0.f);
            outv[k] = r;
        }
    }
}

// ---------------------------------------------------------------------------
// Launch
// Inputs (metadata order):
//  0 atom_repr [N,64] f32     1 src [E] i32      2 dst [E] i32
//  3 r_dir     4 r_type       5 r_ring           6 p_dir
//  7 p_type    8 p_ring       9 r_len f32       10 p_len f32
// 11 emb_dir [8,32]          12 emb_type [16,32] 13 emb_ring [4,32]
// 14 rbf_W [20,32]           15 rbf_b [32]
// 16 W1 [64,128]             17 b1 [128]
// 18 W2 [128,64]             19 b2 [64]
// Output: [N,64] f32
// ---------------------------------------------------------------------------
extern "C" void kernel_launch(void* const* d_in, const int* in_sizes, int n_in,
                              void* d_out, int out_size) {
    const float* atom     = (const float*)d_in[0];
    const int*   src      = (const int*)d_in[1];
    const int*   dst      = (const int*)d_in[2];
    const int*   rdir     = (const int*)d_in[3];
    const int*   rtype    = (const int*)d_in[4];
    const int*   rring    = (const int*)d_in[5];
    const int*   pdir     = (const int*)d_in[6];
    const int*   ptype    = (const int*)d_in[7];
    const int*   pring    = (const int*)d_in[8];
    const float* rlen     = (const float*)d_in[9];
    const float* plen     = (const float*)d_in[10];
    const float* emb_dir  = (const float*)d_in[11];
    const float* emb_type = (const float*)d_in[12];
    const float* emb_ring = (const float*)d_in[13];
    const float* rbf_W    = (const float*)d_in[14];
    const float* rbf_b    = (const float*)d_in[15];
    const float* W1       = (const float*)d_in[16];
    const float* b1       = (const float*)d_in[17];
    const float* W2       = (const float*)d_in[18];
    const float* b2       = (const float*)d_in[19];
    float* out = (float*)d_out;

    // 0) build lookup tables (tiny)
    build_ct_kernel<<<(512 * 32 + 255) / 256, 256>>>(emb_dir, emb_type, emb_ring);
    build_tab_kernel<<<(TAB_INTERVALS * 16 + 255) / 256, 256>>>(rbf_W, rbf_b);

    // 1) zero the agg buffer (= d_out)
    int n4 = (N_NODES * CD) / 4;
    zero_kernel<<<4096, 256>>>((float4*)out, n4);

    // 2) edge scatter (2 edges/warp, 2-way software pipeline)
    edge_kernel<<<2048, 256>>>(atom, src, dst, rdir, rtype, rring,
                               pdir, ptype, pring, rlen, plen, out);

    // 3) node MLP (in place), 4 threads per node, grid-stride
    size_t smem = (size_t)(8 * QPANEL + HID + CD) * sizeof(float);
    cudaFuncSetAttribute(mlp_kernel, cudaFuncAttributeMaxDynamicSharedMemorySize,
                         (int)smem);
    mlp_kernel<<<444, 256, smem>>>(out, W1, b1, W2, b2);
}

// round 6
// speedup vs baseline: 1.3717x; 1.3717x over previous
#include <cuda_runtime.h>
#include <cuda_bf16.h>
#include <cstdint>

// Problem constants (fixed by the reference)
#define N_NODES 500000
#define N_EDGES 1000000
#define D       32
#define CD      64
#define HID     128
#define NCEN    20
#define RBF_GAMMA 10.0f

#define TAB_INTERVALS 2048        // PWL intervals over len in [0,2)
#define TAB_SCALE     1024.0f     // intervals per unit length

#define FULLMASK 0xffffffffu

typedef unsigned long long ull;

// ---- device-global precomputed tables (allowed scratch) --------------------
__device__ float  g_ct[512 * 32];              // combined cat embedding [(dir*16+type)*4+ring][ch]
__device__ float4 g_tab[TAB_INTERVALS * 16];   // PWL rbf: per (interval, ch-pair): (v0,v1,dv0,dv1)

// ---- packed f32x2 helpers (sm_103a) ---------------------------------------
__device__ __forceinline__ ull ffma2(ull a, ull b, ull c) {
    ull d;
    asm("fma.rn.f32x2 %0, %1, %2, %3;" : "=l"(d) : "l"(a), "l"(b), "l"(c));
    return d;
}
__device__ __forceinline__ ull pack2(float lo, float hi) {
    ull d;
    asm("mov.b64 %0, {%1, %2};" : "=l"(d) : "f"(lo), "f"(hi));
    return d;
}
__device__ __forceinline__ void unpack2(ull v, float& lo, float& hi) {
    asm("mov.b64 {%0, %1}, %2;" : "=f"(lo), "=f"(hi) : "l"(v));
}

// ---------------------------------------------------------------------------
// Setup kernel A: combined categorical embedding table (512 combos x 32 ch)
// ---------------------------------------------------------------------------
__global__ void build_ct_kernel(const float* __restrict__ emb_dir,
                                const float* __restrict__ emb_type,
                                const float* __restrict__ emb_ring) {
    int idx = blockIdx.x * blockDim.x + threadIdx.x;
    if (idx >= 512 * 32) return;
    int l = idx & 31;
    int comb = idx >> 5;
    int ring = comb & 3;
    int type = (comb >> 2) & 15;
    int dir  = comb >> 6;
    g_ct[idx] = emb_dir[dir * 32 + l] + emb_type[type * 32 + l] + emb_ring[ring * 32 + l];
}

// ---------------------------------------------------------------------------
// Setup kernel B: PWL table for g(x) = rbf(x) @ rbf_W + rbf_b
// ---------------------------------------------------------------------------
__global__ void build_tab_kernel(const float* __restrict__ rbf_W,
                                 const float* __restrict__ rbf_b) {
    int idx = blockIdx.x * blockDim.x + threadIdx.x;
    if (idx >= TAB_INTERVALS * 16) return;
    int p = idx & 15;       // channel pair: channels 2p, 2p+1
    int i = idx >> 4;       // interval
    float x0 = (float)i / TAB_SCALE;
    float x1 = (float)(i + 1) / TAB_SCALE;
    float v00 = rbf_b[2 * p], v01 = rbf_b[2 * p + 1];
    float v10 = v00, v11 = v01;
#pragma unroll
    for (int k = 0; k < NCEN; k++) {
        float c = 0.1f * (float)k;
        float w0 = rbf_W[k * 32 + 2 * p];
        float w1 = rbf_W[k * 32 + 2 * p + 1];
        float d0 = x0 - c, d1 = x1 - c;
        float e0 = expf(-RBF_GAMMA * d0 * d0);
        float e1 = expf(-RBF_GAMMA * d1 * d1);
        v00 = fmaf(e0, w0, v00);
        v01 = fmaf(e0, w1, v01);
        v10 = fmaf(e1, w0, v10);
        v11 = fmaf(e1, w1, v11);
    }
    g_tab[idx] = make_float4(v00, v01, v10 - v00, v11 - v01);
}

// ---------------------------------------------------------------------------
// Kernel 1: zero the aggregation buffer (we reuse d_out as agg scratch)
// ---------------------------------------------------------------------------
__global__ void zero_kernel(float4* __restrict__ p, int n4) {
    int i = blockIdx.x * blockDim.x + threadIdx.x;
    int stride = gridDim.x * blockDim.x;
    float4 z = make_float4(0.f, 0.f, 0.f, 0.f);
    for (; i < n4; i += stride) p[i] = z;
}

// ---------------------------------------------------------------------------
// Kernel 2: edge message + scatter. TWO edges per warp (lanes 0-15 / 16-31),
// lane m owns channels 4m..4m+3. 4-deep software pipeline: loads for four
// strided edges are issued before any REDG; REDG carries no memory clobber.
// ---------------------------------------------------------------------------
struct EdgeVals {
    float4 a;             // gathered atom channels
    float ad0, ad1, ad2, ad3;
    long  qoff;           // agg offset
};

__device__ __forceinline__ void edge_compute(
    int e, int m, int cb, int pb, bool upper,
    const float* __restrict__ atom,
    const int* __restrict__ src,  const int* __restrict__ dst,
    const int* __restrict__ rdir, const int* __restrict__ rtype, const int* __restrict__ rring,
    const int* __restrict__ pdir, const int* __restrict__ ptype, const int* __restrict__ pring,
    const float* __restrict__ rlen, const float* __restrict__ plen,
    EdgeVals& V)
{
    const int s  = src[e];
    const int dn = dst[e];
    const int icr = (rdir[e] * 16 + rtype[e]) * 4 + rring[e];
    const int icp = (pdir[e] * 16 + ptype[e]) * 4 + pring[e];

    float xr = rlen[e] * TAB_SCALE;
    int   ir = min((int)xr, TAB_INTERVALS - 1);
    float fr = xr - (float)ir;
    float xp = plen[e] * TAB_SCALE;
    int   ip = min((int)xp, TAB_INTERVALS - 1);
    float fp_ = xp - (float)ip;

    float4 ctr = *reinterpret_cast<const float4*>(&g_ct[icr * 32 + cb]);
    float4 ctp = *reinterpret_cast<const float4*>(&g_ct[icp * 32 + cb]);
    float4 t0r = g_tab[ir * 16 + pb];
    float4 t1r = g_tab[ir * 16 + pb + 1];
    float4 t0p = g_tab[ip * 16 + pb];
    float4 t1p = g_tab[ip * 16 + pb + 1];

    V.a = *reinterpret_cast<const float4*>(&atom[(size_t)s * CD + 4 * m]);

    float re0 = ctr.x + fmaf(fr, t0r.z, t0r.x);
    float re1 = ctr.y + fmaf(fr, t0r.w, t0r.y);
    float re2 = ctr.z + fmaf(fr, t1r.z, t1r.x);
    float re3 = ctr.w + fmaf(fr, t1r.w, t1r.y);

    float pe0 = ctp.x + fmaf(fp_, t0p.z, t0p.x);
    float pe1 = ctp.y + fmaf(fp_, t0p.w, t0p.y);
    float pe2 = ctp.z + fmaf(fp_, t1p.z, t1p.x);
    float pe3 = ctp.w + fmaf(fp_, t1p.w, t1p.y);

    V.ad0 = upper ? (pe0 - re0) : re0;
    V.ad1 = upper ? (pe1 - re1) : re1;
    V.ad2 = upper ? (pe2 - re2) : re2;
    V.ad3 = upper ? (pe3 - re3) : re3;
    V.qoff = (long)dn * CD + 4 * m;
}

__device__ __forceinline__ void edge_commit(float* agg, const EdgeVals& V) {
    float v0 = V.a.x + V.ad0;
    float v1 = V.a.y + V.ad1;
    float v2 = V.a.z + V.ad2;
    float v3 = V.a.w + V.ad3;
    float* q = agg + V.qoff;
    asm volatile("red.global.add.v4.f32 [%0], {%1,%2,%3,%4};"
                 :: "l"(q), "f"(v0), "f"(v1), "f"(v2), "f"(v3));
}

__global__ void edge_kernel(
    const float* __restrict__ atom,
    const int*   __restrict__ src,  const int* __restrict__ dst,
    const int*   __restrict__ rdir, const int* __restrict__ rtype, const int* __restrict__ rring,
    const int*   __restrict__ pdir, const int* __restrict__ ptype, const int* __restrict__ pring,
    const float* __restrict__ rlen, const float* __restrict__ plen,
    float* __restrict__ agg)
{
    const int l = threadIdx.x & 31;
    const int g = l >> 4;                 // edge group within warp
    const int m = l & 15;                 // lane within group
    const bool upper = (m >= 8);          // owns channels 32..63 (the p-r half)
    const int cb = (4 * m) & 31;          // channel base within 32-wide embed
    const int pb = cb >> 1;               // pair base (even, 0..14)
    const int warp = (blockIdx.x * blockDim.x + threadIdx.x) >> 5;
    const int nwarps = (gridDim.x * blockDim.x) >> 5;
    const int S = nwarps * 2;             // edge stride between pipeline slots

    for (int e = warp * 2 + g; e < N_EDGES; e += 4 * S) {
        EdgeVals V[4];
        bool h[4];
#pragma unroll
        for (int k = 0; k < 4; k++) {
            int ek = e + k * S;
            h[k] = (ek < N_EDGES);
            if (h[k])
                edge_compute(ek, m, cb, pb, upper, atom, src, dst,
                             rdir, rtype, rring, pdir, ptype, pring,
                             rlen, plen, V[k]);
        }
#pragma unroll
        for (int k = 0; k < 4; k++)
            if (h[k]) edge_commit(agg, V[k]);
    }
}

// ---------------------------------------------------------------------------
// Kernel 3: per-node MLP, in place. TWO THREADS per node (known-good R4
// layout): even lane owns channels 0..31, odd lane 32..63; one shfl.xor(1)
// per hidden unit. 192-thread blocks -> 3 blocks/SM by smem -> 18 warps/SM
// (was 12), regs safely under the 64k/SM file.
// ---------------------------------------------------------------------------
#define PANEL (HID * 32 + 4)   // 4100 floats per panel incl. 16B skew pad
#define MLP_THREADS 192
#define NODES_PER_BLOCK (MLP_THREADS / 2)

__global__ __launch_bounds__(MLP_THREADS) void mlp_kernel(
    float* __restrict__ inout,           // [N_NODES, CD], agg in, out out
    const float* __restrict__ W1,        // [CD, HID]
    const float* __restrict__ b1,        // [HID]
    const float* __restrict__ W2,        // [HID, CD]
    const float* __restrict__ b2)        // [CD]
{
    extern __shared__ float sm[];
    float* sW1E = sm;                    // [128][32]: W1[j][i], j<32  (indexed [i*32+j])
    float* sW1O = sW1E + PANEL;          // j>=32
    float* sW2E = sW1O + PANEL;          // [128][32]: W2[i][c], c<32 (indexed [i*32+c])
    float* sW2O = sW2E + PANEL;          // c>=32
    float* sb1  = sW2O + PANEL;          // [128]
    float* sb2  = sb1 + HID;             // [64]

    const int tid = threadIdx.x;

    // W1 [64][128] j-major -> split panels, transposed to i-major rows of 32.
    for (int idx = tid; idx < CD * HID; idx += blockDim.x) {
        int j = idx >> 7;        // 0..63
        int i = idx & 127;       // 0..127
        float v = W1[idx];
        if (j < 32) sW1E[i * 32 + j] = v;
        else        sW1O[i * 32 + (j - 32)] = v;
    }
    // W2 [128][64] i-major -> split halves.
    for (int idx = tid; idx < HID * CD; idx += blockDim.x) {
        int i = idx >> 6;        // 0..127
        int c = idx & 63;        // 0..63
        float v = W2[idx];
        if (c < 32) sW2E[i * 32 + c] = v;
        else        sW2O[i * 32 + (c - 32)] = v;
    }
    if (tid < HID) sb1[tid] = b1[tid];
    if (tid < CD)  sb2[tid] = b2[tid];
    __syncthreads();

    const int half = tid & 1;            // 0: channels 0..31, 1: channels 32..63
    const int slot = tid >> 1;           // node slot within block
    const float* w1p = half ? sW1O : sW1E;
    const float* w2p = half ? sW2O : sW2E;

    for (long n = (long)blockIdx.x * NODES_PER_BLOCK + slot; n < N_NODES;
         n += (long)gridDim.x * NODES_PER_BLOCK) {
        float* row = inout + n * CD + half * 32;   // this thread's 32 channels

        // activations (my half of the row): 32 floats = 16 packed pairs
        ull a[16];
        {
            const ulonglong2* ar = reinterpret_cast<const ulonglong2*>(row);
#pragma unroll
            for (int k = 0; k < 8; k++) {
                ulonglong2 v = ar[k];
                a[2 * k]     = v.x;
                a[2 * k + 1] = v.y;
            }
        }
        // output accumulators init = my half of b2
        ull o[16];
        {
            const ulonglong2* bp =
                reinterpret_cast<const ulonglong2*>(sb2 + half * 32);
#pragma unroll
            for (int k = 0; k < 8; k++) {
                ulonglong2 v = bp[k];
                o[2 * k]     = v.x;
                o[2 * k + 1] = v.y;
            }
        }

#pragma unroll 2
        for (int i = 0; i < HID; i++) {
            // partial_i = sum over my 32 j of a[j]*W1[j][i]
            const ulonglong2* w1r =
                reinterpret_cast<const ulonglong2*>(w1p + i * 32);
            ull acc0 = 0ull, acc1 = 0ull;
#pragma unroll
            for (int q = 0; q < 4; q++) {
                ulonglong2 wA = w1r[2 * q];
                ulonglong2 wB = w1r[2 * q + 1];
                acc0 = ffma2(a[4 * q],     wA.x, acc0);
                acc1 = ffma2(a[4 * q + 1], wA.y, acc1);
                acc0 = ffma2(a[4 * q + 2], wB.x, acc0);
                acc1 = ffma2(a[4 * q + 3], wB.y, acc1);
            }
            float x0, x1, y0, y1;
            unpack2(acc0, x0, x1);
            unpack2(acc1, y0, y1);
            float part = (x0 + y0) + (x1 + y1);
            float h = part + __shfl_xor_sync(FULLMASK, part, 1) + sb1[i];
            h = fmaxf(h, 0.f);
            ull hh = pack2(h, h);

            // out[my 32 c] += h * W2[i][c]
            const ulonglong2* w2r =
                reinterpret_cast<const ulonglong2*>(w2p + i * 32);
#pragma unroll
            for (int q = 0; q < 8; q++) {
                ulonglong2 w = w2r[q];
                o[2 * q]     = ffma2(hh, w.x, o[2 * q]);
                o[2 * q + 1] = ffma2(hh, w.y, o[2 * q + 1]);
            }
        }

        // relu + store my half
        float4* outv = reinterpret_cast<float4*>(row);
#pragma unroll
        for (int k = 0; k < 8; k++) {
            float x0, x1, x2, x3;
            unpack2(o[2 * k],     x0, x1);
            unpack2(o[2 * k + 1], x2, x3);
            float4 r;
            r.x = fmaxf(x0, 0.f);
            r.y = fmaxf(x1, 0.f);
            r.z = fmaxf(x2, 0.f);
            r.w = fmaxf(x3, 0.f);
            outv[k] = r;
        }
    }
}

// ---------------------------------------------------------------------------
// Launch
// Inputs (metadata order):
//  0 atom_repr [N,64] f32     1 src [E] i32      2 dst [E] i32
//  3 r_dir     4 r_type       5 r_ring           6 p_dir
//  7 p_type    8 p_ring       9 r_len f32       10 p_len f32
// 11 emb_dir [8,32]          12 emb_type [16,32] 13 emb_ring [4,32]
// 14 rbf_W [20,32]           15 rbf_b [32]
// 16 W1 [64,128]             17 b1 [128]
// 18 W2 [128,64]             19 b2 [64]
// Output: [N,64] f32
// ---------------------------------------------------------------------------
extern "C" void kernel_launch(void* const* d_in, const int* in_sizes, int n_in,
                              void* d_out, int out_size) {
    const float* atom     = (const float*)d_in[0];
    const int*   src      = (const int*)d_in[1];
    const int*   dst      = (const int*)d_in[2];
    const int*   rdir     = (const int*)d_in[3];
    const int*   rtype    = (const int*)d_in[4];
    const int*   rring    = (const int*)d_in[5];
    const int*   pdir     = (const int*)d_in[6];
    const int*   ptype    = (const int*)d_in[7];
    const int*   pring    = (const int*)d_in[8];
    const float* rlen     = (const float*)d_in[9];
    const float* plen     = (const float*)d_in[10];
    const float* emb_dir  = (const float*)d_in[11];
    const float* emb_type = (const float*)d_in[12];
    const float* emb_ring = (const float*)d_in[13];
    const float* rbf_W    = (const float*)d_in[14];
    const float* rbf_b    = (const float*)d_in[15];
    const float* W1       = (const float*)d_in[16];
    const float* b1       = (const float*)d_in[17];
    const float* W2       = (const float*)d_in[18];
    const float* b2       = (const float*)d_in[19];
    float* out = (float*)d_out;

    // 0) build lookup tables (tiny)
    build_ct_kernel<<<(512 * 32 + 255) / 256, 256>>>(emb_dir, emb_type, emb_ring);
    build_tab_kernel<<<(TAB_INTERVALS * 16 + 255) / 256, 256>>>(rbf_W, rbf_b);

    // 1) zero the agg buffer (= d_out)
    int n4 = (N_NODES * CD) / 4;
    zero_kernel<<<4096, 256>>>((float4*)out, n4);

    // 2) edge scatter (2 edges/warp, 4-deep software pipeline)
    edge_kernel<<<2048, 256>>>(atom, src, dst, rdir, rtype, rring,
                               pdir, ptype, pring, rlen, plen, out);

    // 3) node MLP (in place), 2 threads per node, 192-thr blocks, grid-stride
    size_t smem = (size_t)(4 * PANEL + HID + CD) * sizeof(float);
    cudaFuncSetAttribute(mlp_kernel, cudaFuncAttributeMaxDynamicSharedMemorySize,
                         (int)smem);
    mlp_kernel<<<444, MLP_THREADS, smem>>>(out, W1, b1, W2, b2);
}

// round 7
// speedup vs baseline: 1.8779x; 1.3691x over previous
#include <cuda_runtime.h>
#include <cuda_bf16.h>
#include <cstdint>

// Problem constants (fixed by the reference)
#define N_NODES 500000
#define N_EDGES 1000000
#define D       32
#define CD      64
#define HID     128
#define NCEN    20
#define RBF_GAMMA 10.0f

#define TAB_INTERVALS 2048        // PWL intervals over len in [0,2)
#define TAB_SCALE     1024.0f     // intervals per unit length

#define FULLMASK 0xffffffffu

typedef unsigned long long ull;

// ---- device-global precomputed tables (allowed scratch) --------------------
__device__ float  g_ct[512 * 32];              // combined cat embedding [(dir*16+type)*4+ring][ch]
__device__ float4 g_tab[TAB_INTERVALS * 16];   // PWL rbf: per (interval, ch-pair): (v0,v1,dv0,dv1)

// ---- packed f32x2 helpers (sm_103a) ---------------------------------------
__device__ __forceinline__ ull ffma2(ull a, ull b, ull c) {
    ull d;
    asm("fma.rn.f32x2 %0, %1, %2, %3;" : "=l"(d) : "l"(a), "l"(b), "l"(c));
    return d;
}
__device__ __forceinline__ ull pack2(float lo, float hi) {
    ull d;
    asm("mov.b64 %0, {%1, %2};" : "=l"(d) : "f"(lo), "f"(hi));
    return d;
}
__device__ __forceinline__ void unpack2(ull v, float& lo, float& hi) {
    asm("mov.b64 {%0, %1}, %2;" : "=f"(lo), "=f"(hi) : "l"(v));
}

// ---------------------------------------------------------------------------
// Setup kernel A: combined categorical embedding table (512 combos x 32 ch)
// ---------------------------------------------------------------------------
__global__ void build_ct_kernel(const float* __restrict__ emb_dir,
                                const float* __restrict__ emb_type,
                                const float* __restrict__ emb_ring) {
    int idx = blockIdx.x * blockDim.x + threadIdx.x;
    if (idx >= 512 * 32) return;
    int l = idx & 31;
    int comb = idx >> 5;
    int ring = comb & 3;
    int type = (comb >> 2) & 15;
    int dir  = comb >> 6;
    g_ct[idx] = emb_dir[dir * 32 + l] + emb_type[type * 32 + l] + emb_ring[ring * 32 + l];
}

// ---------------------------------------------------------------------------
// Setup kernel B: PWL table for g(x) = rbf(x) @ rbf_W + rbf_b
// ---------------------------------------------------------------------------
__global__ void build_tab_kernel(const float* __restrict__ rbf_W,
                                 const float* __restrict__ rbf_b) {
    int idx = blockIdx.x * blockDim.x + threadIdx.x;
    if (idx >= TAB_INTERVALS * 16) return;
    int p = idx & 15;       // channel pair: channels 2p, 2p+1
    int i = idx >> 4;       // interval
    float x0 = (float)i / TAB_SCALE;
    float x1 = (float)(i + 1) / TAB_SCALE;
    float v00 = rbf_b[2 * p], v01 = rbf_b[2 * p + 1];
    float v10 = v00, v11 = v01;
#pragma unroll
    for (int k = 0; k < NCEN; k++) {
        float c = 0.1f * (float)k;
        float w0 = rbf_W[k * 32 + 2 * p];
        float w1 = rbf_W[k * 32 + 2 * p + 1];
        float d0 = x0 - c, d1 = x1 - c;
        float e0 = expf(-RBF_GAMMA * d0 * d0);
        float e1 = expf(-RBF_GAMMA * d1 * d1);
        v00 = fmaf(e0, w0, v00);
        v01 = fmaf(e0, w1, v01);
        v10 = fmaf(e1, w0, v10);
        v11 = fmaf(e1, w1, v11);
    }
    g_tab[idx] = make_float4(v00, v01, v10 - v00, v11 - v01);
}

// ---------------------------------------------------------------------------
// Kernel 1: zero the aggregation buffer (we reuse d_out as agg scratch)
// ---------------------------------------------------------------------------
__global__ void zero_kernel(float4* __restrict__ p, int n4) {
    int i = blockIdx.x * blockDim.x + threadIdx.x;
    int stride = gridDim.x * blockDim.x;
    float4 z = make_float4(0.f, 0.f, 0.f, 0.f);
    for (; i < n4; i += stride) p[i] = z;
}

// ---------------------------------------------------------------------------
// Kernel 2: edge message + scatter. TWO edges per warp (lanes 0-15 / 16-31),
// lane m owns channels 4m..4m+3. 2-deep software pipeline (R5 config: best
// measured 224us). __launch_bounds__(256,4) caps regs at 64 -> 32 warps/SM.
// ---------------------------------------------------------------------------
struct EdgeVals {
    float4 a;             // gathered atom channels
    float ad0, ad1, ad2, ad3;
    long  qoff;           // agg offset
};

__device__ __forceinline__ void edge_compute(
    int e, int m, int cb, int pb, bool upper,
    const float* __restrict__ atom,
    const int* __restrict__ src,  const int* __restrict__ dst,
    const int* __restrict__ rdir, const int* __restrict__ rtype, const int* __restrict__ rring,
    const int* __restrict__ pdir, const int* __restrict__ ptype, const int* __restrict__ pring,
    const float* __restrict__ rlen, const float* __restrict__ plen,
    EdgeVals& V)
{
    const int s  = src[e];
    const int dn = dst[e];
    const int icr = (rdir[e] * 16 + rtype[e]) * 4 + rring[e];
    const int icp = (pdir[e] * 16 + ptype[e]) * 4 + pring[e];

    float xr = rlen[e] * TAB_SCALE;
    int   ir = min((int)xr, TAB_INTERVALS - 1);
    float fr = xr - (float)ir;
    float xp = plen[e] * TAB_SCALE;
    int   ip = min((int)xp, TAB_INTERVALS - 1);
    float fp_ = xp - (float)ip;

    float4 ctr = *reinterpret_cast<const float4*>(&g_ct[icr * 32 + cb]);
    float4 ctp = *reinterpret_cast<const float4*>(&g_ct[icp * 32 + cb]);
    float4 t0r = g_tab[ir * 16 + pb];
    float4 t1r = g_tab[ir * 16 + pb + 1];
    float4 t0p = g_tab[ip * 16 + pb];
    float4 t1p = g_tab[ip * 16 + pb + 1];

    V.a = *reinterpret_cast<const float4*>(&atom[(size_t)s * CD + 4 * m]);

    float re0 = ctr.x + fmaf(fr, t0r.z, t0r.x);
    float re1 = ctr.y + fmaf(fr, t0r.w, t0r.y);
    float re2 = ctr.z + fmaf(fr, t1r.z, t1r.x);
    float re3 = ctr.w + fmaf(fr, t1r.w, t1r.y);

    float pe0 = ctp.x + fmaf(fp_, t0p.z, t0p.x);
    float pe1 = ctp.y + fmaf(fp_, t0p.w, t0p.y);
    float pe2 = ctp.z + fmaf(fp_, t1p.z, t1p.x);
    float pe3 = ctp.w + fmaf(fp_, t1p.w, t1p.y);

    V.ad0 = upper ? (pe0 - re0) : re0;
    V.ad1 = upper ? (pe1 - re1) : re1;
    V.ad2 = upper ? (pe2 - re2) : re2;
    V.ad3 = upper ? (pe3 - re3) : re3;
    V.qoff = (long)dn * CD + 4 * m;
}

__device__ __forceinline__ void edge_commit(float* agg, const EdgeVals& V) {
    float v0 = V.a.x + V.ad0;
    float v1 = V.a.y + V.ad1;
    float v2 = V.a.z + V.ad2;
    float v3 = V.a.w + V.ad3;
    float* q = agg + V.qoff;
    asm volatile("red.global.add.v4.f32 [%0], {%1,%2,%3,%4};"
                 :: "l"(q), "f"(v0), "f"(v1), "f"(v2), "f"(v3));
}

__global__ __launch_bounds__(256, 4) void edge_kernel(
    const float* __restrict__ atom,
    const int*   __restrict__ src,  const int* __restrict__ dst,
    const int*   __restrict__ rdir, const int* __restrict__ rtype, const int* __restrict__ rring,
    const int*   __restrict__ pdir, const int* __restrict__ ptype, const int* __restrict__ pring,
    const float* __restrict__ rlen, const float* __restrict__ plen,
    float* __restrict__ agg)
{
    const int l = threadIdx.x & 31;
    const int g = l >> 4;                 // edge group within warp
    const int m = l & 15;                 // lane within group
    const bool upper = (m >= 8);          // owns channels 32..63 (the p-r half)
    const int cb = (4 * m) & 31;          // channel base within 32-wide embed
    const int pb = cb >> 1;               // pair base (even, 0..14)
    const int warp = (blockIdx.x * blockDim.x + threadIdx.x) >> 5;
    const int nwarps = (gridDim.x * blockDim.x) >> 5;
    const int stride = nwarps * 2;

    for (int e = warp * 2 + g; e < N_EDGES; e += 2 * stride) {
        int e1 = e + stride;
        EdgeVals V0, V1;
        edge_compute(e, m, cb, pb, upper, atom, src, dst,
                     rdir, rtype, rring, pdir, ptype, pring, rlen, plen, V0);
        bool has1 = (e1 < N_EDGES);
        if (has1)
            edge_compute(e1, m, cb, pb, upper, atom, src, dst,
                         rdir, rtype, rring, pdir, ptype, pring, rlen, plen, V1);
        edge_commit(agg, V0);
        if (has1) edge_commit(agg, V1);
    }
}

// ---------------------------------------------------------------------------
// Kernel 3: per-node MLP, in place. TWO THREADS per node (R4 layout, best
// measured). 256-thread blocks, grid 296: 2 blocks/SM resident (fits both
// regs ~125<=128 and smem 2x66KB) -> 16 warps/SM (was 12).
// ---------------------------------------------------------------------------
#define PANEL (HID * 32 + 4)   // 4100 floats per panel incl. 16B skew pad
#define MLP_THREADS 256
#define NODES_PER_BLOCK (MLP_THREADS / 2)

__global__ __launch_bounds__(MLP_THREADS) void mlp_kernel(
    float* __restrict__ inout,           // [N_NODES, CD], agg in, out out
    const float* __restrict__ W1,        // [CD, HID]
    const float* __restrict__ b1,        // [HID]
    const float* __restrict__ W2,        // [HID, CD]
    const float* __restrict__ b2)        // [CD]
{
    extern __shared__ float sm[];
    float* sW1E = sm;                    // [128][32]: W1[j][i], j<32  (indexed [i*32+j])
    float* sW1O = sW1E + PANEL;          // j>=32
    float* sW2E = sW1O + PANEL;          // [128][32]: W2[i][c], c<32 (indexed [i*32+c])
    float* sW2O = sW2E + PANEL;          // c>=32
    float* sb1  = sW2O + PANEL;          // [128]
    float* sb2  = sb1 + HID;             // [64]

    const int tid = threadIdx.x;

    // W1 [64][128] j-major -> split panels, transposed to i-major rows of 32.
    for (int idx = tid; idx < CD * HID; idx += blockDim.x) {
        int j = idx >> 7;        // 0..63
        int i = idx & 127;       // 0..127
        float v = W1[idx];
        if (j < 32) sW1E[i * 32 + j] = v;
        else        sW1O[i * 32 + (j - 32)] = v;
    }
    // W2 [128][64] i-major -> split halves.
    for (int idx = tid; idx < HID * CD; idx += blockDim.x) {
        int i = idx >> 6;        // 0..127
        int c = idx & 63;        // 0..63
        float v = W2[idx];
        if (c < 32) sW2E[i * 32 + c] = v;
        else        sW2O[i * 32 + (c - 32)] = v;
    }
    if (tid < HID) sb1[tid] = b1[tid];
    if (tid < CD)  sb2[tid] = b2[tid];
    __syncthreads();

    const int half = tid & 1;            // 0: channels 0..31, 1: channels 32..63
    const int slot = tid >> 1;           // node slot within block
    const float* w1p = half ? sW1O : sW1E;
    const float* w2p = half ? sW2O : sW2E;

    for (long n = (long)blockIdx.x * NODES_PER_BLOCK + slot; n < N_NODES;
         n += (long)gridDim.x * NODES_PER_BLOCK) {
        float* row = inout + n * CD + half * 32;   // this thread's 32 channels

        // activations (my half of the row): 32 floats = 16 packed pairs
        ull a[16];
        {
            const ulonglong2* ar = reinterpret_cast<const ulonglong2*>(row);
#pragma unroll
            for (int k = 0; k < 8; k++) {
                ulonglong2 v = ar[k];
                a[2 * k]     = v.x;
                a[2 * k + 1] = v.y;
            }
        }
        // output accumulators init = my half of b2
        ull o[16];
        {
            const ulonglong2* bp =
                reinterpret_cast<const ulonglong2*>(sb2 + half * 32);
#pragma unroll
            for (int k = 0; k < 8; k++) {
                ulonglong2 v = bp[k];
                o[2 * k]     = v.x;
                o[2 * k + 1] = v.y;
            }
        }

#pragma unroll 2
        for (int i = 0; i < HID; i++) {
            // partial_i = sum over my 32 j of a[j]*W1[j][i]
            const ulonglong2* w1r =
                reinterpret_cast<const ulonglong2*>(w1p + i * 32);
            ull acc0 = 0ull, acc1 = 0ull;
#pragma unroll
            for (int q = 0; q < 4; q++) {
                ulonglong2 wA = w1r[2 * q];
                ulonglong2 wB = w1r[2 * q + 1];
                acc0 = ffma2(a[4 * q],     wA.x, acc0);
                acc1 = ffma2(a[4 * q + 1], wA.y, acc1);
                acc0 = ffma2(a[4 * q + 2], wB.x, acc0);
                acc1 = ffma2(a[4 * q + 3], wB.y, acc1);
            }
            float x0, x1, y0, y1;
            unpack2(acc0, x0, x1);
            unpack2(acc1, y0, y1);
            float part = (x0 + y0) + (x1 + y1);
            float h = part + __shfl_xor_sync(FULLMASK, part, 1) + sb1[i];
            h = fmaxf(h, 0.f);
            ull hh = pack2(h, h);

            // out[my 32 c] += h * W2[i][c]
            const ulonglong2* w2r =
                reinterpret_cast<const ulonglong2*>(w2p + i * 32);
#pragma unroll
            for (int q = 0; q < 8; q++) {
                ulonglong2 w = w2r[q];
                o[2 * q]     = ffma2(hh, w.x, o[2 * q]);
                o[2 * q + 1] = ffma2(hh, w.y, o[2 * q + 1]);
            }
        }

        // relu + store my half
        float4* outv = reinterpret_cast<float4*>(row);
#pragma unroll
        for (int k = 0; k < 8; k++) {
            float x0, x1, x2, x3;
            unpack2(o[2 * k],     x0, x1);
            unpack2(o[2 * k + 1], x2, x3);
            float4 r;
            r.x = fmaxf(x0, 0.f);
            r.y = fmaxf(x1, 0.f);
            r.z = fmaxf(x2, 0.f);
            r.w = fmaxf(x3, 0.f);
            outv[k] = r;
        }
    }
}

// ---------------------------------------------------------------------------
// Launch
// Inputs (metadata order):
//  0 atom_repr [N,64] f32     1 src [E] i32      2 dst [E] i32
//  3 r_dir     4 r_type       5 r_ring           6 p_dir
//  7 p_type    8 p_ring       9 r_len f32       10 p_len f32
// 11 emb_dir [8,32]          12 emb_type [16,32] 13 emb_ring [4,32]
// 14 rbf_W [20,32]           15 rbf_b [32]
// 16 W1 [64,128]             17 b1 [128]
// 18 W2 [128,64]             19 b2 [64]
// Output: [N,64] f32
// ---------------------------------------------------------------------------
extern "C" void kernel_launch(void* const* d_in, const int* in_sizes, int n_in,
                              void* d_out, int out_size) {
    const float* atom     = (const float*)d_in[0];
    const int*   src      = (const int*)d_in[1];
    const int*   dst      = (const int*)d_in[2];
    const int*   rdir     = (const int*)d_in[3];
    const int*   rtype    = (const int*)d_in[4];
    const int*   rring    = (const int*)d_in[5];
    const int*   pdir     = (const int*)d_in[6];
    const int*   ptype    = (const int*)d_in[7];
    const int*   pring    = (const int*)d_in[8];
    const float* rlen     = (const float*)d_in[9];
    const float* plen     = (const float*)d_in[10];
    const float* emb_dir  = (const float*)d_in[11];
    const float* emb_type = (const float*)d_in[12];
    const float* emb_ring = (const float*)d_in[13];
    const float* rbf_W    = (const float*)d_in[14];
    const float* rbf_b    = (const float*)d_in[15];
    const float* W1       = (const float*)d_in[16];
    const float* b1       = (const float*)d_in[17];
    const float* W2       = (const float*)d_in[18];
    const float* b2       = (const float*)d_in[19];
    float* out = (float*)d_out;

    // 0) build lookup tables (tiny)
    build_ct_kernel<<<(512 * 32 + 255) / 256, 256>>>(emb_dir, emb_type, emb_ring);
    build_tab_kernel<<<(TAB_INTERVALS * 16 + 255) / 256, 256>>>(rbf_W, rbf_b);

    // 1) zero the agg buffer (= d_out)
    int n4 = (N_NODES * CD) / 4;
    zero_kernel<<<4096, 256>>>((float4*)out, n4);

    // 2) edge scatter (2 edges/warp, 2-deep pipeline, 64-reg cap)
    edge_kernel<<<2368, 256>>>(atom, src, dst, rdir, rtype, rring,
                               pdir, ptype, pring, rlen, plen, out);

    // 3) node MLP (in place), 2 threads per node, 256-thr blocks, grid 296
    size_t smem = (size_t)(4 * PANEL + HID + CD) * sizeof(float);
    cudaFuncSetAttribute(mlp_kernel, cudaFuncAttributeMaxDynamicSharedMemorySize,
                         (int)smem);
    mlp_kernel<<<296, MLP_THREADS, smem>>>(out, W1, b1, W2, b2);
}

// round 8
// speedup vs baseline: 3.1068x; 1.6544x over previous
#include <cuda_runtime.h>
#include <cuda_bf16.h>
#include <cstdint>

// Problem constants (fixed by the reference)
#define N_NODES 500000
#define N_EDGES 1000000
#define D       32
#define CD      64
#define HID     128
#define NCEN    20
#define RBF_GAMMA 10.0f

#define TAB_INTERVALS 2048        // PWL intervals over len in [0,2)
#define TAB_SCALE     1024.0f     // intervals per unit length

#define FULLMASK 0xffffffffu

typedef unsigned long long ull;

// ---- device-global precomputed tables (allowed scratch) --------------------
__device__ float  g_ct[512 * 32];              // combined cat embedding [(dir*16+type)*4+ring][ch]
__device__ float4 g_tab[TAB_INTERVALS * 16];   // PWL rbf: per (interval, ch-pair): (v0,v1,dv0,dv1)

// ---------------------------------------------------------------------------
// Setup kernel A: combined categorical embedding table (512 combos x 32 ch)
// ---------------------------------------------------------------------------
__global__ void build_ct_kernel(const float* __restrict__ emb_dir,
                                const float* __restrict__ emb_type,
                                const float* __restrict__ emb_ring) {
    int idx = blockIdx.x * blockDim.x + threadIdx.x;
    if (idx >= 512 * 32) return;
    int l = idx & 31;
    int comb = idx >> 5;
    int ring = comb & 3;
    int type = (comb >> 2) & 15;
    int dir  = comb >> 6;
    g_ct[idx] = emb_dir[dir * 32 + l] + emb_type[type * 32 + l] + emb_ring[ring * 32 + l];
}

// ---------------------------------------------------------------------------
// Setup kernel B: PWL table for g(x) = rbf(x) @ rbf_W + rbf_b
// ---------------------------------------------------------------------------
__global__ void build_tab_kernel(const float* __restrict__ rbf_W,
                                 const float* __restrict__ rbf_b) {
    int idx = blockIdx.x * blockDim.x + threadIdx.x;
    if (idx >= TAB_INTERVALS * 16) return;
    int p = idx & 15;       // channel pair: channels 2p, 2p+1
    int i = idx >> 4;       // interval
    float x0 = (float)i / TAB_SCALE;
    float x1 = (float)(i + 1) / TAB_SCALE;
    float v00 = rbf_b[2 * p], v01 = rbf_b[2 * p + 1];
    float v10 = v00, v11 = v01;
#pragma unroll
    for (int k = 0; k < NCEN; k++) {
        float c = 0.1f * (float)k;
        float w0 = rbf_W[k * 32 + 2 * p];
        float w1 = rbf_W[k * 32 + 2 * p + 1];
        float d0 = x0 - c, d1 = x1 - c;
        float e0 = expf(-RBF_GAMMA * d0 * d0);
        float e1 = expf(-RBF_GAMMA * d1 * d1);
        v00 = fmaf(e0, w0, v00);
        v01 = fmaf(e0, w1, v01);
        v10 = fmaf(e1, w0, v10);
        v11 = fmaf(e1, w1, v11);
    }
    g_tab[idx] = make_float4(v00, v01, v10 - v00, v11 - v01);
}

// ---------------------------------------------------------------------------
// Kernel 1: zero the aggregation buffer (we reuse d_out as agg scratch)
// ---------------------------------------------------------------------------
__global__ void zero_kernel(float4* __restrict__ p, int n4) {
    int i = blockIdx.x * blockDim.x + threadIdx.x;
    int stride = gridDim.x * blockDim.x;
    float4 z = make_float4(0.f, 0.f, 0.f, 0.f);
    for (; i < n4; i += stride) p[i] = z;
}

// ---------------------------------------------------------------------------
// Kernel 2: edge message + scatter (R7 config, measured 171us). TWO edges per
// warp, lane m owns channels 4m..4m+3, 2-deep pipeline, 64-reg cap.
// ---------------------------------------------------------------------------
struct EdgeVals {
    float4 a;
    float ad0, ad1, ad2, ad3;
    long  qoff;
};

__device__ __forceinline__ void edge_compute(
    int e, int m, int cb, int pb, bool upper,
    const float* __restrict__ atom,
    const int* __restrict__ src,  const int* __restrict__ dst,
    const int* __restrict__ rdir, const int* __restrict__ rtype, const int* __restrict__ rring,
    const int* __restrict__ pdir, const int* __restrict__ ptype, const int* __restrict__ pring,
    const float* __restrict__ rlen, const float* __restrict__ plen,
    EdgeVals& V)
{
    const int s  = src[e];
    const int dn = dst[e];
    const int icr = (rdir[e] * 16 + rtype[e]) * 4 + rring[e];
    const int icp = (pdir[e] * 16 + ptype[e]) * 4 + pring[e];

    float xr = rlen[e] * TAB_SCALE;
    int   ir = min((int)xr, TAB_INTERVALS - 1);
    float fr = xr - (float)ir;
    float xp = plen[e] * TAB_SCALE;
    int   ip = min((int)xp, TAB_INTERVALS - 1);
    float fp_ = xp - (float)ip;

    float4 ctr = *reinterpret_cast<const float4*>(&g_ct[icr * 32 + cb]);
    float4 ctp = *reinterpret_cast<const float4*>(&g_ct[icp * 32 + cb]);
    float4 t0r = g_tab[ir * 16 + pb];
    float4 t1r = g_tab[ir * 16 + pb + 1];
    float4 t0p = g_tab[ip * 16 + pb];
    float4 t1p = g_tab[ip * 16 + pb + 1];

    V.a = *reinterpret_cast<const float4*>(&atom[(size_t)s * CD + 4 * m]);

    float re0 = ctr.x + fmaf(fr, t0r.z, t0r.x);
    float re1 = ctr.y + fmaf(fr, t0r.w, t0r.y);
    float re2 = ctr.z + fmaf(fr, t1r.z, t1r.x);
    float re3 = ctr.w + fmaf(fr, t1r.w, t1r.y);

    float pe0 = ctp.x + fmaf(fp_, t0p.z, t0p.x);
    float pe1 = ctp.y + fmaf(fp_, t0p.w, t0p.y);
    float pe2 = ctp.z + fmaf(fp_, t1p.z, t1p.x);
    float pe3 = ctp.w + fmaf(fp_, t1p.w, t1p.y);

    V.ad0 = upper ? (pe0 - re0) : re0;
    V.ad1 = upper ? (pe1 - re1) : re1;
    V.ad2 = upper ? (pe2 - re2) : re2;
    V.ad3 = upper ? (pe3 - re3) : re3;
    V.qoff = (long)dn * CD + 4 * m;
}

__device__ __forceinline__ void edge_commit(float* agg, const EdgeVals& V) {
    float v0 = V.a.x + V.ad0;
    float v1 = V.a.y + V.ad1;
    float v2 = V.a.z + V.ad2;
    float v3 = V.a.w + V.ad3;
    float* q = agg + V.qoff;
    asm volatile("red.global.add.v4.f32 [%0], {%1,%2,%3,%4};"
                 :: "l"(q), "f"(v0), "f"(v1), "f"(v2), "f"(v3));
}

__global__ __launch_bounds__(256, 4) void edge_kernel(
    const float* __restrict__ atom,
    const int*   __restrict__ src,  const int* __restrict__ dst,
    const int*   __restrict__ rdir, const int* __restrict__ rtype, const int* __restrict__ rring,
    const int*   __restrict__ pdir, const int* __restrict__ ptype, const int* __restrict__ pring,
    const float* __restrict__ rlen, const float* __restrict__ plen,
    float* __restrict__ agg)
{
    const int l = threadIdx.x & 31;
    const int g = l >> 4;
    const int m = l & 15;
    const bool upper = (m >= 8);
    const int cb = (4 * m) & 31;
    const int pb = cb >> 1;
    const int warp = (blockIdx.x * blockDim.x + threadIdx.x) >> 5;
    const int nwarps = (gridDim.x * blockDim.x) >> 5;
    const int stride = nwarps * 2;

    for (int e = warp * 2 + g; e < N_EDGES; e += 2 * stride) {
        int e1 = e + stride;
        EdgeVals V0, V1;
        edge_compute(e, m, cb, pb, upper, atom, src, dst,
                     rdir, rtype, rring, pdir, ptype, pring, rlen, plen, V0);
        bool has1 = (e1 < N_EDGES);
        if (has1)
            edge_compute(e1, m, cb, pb, upper, atom, src, dst,
                         rdir, rtype, rring, pdir, ptype, pring, rlen, plen, V1);
        edge_commit(agg, V0);
        if (has1) edge_commit(agg, V1);
    }
}

// ---------------------------------------------------------------------------
// Kernel 3: node MLP on TENSOR CORES (mma.sync m16n8k8 tf32).
// Block = 256 thr / 8 warps, tile = 128 nodes; each warp owns a 16-row strip
// end-to-end: A strip (smem) -> stage1 GEMM (K=64) -> relu -> H strip (smem,
// tf32 bits) -> stage2 GEMM (K=128) -> relu -> gmem. In-place safe because a
// warp only writes its own rows after consuming them.
// ---------------------------------------------------------------------------
#define SA_STRIDE 68      // f32 stride, %32 == 4 -> conflict-free frag reads
#define SH_STRIDE 132
#define SW1_STRIDE 132
#define SW2_STRIDE 68

__device__ __forceinline__ unsigned cvt_tf32(float x) {
    unsigned r;
    asm("cvt.rna.tf32.f32 %0, %1;" : "=r"(r) : "f"(x));
    return r;
}

__device__ __forceinline__ void mma_tf32(float c[4], const unsigned a[4],
                                         unsigned b0, unsigned b1) {
    asm("mma.sync.aligned.m16n8k8.row.col.f32.tf32.tf32.f32 "
        "{%0,%1,%2,%3}, {%4,%5,%6,%7}, {%8,%9}, {%0,%1,%2,%3};"
        : "+f"(c[0]), "+f"(c[1]), "+f"(c[2]), "+f"(c[3])
        : "r"(a[0]), "r"(a[1]), "r"(a[2]), "r"(a[3]), "r"(b0), "r"(b1));
}

__global__ __launch_bounds__(256) void mlp_kernel(
    float* __restrict__ inout,           // [N_NODES, CD], agg in, out out
    const float* __restrict__ W1,        // [CD, HID]
    const float* __restrict__ b1,        // [HID]
    const float* __restrict__ W2,        // [HID, CD]
    const float* __restrict__ b2)        // [CD]
{
    extern __shared__ unsigned smu[];
    // layout (all 4B words):
    unsigned* sW1 = smu;                                   // [64][132] tf32
    unsigned* sW2 = sW1 + CD * SW1_STRIDE;                 // [128][68] tf32
    float*    sb1 = (float*)(sW2 + HID * SW2_STRIDE);      // [128]
    float*    sb2 = sb1 + HID;                             // [64]
    float*    sA  = sb2 + CD;                              // 8 x [16][68] f32
    unsigned* sH  = (unsigned*)(sA + 8 * 16 * SA_STRIDE);  // 8 x [16][132] tf32

    const int tid  = threadIdx.x;
    const int w    = tid >> 5;
    const int lane = tid & 31;
    const int gid  = lane >> 2;   // group id 0..7
    const int tig  = lane & 3;    // thread in group 0..3

    // ---- stage weights (convert to tf32 once per block) ----
    for (int idx = tid; idx < CD * HID; idx += 256) {
        int k = idx >> 7, n = idx & 127;              // W1[k][n]
        sW1[k * SW1_STRIDE + n] = cvt_tf32(W1[idx]);
    }
    for (int idx = tid; idx < HID * CD; idx += 256) {
        int i = idx >> 6, c = idx & 63;               // W2[i][c]
        sW2[i * SW2_STRIDE + c] = cvt_tf32(W2[idx]);
    }
    if (tid < HID) sb1[tid] = b1[tid];
    if (tid < CD)  sb2[tid] = b2[tid];
    __syncthreads();

    const long rowBase = (long)blockIdx.x * 128 + w * 16;  // first node of strip
    float* sAw = sA + w * 16 * SA_STRIDE;
    unsigned* sHw = sH + w * 16 * SH_STRIDE;

    // ---- load A strip (16 x 64 f32) into smem, zero-padded past N ----
#pragma unroll
    for (int it = 0; it < 8; it++) {
        int idx = it * 32 + lane;          // 0..255
        int r   = idx >> 4;                // 0..15
        int c4  = idx & 15;                // float4 col
        long grow = rowBase + r;
        float4 v = make_float4(0.f, 0.f, 0.f, 0.f);
        if (grow < N_NODES)
            v = *reinterpret_cast<const float4*>(inout + grow * CD + c4 * 4);
        *reinterpret_cast<float4*>(sAw + r * SA_STRIDE + c4 * 4) = v;
    }
    __syncwarp();

    // ---- stage 1: H(16x128) = relu(A(16x64) @ W1(64x128) + b1) ----
    // A fragments for 8 k-steps, converted once.
    unsigned afr[8][4];
#pragma unroll
    for (int k = 0; k < 8; k++) {
        int kc = k * 8;
        afr[k][0] = cvt_tf32(sAw[gid * SA_STRIDE + kc + tig]);
        afr[k][1] = cvt_tf32(sAw[(gid + 8) * SA_STRIDE + kc + tig]);
        afr[k][2] = cvt_tf32(sAw[gid * SA_STRIDE + kc + tig + 4]);
        afr[k][3] = cvt_tf32(sAw[(gid + 8) * SA_STRIDE + kc + tig + 4]);
    }

#pragma unroll
    for (int n0 = 0; n0 < 16; n0++) {       // 16 n-tiles of width 8
        float c[4] = {0.f, 0.f, 0.f, 0.f};
        const int nb = n0 * 8;
#pragma unroll
        for (int k = 0; k < 8; k++) {
            unsigned b0 = sW1[(k * 8 + tig) * SW1_STRIDE + nb + gid];
            unsigned b1_ = sW1[(k * 8 + tig + 4) * SW1_STRIDE + nb + gid];
            mma_tf32(c, afr[k], b0, b1_);
        }
        int col = nb + 2 * tig;
        float bia0 = sb1[col], bia1 = sb1[col + 1];
        sHw[gid * SH_STRIDE + col]           = cvt_tf32(fmaxf(c[0] + bia0, 0.f));
        sHw[gid * SH_STRIDE + col + 1]       = cvt_tf32(fmaxf(c[1] + bia1, 0.f));
        sHw[(gid + 8) * SH_STRIDE + col]     = cvt_tf32(fmaxf(c[2] + bia0, 0.f));
        sHw[(gid + 8) * SH_STRIDE + col + 1] = cvt_tf32(fmaxf(c[3] + bia1, 0.f));
    }
    __syncwarp();

    // ---- stage 2: O(16x64) = relu(H(16x128) @ W2(128x64) + b2) ----
    unsigned ah[16][4];
#pragma unroll
    for (int k = 0; k < 16; k++) {
        int kc = k * 8;
        ah[k][0] = sHw[gid * SH_STRIDE + kc + tig];
        ah[k][1] = sHw[(gid + 8) * SH_STRIDE + kc + tig];
        ah[k][2] = sHw[gid * SH_STRIDE + kc + tig + 4];
        ah[k][3] = sHw[(gid + 8) * SH_STRIDE + kc + tig + 4];
    }

    long row0 = rowBase + gid;
    long row1 = rowBase + gid + 8;
#pragma unroll
    for (int n0 = 0; n0 < 8; n0++) {        // 8 n-tiles of width 8 (N=64)
        float c[4] = {0.f, 0.f, 0.f, 0.f};
        const int nb = n0 * 8;
#pragma unroll
        for (int k = 0; k < 16; k++) {
            unsigned b0 = sW2[(k * 8 + tig) * SW2_STRIDE + nb + gid];
            unsigned b1_ = sW2[(k * 8 + tig + 4) * SW2_STRIDE + nb + gid];
            mma_tf32(c, ah[k], b0, b1_);
        }
        int col = nb + 2 * tig;
        float bia0 = sb2[col], bia1 = sb2[col + 1];
        if (row0 < N_NODES) {
            float2 r = make_float2(fmaxf(c[0] + bia0, 0.f),
                                   fmaxf(c[1] + bia1, 0.f));
            *reinterpret_cast<float2*>(inout + row0 * CD + col) = r;
        }
        if (row1 < N_NODES) {
            float2 r = make_float2(fmaxf(c[2] + bia0, 0.f),
                                   fmaxf(c[3] + bia1, 0.f));
            *reinterpret_cast<float2*>(inout + row1 * CD + col) = r;
        }
    }
}

// ---------------------------------------------------------------------------
// Launch
// Inputs (metadata order):
//  0 atom_repr [N,64] f32     1 src [E] i32      2 dst [E] i32
//  3 r_dir     4 r_type       5 r_ring           6 p_dir
//  7 p_type    8 p_ring       9 r_len f32       10 p_len f32
// 11 emb_dir [8,32]          12 emb_type [16,32] 13 emb_ring [4,32]
// 14 rbf_W [20,32]           15 rbf_b [32]
// 16 W1 [64,128]             17 b1 [128]
// 18 W2 [128,64]             19 b2 [64]
// Output: [N,64] f32
// ---------------------------------------------------------------------------
extern "C" void kernel_launch(void* const* d_in, const int* in_sizes, int n_in,
                              void* d_out, int out_size) {
    const float* atom     = (const float*)d_in[0];
    const int*   src      = (const int*)d_in[1];
    const int*   dst      = (const int*)d_in[2];
    const int*   rdir     = (const int*)d_in[3];
    const int*   rtype    = (const int*)d_in[4];
    const int*   rring    = (const int*)d_in[5];
    const int*   pdir     = (const int*)d_in[6];
    const int*   ptype    = (const int*)d_in[7];
    const int*   pring    = (const int*)d_in[8];
    const float* rlen     = (const float*)d_in[9];
    const float* plen     = (const float*)d_in[10];
    const float* emb_dir  = (const float*)d_in[11];
    const float* emb_type = (const float*)d_in[12];
    const float* emb_ring = (const float*)d_in[13];
    const float* rbf_W    = (const float*)d_in[14];
    const float* rbf_b    = (const float*)d_in[15];
    const float* W1       = (const float*)d_in[16];
    const float* b1       = (const float*)d_in[17];
    const float* W2       = (const float*)d_in[18];
    const float* b2       = (const float*)d_in[19];
    float* out = (float*)d_out;

    // 0) build lookup tables (tiny)
    build_ct_kernel<<<(512 * 32 + 255) / 256, 256>>>(emb_dir, emb_type, emb_ring);
    build_tab_kernel<<<(TAB_INTERVALS * 16 + 255) / 256, 256>>>(rbf_W, rbf_b);

    // 1) zero the agg buffer (= d_out)
    int n4 = (N_NODES * CD) / 4;
    zero_kernel<<<4096, 256>>>((float4*)out, n4);

    // 2) edge scatter (R7 config)
    edge_kernel<<<2368, 256>>>(atom, src, dst, rdir, rtype, rring,
                               pdir, ptype, pring, rlen, plen, out);

    // 3) node MLP on tensor cores, tile = 128 nodes
    size_t smem = (size_t)(CD * SW1_STRIDE + HID * SW2_STRIDE   // weights
                           + HID + CD                            // biases
                           + 8 * 16 * SA_STRIDE                  // A strips
                           + 8 * 16 * SH_STRIDE) * 4;            // H strips
    cudaFuncSetAttribute(mlp_kernel, cudaFuncAttributeMaxDynamicSharedMemorySize,
                         (int)smem);
    int nb = (N_NODES + 127) / 128;
    mlp_kernel<<<nb, 256, smem>>>(out, W1, b1, W2, b2);
}

// round 9
// speedup vs baseline: 3.1464x; 1.0127x over previous
#include <cuda_runtime.h>
#include <cuda_bf16.h>
#include <cstdint>

// Problem constants (fixed by the reference)
#define N_NODES 500000
#define N_EDGES 1000000
#define D       32
#define CD      64
#define HID     128
#define NCEN    20
#define RBF_GAMMA 10.0f

#define TAB_INTERVALS 2048        // PWL intervals over len in [0,2)
#define TAB_SCALE     1024.0f     // intervals per unit length

#define FULLMASK 0xffffffffu

typedef unsigned long long ull;

// ---- device-global precomputed tables (allowed scratch) --------------------
__device__ float  g_ct[512 * 32];              // combined cat embedding [(dir*16+type)*4+ring][ch]
__device__ float4 g_tab[TAB_INTERVALS * 16];   // PWL rbf: per (interval, ch-pair): (v0,v1,dv0,dv1)

// ---------------------------------------------------------------------------
// Setup kernel A: combined categorical embedding table (512 combos x 32 ch)
// ---------------------------------------------------------------------------
__global__ void build_ct_kernel(const float* __restrict__ emb_dir,
                                const float* __restrict__ emb_type,
                                const float* __restrict__ emb_ring) {
    int idx = blockIdx.x * blockDim.x + threadIdx.x;
    if (idx >= 512 * 32) return;
    int l = idx & 31;
    int comb = idx >> 5;
    int ring = comb & 3;
    int type = (comb >> 2) & 15;
    int dir  = comb >> 6;
    g_ct[idx] = emb_dir[dir * 32 + l] + emb_type[type * 32 + l] + emb_ring[ring * 32 + l];
}

// ---------------------------------------------------------------------------
// Setup kernel B: PWL table for g(x) = rbf(x) @ rbf_W + rbf_b
// ---------------------------------------------------------------------------
__global__ void build_tab_kernel(const float* __restrict__ rbf_W,
                                 const float* __restrict__ rbf_b) {
    int idx = blockIdx.x * blockDim.x + threadIdx.x;
    if (idx >= TAB_INTERVALS * 16) return;
    int p = idx & 15;       // channel pair: channels 2p, 2p+1
    int i = idx >> 4;       // interval
    float x0 = (float)i / TAB_SCALE;
    float x1 = (float)(i + 1) / TAB_SCALE;
    float v00 = rbf_b[2 * p], v01 = rbf_b[2 * p + 1];
    float v10 = v00, v11 = v01;
#pragma unroll
    for (int k = 0; k < NCEN; k++) {
        float c = 0.1f * (float)k;
        float w0 = rbf_W[k * 32 + 2 * p];
        float w1 = rbf_W[k * 32 + 2 * p + 1];
        float d0 = x0 - c, d1 = x1 - c;
        float e0 = expf(-RBF_GAMMA * d0 * d0);
        float e1 = expf(-RBF_GAMMA * d1 * d1);
        v00 = fmaf(e0, w0, v00);
        v01 = fmaf(e0, w1, v01);
        v10 = fmaf(e1, w0, v10);
        v11 = fmaf(e1, w1, v11);
    }
    g_tab[idx] = make_float4(v00, v01, v10 - v00, v11 - v01);
}

// ---------------------------------------------------------------------------
// Kernel 1: zero the aggregation buffer (we reuse d_out as agg scratch)
// ---------------------------------------------------------------------------
__global__ void zero_kernel(float4* __restrict__ p, int n4) {
    int i = blockIdx.x * blockDim.x + threadIdx.x;
    int stride = gridDim.x * blockDim.x;
    float4 z = make_float4(0.f, 0.f, 0.f, 0.f);
    for (; i < n4; i += stride) p[i] = z;
}

// ---------------------------------------------------------------------------
// Kernel 2: edge message + scatter (R7 config, measured ~173us). TWO edges
// per warp, lane m owns channels 4m..4m+3, 2-deep pipeline, 64-reg cap.
// ---------------------------------------------------------------------------
struct EdgeVals {
    float4 a;
    float ad0, ad1, ad2, ad3;
    long  qoff;
};

__device__ __forceinline__ void edge_compute(
    int e, int m, int cb, int pb, bool upper,
    const float* __restrict__ atom,
    const int* __restrict__ src,  const int* __restrict__ dst,
    const int* __restrict__ rdir, const int* __restrict__ rtype, const int* __restrict__ rring,
    const int* __restrict__ pdir, const int* __restrict__ ptype, const int* __restrict__ pring,
    const float* __restrict__ rlen, const float* __restrict__ plen,
    EdgeVals& V)
{
    const int s  = src[e];
    const int dn = dst[e];
    const int icr = (rdir[e] * 16 + rtype[e]) * 4 + rring[e];
    const int icp = (pdir[e] * 16 + ptype[e]) * 4 + pring[e];

    float xr = rlen[e] * TAB_SCALE;
    int   ir = min((int)xr, TAB_INTERVALS - 1);
    float fr = xr - (float)ir;
    float xp = plen[e] * TAB_SCALE;
    int   ip = min((int)xp, TAB_INTERVALS - 1);
    float fp_ = xp - (float)ip;

    float4 ctr = *reinterpret_cast<const float4*>(&g_ct[icr * 32 + cb]);
    float4 ctp = *reinterpret_cast<const float4*>(&g_ct[icp * 32 + cb]);
    float4 t0r = g_tab[ir * 16 + pb];
    float4 t1r = g_tab[ir * 16 + pb + 1];
    float4 t0p = g_tab[ip * 16 + pb];
    float4 t1p = g_tab[ip * 16 + pb + 1];

    V.a = *reinterpret_cast<const float4*>(&atom[(size_t)s * CD + 4 * m]);

    float re0 = ctr.x + fmaf(fr, t0r.z, t0r.x);
    float re1 = ctr.y + fmaf(fr, t0r.w, t0r.y);
    float re2 = ctr.z + fmaf(fr, t1r.z, t1r.x);
    float re3 = ctr.w + fmaf(fr, t1r.w, t1r.y);

    float pe0 = ctp.x + fmaf(fp_, t0p.z, t0p.x);
    float pe1 = ctp.y + fmaf(fp_, t0p.w, t0p.y);
    float pe2 = ctp.z + fmaf(fp_, t1p.z, t1p.x);
    float pe3 = ctp.w + fmaf(fp_, t1p.w, t1p.y);

    V.ad0 = upper ? (pe0 - re0) : re0;
    V.ad1 = upper ? (pe1 - re1) : re1;
    V.ad2 = upper ? (pe2 - re2) : re2;
    V.ad3 = upper ? (pe3 - re3) : re3;
    V.qoff = (long)dn * CD + 4 * m;
}

__device__ __forceinline__ void edge_commit(float* agg, const EdgeVals& V) {
    float v0 = V.a.x + V.ad0;
    float v1 = V.a.y + V.ad1;
    float v2 = V.a.z + V.ad2;
    float v3 = V.a.w + V.ad3;
    float* q = agg + V.qoff;
    asm volatile("red.global.add.v4.f32 [%0], {%1,%2,%3,%4};"
                 :: "l"(q), "f"(v0), "f"(v1), "f"(v2), "f"(v3));
}

__global__ __launch_bounds__(256, 4) void edge_kernel(
    const float* __restrict__ atom,
    const int*   __restrict__ src,  const int* __restrict__ dst,
    const int*   __restrict__ rdir, const int* __restrict__ rtype, const int* __restrict__ rring,
    const int*   __restrict__ pdir, const int* __restrict__ ptype, const int* __restrict__ pring,
    const float* __restrict__ rlen, const float* __restrict__ plen,
    float* __restrict__ agg)
{
    const int l = threadIdx.x & 31;
    const int g = l >> 4;
    const int m = l & 15;
    const bool upper = (m >= 8);
    const int cb = (4 * m) & 31;
    const int pb = cb >> 1;
    const int warp = (blockIdx.x * blockDim.x + threadIdx.x) >> 5;
    const int nwarps = (gridDim.x * blockDim.x) >> 5;
    const int stride = nwarps * 2;

    for (int e = warp * 2 + g; e < N_EDGES; e += 2 * stride) {
        int e1 = e + stride;
        EdgeVals V0, V1;
        edge_compute(e, m, cb, pb, upper, atom, src, dst,
                     rdir, rtype, rring, pdir, ptype, pring, rlen, plen, V0);
        bool has1 = (e1 < N_EDGES);
        if (has1)
            edge_compute(e1, m, cb, pb, upper, atom, src, dst,
                         rdir, rtype, rring, pdir, ptype, pring, rlen, plen, V1);
        edge_commit(agg, V0);
        if (has1) edge_commit(agg, V1);
    }
}

// ---------------------------------------------------------------------------
// Kernel 3: node MLP on TENSOR CORES (mma.sync m16n8k8 tf32).
// Block = 256 thr / 8 warps, tile = 128 nodes; each warp owns a 16-row strip.
// R9 change: n-tiles processed in PAIRS with two independent accumulators so
// the mma chain has 2-way ILP (was a serial 8/16-deep dependent chain).
// ---------------------------------------------------------------------------
#define SA_STRIDE 68      // f32 stride, %32 == 4 -> conflict-free frag reads
#define SH_STRIDE 132
#define SW1_STRIDE 132
#define SW2_STRIDE 68

__device__ __forceinline__ unsigned cvt_tf32(float x) {
    unsigned r;
    asm("cvt.rna.tf32.f32 %0, %1;" : "=r"(r) : "f"(x));
    return r;
}

__device__ __forceinline__ void mma_tf32(float c[4], const unsigned a[4],
                                         unsigned b0, unsigned b1) {
    asm("mma.sync.aligned.m16n8k8.row.col.f32.tf32.tf32.f32 "
        "{%0,%1,%2,%3}, {%4,%5,%6,%7}, {%8,%9}, {%0,%1,%2,%3};"
        : "+f"(c[0]), "+f"(c[1]), "+f"(c[2]), "+f"(c[3])
        : "r"(a[0]), "r"(a[1]), "r"(a[2]), "r"(a[3]), "r"(b0), "r"(b1));
}

__global__ __launch_bounds__(256) void mlp_kernel(
    float* __restrict__ inout,           // [N_NODES, CD], agg in, out out
    const float* __restrict__ W1,        // [CD, HID]
    const float* __restrict__ b1,        // [HID]
    const float* __restrict__ W2,        // [HID, CD]
    const float* __restrict__ b2)        // [CD]
{
    extern __shared__ unsigned smu[];
    unsigned* sW1 = smu;                                   // [64][132] tf32
    unsigned* sW2 = sW1 + CD * SW1_STRIDE;                 // [128][68] tf32
    float*    sb1 = (float*)(sW2 + HID * SW2_STRIDE);      // [128]
    float*    sb2 = sb1 + HID;                             // [64]
    float*    sA  = sb2 + CD;                              // 8 x [16][68] f32
    unsigned* sH  = (unsigned*)(sA + 8 * 16 * SA_STRIDE);  // 8 x [16][132] tf32

    const int tid  = threadIdx.x;
    const int w    = tid >> 5;
    const int lane = tid & 31;
    const int gid  = lane >> 2;   // group id 0..7
    const int tig  = lane & 3;    // thread in group 0..3

    // ---- stage weights (convert to tf32 once per block) ----
    for (int idx = tid; idx < CD * HID; idx += 256) {
        int k = idx >> 7, n = idx & 127;              // W1[k][n]
        sW1[k * SW1_STRIDE + n] = cvt_tf32(W1[idx]);
    }
    for (int idx = tid; idx < HID * CD; idx += 256) {
        int i = idx >> 6, c = idx & 63;               // W2[i][c]
        sW2[i * SW2_STRIDE + c] = cvt_tf32(W2[idx]);
    }
    if (tid < HID) sb1[tid] = b1[tid];
    if (tid < CD)  sb2[tid] = b2[tid];
    __syncthreads();

    const long rowBase = (long)blockIdx.x * 128 + w * 16;  // first node of strip
    float* sAw = sA + w * 16 * SA_STRIDE;
    unsigned* sHw = sH + w * 16 * SH_STRIDE;

    // ---- load A strip (16 x 64 f32) into smem, zero-padded past N ----
#pragma unroll
    for (int it = 0; it < 8; it++) {
        int idx = it * 32 + lane;          // 0..255
        int r   = idx >> 4;                // 0..15
        int c4  = idx & 15;                // float4 col
        long grow = rowBase + r;
        float4 v = make_float4(0.f, 0.f, 0.f, 0.f);
        if (grow < N_NODES)
            v = *reinterpret_cast<const float4*>(inout + grow * CD + c4 * 4);
        *reinterpret_cast<float4*>(sAw + r * SA_STRIDE + c4 * 4) = v;
    }
    __syncwarp();

    // ---- stage 1: H(16x128) = relu(A(16x64) @ W1(64x128) + b1) ----
    unsigned afr[8][4];
#pragma unroll
    for (int k = 0; k < 8; k++) {
        int kc = k * 8;
        afr[k][0] = cvt_tf32(sAw[gid * SA_STRIDE + kc + tig]);
        afr[k][1] = cvt_tf32(sAw[(gid + 8) * SA_STRIDE + kc + tig]);
        afr[k][2] = cvt_tf32(sAw[gid * SA_STRIDE + kc + tig + 4]);
        afr[k][3] = cvt_tf32(sAw[(gid + 8) * SA_STRIDE + kc + tig + 4]);
    }

#pragma unroll
    for (int n0 = 0; n0 < 16; n0 += 2) {    // paired n-tiles: 2 indep accum chains
        float c0[4] = {0.f, 0.f, 0.f, 0.f};
        float c1[4] = {0.f, 0.f, 0.f, 0.f};
        const int nbA = n0 * 8;
        const int nbB = nbA + 8;
#pragma unroll
        for (int k = 0; k < 8; k++) {
            const unsigned* wr0 = &sW1[(k * 8 + tig) * SW1_STRIDE];
            const unsigned* wr1 = &sW1[(k * 8 + tig + 4) * SW1_STRIDE];
            unsigned bA0 = wr0[nbA + gid];
            unsigned bA1 = wr1[nbA + gid];
            unsigned bB0 = wr0[nbB + gid];
            unsigned bB1 = wr1[nbB + gid];
            mma_tf32(c0, afr[k], bA0, bA1);
            mma_tf32(c1, afr[k], bB0, bB1);
        }
#pragma unroll
        for (int t = 0; t < 2; t++) {
            const float* c = t ? c1 : c0;
            int col = (t ? nbB : nbA) + 2 * tig;
            float bia0 = sb1[col], bia1 = sb1[col + 1];
            sHw[gid * SH_STRIDE + col]           = cvt_tf32(fmaxf(c[0] + bia0, 0.f));
            sHw[gid * SH_STRIDE + col + 1]       = cvt_tf32(fmaxf(c[1] + bia1, 0.f));
            sHw[(gid + 8) * SH_STRIDE + col]     = cvt_tf32(fmaxf(c[2] + bia0, 0.f));
            sHw[(gid + 8) * SH_STRIDE + col + 1] = cvt_tf32(fmaxf(c[3] + bia1, 0.f));
        }
    }
    __syncwarp();

    // ---- stage 2: O(16x64) = relu(H(16x128) @ W2(128x64) + b2) ----
    unsigned ah[16][4];
#pragma unroll
    for (int k = 0; k < 16; k++) {
        int kc = k * 8;
        ah[k][0] = sHw[gid * SH_STRIDE + kc + tig];
        ah[k][1] = sHw[(gid + 8) * SH_STRIDE + kc + tig];
        ah[k][2] = sHw[gid * SH_STRIDE + kc + tig + 4];
        ah[k][3] = sHw[(gid + 8) * SH_STRIDE + kc + tig + 4];
    }

    long row0 = rowBase + gid;
    long row1 = rowBase + gid + 8;
#pragma unroll
    for (int n0 = 0; n0 < 8; n0 += 2) {     // paired n-tiles (N=64 total)
        float c0[4] = {0.f, 0.f, 0.f, 0.f};
        float c1[4] = {0.f, 0.f, 0.f, 0.f};
        const int nbA = n0 * 8;
        const int nbB = nbA + 8;
#pragma unroll
        for (int k = 0; k < 16; k++) {
            const unsigned* wr0 = &sW2[(k * 8 + tig) * SW2_STRIDE];
            const unsigned* wr1 = &sW2[(k * 8 + tig + 4) * SW2_STRIDE];
            unsigned bA0 = wr0[nbA + gid];
            unsigned bA1 = wr1[nbA + gid];
            unsigned bB0 = wr0[nbB + gid];
            unsigned bB1 = wr1[nbB + gid];
            mma_tf32(c0, ah[k], bA0, bA1);
            mma_tf32(c1, ah[k], bB0, bB1);
        }
#pragma unroll
        for (int t = 0; t < 2; t++) {
            const float* c = t ? c1 : c0;
            int col = (t ? nbB : nbA) + 2 * tig;
            float bia0 = sb2[col], bia1 = sb2[col + 1];
            if (row0 < N_NODES) {
                float2 r = make_float2(fmaxf(c[0] + bia0, 0.f),
                                       fmaxf(c[1] + bia1, 0.f));
                *reinterpret_cast<float2*>(inout + row0 * CD + col) = r;
            }
            if (row1 < N_NODES) {
                float2 r = make_float2(fmaxf(c[2] + bia0, 0.f),
                                       fmaxf(c[3] + bia1, 0.f));
                *reinterpret_cast<float2*>(inout + row1 * CD + col) = r;
            }
        }
    }
}

// ---------------------------------------------------------------------------
// Launch
// Inputs (metadata order):
//  0 atom_repr [N,64] f32     1 src [E] i32      2 dst [E] i32
//  3 r_dir     4 r_type       5 r_ring           6 p_dir
//  7 p_type    8 p_ring       9 r_len f32       10 p_len f32
// 11 emb_dir [8,32]          12 emb_type [16,32] 13 emb_ring [4,32]
// 14 rbf_W [20,32]           15 rbf_b [32]
// 16 W1 [64,128]             17 b1 [128]
// 18 W2 [128,64]             19 b2 [64]
// Output: [N,64] f32
// ---------------------------------------------------------------------------
extern "C" void kernel_launch(void* const* d_in, const int* in_sizes, int n_in,
                              void* d_out, int out_size) {
    const float* atom     = (const float*)d_in[0];
    const int*   src      = (const int*)d_in[1];
    const int*   dst      = (const int*)d_in[2];
    const int*   rdir     = (const int*)d_in[3];
    const int*   rtype    = (const int*)d_in[4];
    const int*   rring    = (const int*)d_in[5];
    const int*   pdir     = (const int*)d_in[6];
    const int*   ptype    = (const int*)d_in[7];
    const int*   pring    = (const int*)d_in[8];
    const float* rlen     = (const float*)d_in[9];
    const float* plen     = (const float*)d_in[10];
    const float* emb_dir  = (const float*)d_in[11];
    const float* emb_type = (const float*)d_in[12];
    const float* emb_ring = (const float*)d_in[13];
    const float* rbf_W    = (const float*)d_in[14];
    const float* rbf_b    = (const float*)d_in[15];
    const float* W1       = (const float*)d_in[16];
    const float* b1       = (const float*)d_in[17];
    const float* W2       = (const float*)d_in[18];
    const float* b2       = (const float*)d_in[19];
    float* out = (float*)d_out;

    // 0) build lookup tables (tiny)
    build_ct_kernel<<<(512 * 32 + 255) / 256, 256>>>(emb_dir, emb_type, emb_ring);
    build_tab_kernel<<<(TAB_INTERVALS * 16 + 255) / 256, 256>>>(rbf_W, rbf_b);

    // 1) zero the agg buffer (= d_out)
    int n4 = (N_NODES * CD) / 4;
    zero_kernel<<<4096, 256>>>((float4*)out, n4);

    // 2) edge scatter (R7 config)
    edge_kernel<<<2368, 256>>>(atom, src, dst, rdir, rtype, rring,
                               pdir, ptype, pring, rlen, plen, out);

    // 3) node MLP on tensor cores, tile = 128 nodes
    size_t smem = (size_t)(CD * SW1_STRIDE + HID * SW2_STRIDE   // weights
                           + HID + CD                            // biases
                           + 8 * 16 * SA_STRIDE                  // A strips
                           + 8 * 16 * SH_STRIDE) * 4;            // H strips
    cudaFuncSetAttribute(mlp_kernel, cudaFuncAttributeMaxDynamicSharedMemorySize,
                         (int)smem);
    int nb = (N_NODES + 127) / 128;
    mlp_kernel<<<nb, 256, smem>>>(out, W1, b1, W2, b2);
}

// round 10
// speedup vs baseline: 4.5741x; 1.4538x over previous
#include <cuda_runtime.h>
#include <cuda_bf16.h>
#include <cstdint>

// Problem constants (fixed by the reference)
#define N_NODES 500000
#define N_EDGES 1000000
#define D       32
#define CD      64
#define HID     128
#define NCEN    20
#define RBF_GAMMA 10.0f

#define TAB_INTERVALS 2048        // PWL intervals over len in [0,2)
#define TAB_SCALE     1024.0f     // intervals per unit length

#define FULLMASK 0xffffffffu

typedef unsigned long long ull;

// ---- device-global precomputed tables (allowed scratch) --------------------
__device__ float  g_ct[512 * 32];              // combined cat embedding [(dir*16+type)*4+ring][ch]
__device__ float4 g_tab[TAB_INTERVALS * 16];   // PWL rbf: per (interval, ch-pair): (v0,v1,dv0,dv1)

// ---------------------------------------------------------------------------
// Setup kernel A: combined categorical embedding table (512 combos x 32 ch)
// ---------------------------------------------------------------------------
__global__ void build_ct_kernel(const float* __restrict__ emb_dir,
                                const float* __restrict__ emb_type,
                                const float* __restrict__ emb_ring) {
    int idx = blockIdx.x * blockDim.x + threadIdx.x;
    if (idx >= 512 * 32) return;
    int l = idx & 31;
    int comb = idx >> 5;
    int ring = comb & 3;
    int type = (comb >> 2) & 15;
    int dir  = comb >> 6;
    g_ct[idx] = emb_dir[dir * 32 + l] + emb_type[type * 32 + l] + emb_ring[ring * 32 + l];
}

// ---------------------------------------------------------------------------
// Setup kernel B: PWL table for g(x) = rbf(x) @ rbf_W + rbf_b
// ---------------------------------------------------------------------------
__global__ void build_tab_kernel(const float* __restrict__ rbf_W,
                                 const float* __restrict__ rbf_b) {
    int idx = blockIdx.x * blockDim.x + threadIdx.x;
    if (idx >= TAB_INTERVALS * 16) return;
    int p = idx & 15;       // channel pair: channels 2p, 2p+1
    int i = idx >> 4;       // interval
    float x0 = (float)i / TAB_SCALE;
    float x1 = (float)(i + 1) / TAB_SCALE;
    float v00 = rbf_b[2 * p], v01 = rbf_b[2 * p + 1];
    float v10 = v00, v11 = v01;
#pragma unroll
    for (int k = 0; k < NCEN; k++) {
        float c = 0.1f * (float)k;
        float w0 = rbf_W[k * 32 + 2 * p];
        float w1 = rbf_W[k * 32 + 2 * p + 1];
        float d0 = x0 - c, d1 = x1 - c;
        float e0 = expf(-RBF_GAMMA * d0 * d0);
        float e1 = expf(-RBF_GAMMA * d1 * d1);
        v00 = fmaf(e0, w0, v00);
        v01 = fmaf(e0, w1, v01);
        v10 = fmaf(e1, w0, v10);
        v11 = fmaf(e1, w1, v11);
    }
    g_tab[idx] = make_float4(v00, v01, v10 - v00, v11 - v01);
}

// ---------------------------------------------------------------------------
// Kernel 1: zero the aggregation buffer (we reuse d_out as agg scratch)
// ---------------------------------------------------------------------------
__global__ void zero_kernel(float4* __restrict__ p, int n4) {
    int i = blockIdx.x * blockDim.x + threadIdx.x;
    int stride = gridDim.x * blockDim.x;
    float4 z = make_float4(0.f, 0.f, 0.f, 0.f);
    for (; i < n4; i += stride) p[i] = z;
}

// ---------------------------------------------------------------------------
// Kernel 2: edge message + scatter (R7 config, measured ~170us). TWO edges
// per warp, lane m owns channels 4m..4m+3, 2-deep pipeline, 64-reg cap.
// ---------------------------------------------------------------------------
struct EdgeVals {
    float4 a;
    float ad0, ad1, ad2, ad3;
    long  qoff;
};

__device__ __forceinline__ void edge_compute(
    int e, int m, int cb, int pb, bool upper,
    const float* __restrict__ atom,
    const int* __restrict__ src,  const int* __restrict__ dst,
    const int* __restrict__ rdir, const int* __restrict__ rtype, const int* __restrict__ rring,
    const int* __restrict__ pdir, const int* __restrict__ ptype, const int* __restrict__ pring,
    const float* __restrict__ rlen, const float* __restrict__ plen,
    EdgeVals& V)
{
    const int s  = src[e];
    const int dn = dst[e];
    const int icr = (rdir[e] * 16 + rtype[e]) * 4 + rring[e];
    const int icp = (pdir[e] * 16 + ptype[e]) * 4 + pring[e];

    float xr = rlen[e] * TAB_SCALE;
    int   ir = min((int)xr, TAB_INTERVALS - 1);
    float fr = xr - (float)ir;
    float xp = plen[e] * TAB_SCALE;
    int   ip = min((int)xp, TAB_INTERVALS - 1);
    float fp_ = xp - (float)ip;

    float4 ctr = *reinterpret_cast<const float4*>(&g_ct[icr * 32 + cb]);
    float4 ctp = *reinterpret_cast<const float4*>(&g_ct[icp * 32 + cb]);
    float4 t0r = g_tab[ir * 16 + pb];
    float4 t1r = g_tab[ir * 16 + pb + 1];
    float4 t0p = g_tab[ip * 16 + pb];
    float4 t1p = g_tab[ip * 16 + pb + 1];

    V.a = *reinterpret_cast<const float4*>(&atom[(size_t)s * CD + 4 * m]);

    float re0 = ctr.x + fmaf(fr, t0r.z, t0r.x);
    float re1 = ctr.y + fmaf(fr, t0r.w, t0r.y);
    float re2 = ctr.z + fmaf(fr, t1r.z, t1r.x);
    float re3 = ctr.w + fmaf(fr, t1r.w, t1r.y);

    float pe0 = ctp.x + fmaf(fp_, t0p.z, t0p.x);
    float pe1 = ctp.y + fmaf(fp_, t0p.w, t0p.y);
    float pe2 = ctp.z + fmaf(fp_, t1p.z, t1p.x);
    float pe3 = ctp.w + fmaf(fp_, t1p.w, t1p.y);

    V.ad0 = upper ? (pe0 - re0) : re0;
    V.ad1 = upper ? (pe1 - re1) : re1;
    V.ad2 = upper ? (pe2 - re2) : re2;
    V.ad3 = upper ? (pe3 - re3) : re3;
    V.qoff = (long)dn * CD + 4 * m;
}

__device__ __forceinline__ void edge_commit(float* agg, const EdgeVals& V) {
    float v0 = V.a.x + V.ad0;
    float v1 = V.a.y + V.ad1;
    float v2 = V.a.z + V.ad2;
    float v3 = V.a.w + V.ad3;
    float* q = agg + V.qoff;
    asm volatile("red.global.add.v4.f32 [%0], {%1,%2,%3,%4};"
                 :: "l"(q), "f"(v0), "f"(v1), "f"(v2), "f"(v3));
}

__global__ __launch_bounds__(256, 4) void edge_kernel(
    const float* __restrict__ atom,
    const int*   __restrict__ src,  const int* __restrict__ dst,
    const int*   __restrict__ rdir, const int* __restrict__ rtype, const int* __restrict__ rring,
    const int*   __restrict__ pdir, const int* __restrict__ ptype, const int* __restrict__ pring,
    const float* __restrict__ rlen, const float* __restrict__ plen,
    float* __restrict__ agg)
{
    const int l = threadIdx.x & 31;
    const int g = l >> 4;
    const int m = l & 15;
    const bool upper = (m >= 8);
    const int cb = (4 * m) & 31;
    const int pb = cb >> 1;
    const int warp = (blockIdx.x * blockDim.x + threadIdx.x) >> 5;
    const int nwarps = (gridDim.x * blockDim.x) >> 5;
    const int stride = nwarps * 2;

    for (int e = warp * 2 + g; e < N_EDGES; e += 2 * stride) {
        int e1 = e + stride;
        EdgeVals V0, V1;
        edge_compute(e, m, cb, pb, upper, atom, src, dst,
                     rdir, rtype, rring, pdir, ptype, pring, rlen, plen, V0);
        bool has1 = (e1 < N_EDGES);
        if (has1)
            edge_compute(e1, m, cb, pb, upper, atom, src, dst,
                         rdir, rtype, rring, pdir, ptype, pring, rlen, plen, V1);
        edge_commit(agg, V0);
        if (has1) edge_commit(agg, V1);
    }
}

// ---------------------------------------------------------------------------
// Kernel 3: PERSISTENT node MLP on tensor cores (mma.sync m16n8k8 tf32).
// Grid = 148 blocks x 256 thr (1 block/SM, smem-limited). Weights staged and
// converted ONCE per SM. Each warp independently grid-strides over 16-row
// strips (N_NODES = 31250 * 16 exactly -> no row guards). Next strip's A is
// prefetched into registers under the current strip's compute. Weight strides
// 136/72 (== 8 mod 32) make B-fragment LDS bank-conflict-free.
// ---------------------------------------------------------------------------
#define SA_STRIDE 68
#define SH_STRIDE 132
#define SW1_STRIDE 136
#define SW2_STRIDE 72
#define NSTRIPS (N_NODES / 16)   // 31250, exact

__device__ __forceinline__ unsigned cvt_tf32(float x) {
    unsigned r;
    asm("cvt.rna.tf32.f32 %0, %1;" : "=r"(r) : "f"(x));
    return r;
}

__device__ __forceinline__ void mma_tf32(float c[4], const unsigned a[4],
                                         unsigned b0, unsigned b1) {
    asm("mma.sync.aligned.m16n8k8.row.col.f32.tf32.tf32.f32 "
        "{%0,%1,%2,%3}, {%4,%5,%6,%7}, {%8,%9}, {%0,%1,%2,%3};"
        : "+f"(c[0]), "+f"(c[1]), "+f"(c[2]), "+f"(c[3])
        : "r"(a[0]), "r"(a[1]), "r"(a[2]), "r"(a[3]), "r"(b0), "r"(b1));
}

__global__ __launch_bounds__(256) void mlp_kernel(
    float* __restrict__ inout,           // [N_NODES, CD], agg in, out out
    const float* __restrict__ W1,        // [CD, HID]
    const float* __restrict__ b1,        // [HID]
    const float* __restrict__ W2,        // [HID, CD]
    const float* __restrict__ b2)        // [CD]
{
    extern __shared__ unsigned smu[];
    unsigned* sW1 = smu;                                   // [64][136] tf32
    unsigned* sW2 = sW1 + CD * SW1_STRIDE;                 // [128][72] tf32
    float*    sb1 = (float*)(sW2 + HID * SW2_STRIDE);      // [128]
    float*    sb2 = sb1 + HID;                             // [64]
    float*    sA  = sb2 + CD;                              // 8 x [16][68] f32
    unsigned* sH  = (unsigned*)(sA + 8 * 16 * SA_STRIDE);  // 8 x [16][132] tf32

    const int tid  = threadIdx.x;
    const int w    = tid >> 5;
    const int lane = tid & 31;
    const int gid  = lane >> 2;   // group id 0..7
    const int tig  = lane & 3;    // thread in group 0..3

    // ---- stage weights ONCE per SM ----
    for (int idx = tid; idx < CD * HID; idx += 256) {
        int k = idx >> 7, n = idx & 127;              // W1[k][n]
        sW1[k * SW1_STRIDE + n] = cvt_tf32(W1[idx]);
    }
    for (int idx = tid; idx < HID * CD; idx += 256) {
        int i = idx >> 6, c = idx & 63;               // W2[i][c]
        sW2[i * SW2_STRIDE + c] = cvt_tf32(W2[idx]);
    }
    if (tid < HID) sb1[tid] = b1[tid];
    if (tid < CD)  sb2[tid] = b2[tid];
    __syncthreads();

    float* sAw = sA + w * 16 * SA_STRIDE;
    unsigned* sHw = sH + w * 16 * SH_STRIDE;

    const int gwarp   = blockIdx.x * 8 + w;
    const int wstride = gridDim.x * 8;

    // per-lane A-strip I/O coordinates
    const int r0 = lane >> 4;            // rows r0, r0+2, ... (8 iters x 2 rows)
    const int c4 = lane & 15;            // float4 column

    long strip = gwarp;
    float4 pf[8];
    if (strip < NSTRIPS) {
        const float* base = inout + strip * 16 * CD;
#pragma unroll
        for (int it = 0; it < 8; it++)
            pf[it] = *reinterpret_cast<const float4*>(base + (it * 2 + r0) * CD + c4 * 4);
    }

    while (strip < NSTRIPS) {
        // ---- commit prefetched A strip to smem ----
#pragma unroll
        for (int it = 0; it < 8; it++)
            *reinterpret_cast<float4*>(sAw + (it * 2 + r0) * SA_STRIDE + c4 * 4) = pf[it];
        __syncwarp();

        // ---- extract A fragments (8 k-steps) ----
        unsigned afr[8][4];
#pragma unroll
        for (int k = 0; k < 8; k++) {
            int kc = k * 8;
            afr[k][0] = cvt_tf32(sAw[gid * SA_STRIDE + kc + tig]);
            afr[k][1] = cvt_tf32(sAw[(gid + 8) * SA_STRIDE + kc + tig]);
            afr[k][2] = cvt_tf32(sAw[gid * SA_STRIDE + kc + tig + 4]);
            afr[k][3] = cvt_tf32(sAw[(gid + 8) * SA_STRIDE + kc + tig + 4]);
        }

        // ---- prefetch NEXT strip under compute ----
        long next = strip + wstride;
        if (next < NSTRIPS) {
            const float* base = inout + next * 16 * CD;
#pragma unroll
            for (int it = 0; it < 8; it++)
                pf[it] = *reinterpret_cast<const float4*>(base + (it * 2 + r0) * CD + c4 * 4);
        }

        // ---- stage 1: H = relu(A @ W1 + b1), paired n-tiles ----
#pragma unroll
        for (int n0 = 0; n0 < 16; n0 += 2) {
            float cA[4] = {0.f, 0.f, 0.f, 0.f};
            float cB[4] = {0.f, 0.f, 0.f, 0.f};
            const int nbA = n0 * 8;
            const int nbB = nbA + 8;
#pragma unroll
            for (int k = 0; k < 8; k++) {
                const unsigned* wr0 = &sW1[(k * 8 + tig) * SW1_STRIDE];
                const unsigned* wr1 = &sW1[(k * 8 + tig + 4) * SW1_STRIDE];
                unsigned bA0 = wr0[nbA + gid];
                unsigned bA1 = wr1[nbA + gid];
                unsigned bB0 = wr0[nbB + gid];
                unsigned bB1 = wr1[nbB + gid];
                mma_tf32(cA, afr[k], bA0, bA1);
                mma_tf32(cB, afr[k], bB0, bB1);
            }
#pragma unroll
            for (int t = 0; t < 2; t++) {
                const float* c = t ? cB : cA;
                int col = (t ? nbB : nbA) + 2 * tig;
                float bia0 = sb1[col], bia1 = sb1[col + 1];
                sHw[gid * SH_STRIDE + col]           = cvt_tf32(fmaxf(c[0] + bia0, 0.f));
                sHw[gid * SH_STRIDE + col + 1]       = cvt_tf32(fmaxf(c[1] + bia1, 0.f));
                sHw[(gid + 8) * SH_STRIDE + col]     = cvt_tf32(fmaxf(c[2] + bia0, 0.f));
                sHw[(gid + 8) * SH_STRIDE + col + 1] = cvt_tf32(fmaxf(c[3] + bia1, 0.f));
            }
        }
        __syncwarp();

        // ---- stage 2: O = relu(H @ W2 + b2) ----
        unsigned ah[16][4];
#pragma unroll
        for (int k = 0; k < 16; k++) {
            int kc = k * 8;
            ah[k][0] = sHw[gid * SH_STRIDE + kc + tig];
            ah[k][1] = sHw[(gid + 8) * SH_STRIDE + kc + tig];
            ah[k][2] = sHw[gid * SH_STRIDE + kc + tig + 4];
            ah[k][3] = sHw[(gid + 8) * SH_STRIDE + kc + tig + 4];
        }

        const long rowBase = strip * 16;
        float* out0 = inout + (rowBase + gid) * CD;
        float* out1 = inout + (rowBase + gid + 8) * CD;
#pragma unroll
        for (int n0 = 0; n0 < 8; n0 += 2) {
            float cA[4] = {0.f, 0.f, 0.f, 0.f};
            float cB[4] = {0.f, 0.f, 0.f, 0.f};
            const int nbA = n0 * 8;
            const int nbB = nbA + 8;
#pragma unroll
            for (int k = 0; k < 16; k++) {
                const unsigned* wr0 = &sW2[(k * 8 + tig) * SW2_STRIDE];
                const unsigned* wr1 = &sW2[(k * 8 + tig + 4) * SW2_STRIDE];
                unsigned bA0 = wr0[nbA + gid];
                unsigned bA1 = wr1[nbA + gid];
                unsigned bB0 = wr0[nbB + gid];
                unsigned bB1 = wr1[nbB + gid];
                mma_tf32(cA, ah[k], bA0, bA1);
                mma_tf32(cB, ah[k], bB0, bB1);
            }
#pragma unroll
            for (int t = 0; t < 2; t++) {
                const float* c = t ? cB : cA;
                int col = (t ? nbB : nbA) + 2 * tig;
                float bia0 = sb2[col], bia1 = sb2[col + 1];
                float2 ra = make_float2(fmaxf(c[0] + bia0, 0.f),
                                        fmaxf(c[1] + bia1, 0.f));
                float2 rb = make_float2(fmaxf(c[2] + bia0, 0.f),
                                        fmaxf(c[3] + bia1, 0.f));
                *reinterpret_cast<float2*>(out0 + col) = ra;
                *reinterpret_cast<float2*>(out1 + col) = rb;
            }
        }

        strip = next;
    }
}

// ---------------------------------------------------------------------------
// Launch
// Inputs (metadata order):
//  0 atom_repr [N,64] f32     1 src [E] i32      2 dst [E] i32
//  3 r_dir     4 r_type       5 r_ring           6 p_dir
//  7 p_type    8 p_ring       9 r_len f32       10 p_len f32
// 11 emb_dir [8,32]          12 emb_type [16,32] 13 emb_ring [4,32]
// 14 rbf_W [20,32]           15 rbf_b [32]
// 16 W1 [64,128]             17 b1 [128]
// 18 W2 [128,64]             19 b2 [64]
// Output: [N,64] f32
// ---------------------------------------------------------------------------
extern "C" void kernel_launch(void* const* d_in, const int* in_sizes, int n_in,
                              void* d_out, int out_size) {
    const float* atom     = (const float*)d_in[0];
    const int*   src      = (const int*)d_in[1];
    const int*   dst      = (const int*)d_in[2];
    const int*   rdir     = (const int*)d_in[3];
    const int*   rtype    = (const int*)d_in[4];
    const int*   rring    = (const int*)d_in[5];
    const int*   pdir     = (const int*)d_in[6];
    const int*   ptype    = (const int*)d_in[7];
    const int*   pring    = (const int*)d_in[8];
    const float* rlen     = (const float*)d_in[9];
    const float* plen     = (const float*)d_in[10];
    const float* emb_dir  = (const float*)d_in[11];
    const float* emb_type = (const float*)d_in[12];
    const float* emb_ring = (const float*)d_in[13];
    const float* rbf_W    = (const float*)d_in[14];
    const float* rbf_b    = (const float*)d_in[15];
    const float* W1       = (const float*)d_in[16];
    const float* b1       = (const float*)d_in[17];
    const float* W2       = (const float*)d_in[18];
    const float* b2       = (const float*)d_in[19];
    float* out = (float*)d_out;

    // 0) build lookup tables (tiny)
    build_ct_kernel<<<(512 * 32 + 255) / 256, 256>>>(emb_dir, emb_type, emb_ring);
    build_tab_kernel<<<(TAB_INTERVALS * 16 + 255) / 256, 256>>>(rbf_W, rbf_b);

    // 1) zero the agg buffer (= d_out)
    int n4 = (N_NODES * CD) / 4;
    zero_kernel<<<4096, 256>>>((float4*)out, n4);

    // 2) edge scatter (R7 config)
    edge_kernel<<<2368, 256>>>(atom, src, dst, rdir, rtype, rring,
                               pdir, ptype, pring, rlen, plen, out);

    // 3) persistent node MLP on tensor cores
    size_t smem = (size_t)(CD * SW1_STRIDE + HID * SW2_STRIDE   // weights
                           + HID + CD                            // biases
                           + 8 * 16 * SA_STRIDE                  // A strips
                           + 8 * 16 * SH_STRIDE) * 4;            // H strips
    cudaFuncSetAttribute(mlp_kernel, cudaFuncAttributeMaxDynamicSharedMemorySize,
                         (int)smem);
    mlp_kernel<<<148, 256, smem>>>(out, W1, b1, W2, b2);
}

// round 11
// speedup vs baseline: 4.9002x; 1.0713x over previous
#include <cuda_runtime.h>
#include <cuda_bf16.h>
#include <cstdint>

// Problem constants (fixed by the reference)
#define N_NODES 500000
#define N_EDGES 1000000
#define D       32
#define CD      64
#define HID     128
#define NCEN    20
#define RBF_GAMMA 10.0f

#define TAB_INTERVALS 2048        // PWL intervals over len in [0,2)
#define TAB_SCALE     1024.0f     // intervals per unit length

#define FULLMASK 0xffffffffu

typedef unsigned long long ull;

// ---- device-global precomputed tables (allowed scratch) --------------------
__device__ float  g_ct[512 * 32];               // combined cat embedding
__device__ float4 g_tabv[TAB_INTERVALS * 8];    // PWL values, ch quad q = ch 4q..4q+3
__device__ float4 g_tabd[TAB_INTERVALS * 8];    // PWL slopes
__device__ int4   g_pack[N_EDGES];              // {icr|icp<<16, ir|ip<<16, fr, fp}

// ---------------------------------------------------------------------------
// Setup kernel A: combined categorical embedding table (512 combos x 32 ch)
// ---------------------------------------------------------------------------
__global__ void build_ct_kernel(const float* __restrict__ emb_dir,
                                const float* __restrict__ emb_type,
                                const float* __restrict__ emb_ring) {
    int idx = blockIdx.x * blockDim.x + threadIdx.x;
    if (idx >= 512 * 32) return;
    int l = idx & 31;
    int comb = idx >> 5;
    int ring = comb & 3;
    int type = (comb >> 2) & 15;
    int dir  = comb >> 6;
    g_ct[idx] = emb_dir[dir * 32 + l] + emb_type[type * 32 + l] + emb_ring[ring * 32 + l];
}

// ---------------------------------------------------------------------------
// Setup kernel B: PWL tables (value-quad + slope-quad layout).
// Thread per (interval i, quad q): channels 4q..4q+3.
// ---------------------------------------------------------------------------
__global__ void build_tab_kernel(const float* __restrict__ rbf_W,
                                 const float* __restrict__ rbf_b) {
    int idx = blockIdx.x * blockDim.x + threadIdx.x;
    if (idx >= TAB_INTERVALS * 8) return;
    int q = idx & 7;        // channel quad
    int i = idx >> 3;       // interval
    float x0 = (float)i / TAB_SCALE;
    float x1 = (float)(i + 1) / TAB_SCALE;
    float v0[4], v1[4];
#pragma unroll
    for (int c = 0; c < 4; c++) { v0[c] = rbf_b[4 * q + c]; v1[c] = v0[c]; }
#pragma unroll
    for (int k = 0; k < NCEN; k++) {
        float ctr = 0.1f * (float)k;
        float d0 = x0 - ctr, d1 = x1 - ctr;
        float e0 = expf(-RBF_GAMMA * d0 * d0);
        float e1 = expf(-RBF_GAMMA * d1 * d1);
#pragma unroll
        for (int c = 0; c < 4; c++) {
            float w = rbf_W[k * 32 + 4 * q + c];
            v0[c] = fmaf(e0, w, v0[c]);
            v1[c] = fmaf(e1, w, v1[c]);
        }
    }
    g_tabv[idx] = make_float4(v0[0], v0[1], v0[2], v0[3]);
    g_tabd[idx] = make_float4(v1[0] - v0[0], v1[1] - v0[1],
                              v1[2] - v0[2], v1[3] - v0[3]);
}

// ---------------------------------------------------------------------------
// Setup kernel C: pack per-edge metadata into one int4 (coalesced streams in,
// one vector out) — collapses 8 broadcast loads/edge in the scatter kernel.
// ---------------------------------------------------------------------------
__global__ void build_pack_kernel(
    const int* __restrict__ rdir, const int* __restrict__ rtype, const int* __restrict__ rring,
    const int* __restrict__ pdir, const int* __restrict__ ptype, const int* __restrict__ pring,
    const float* __restrict__ rlen, const float* __restrict__ plen)
{
    int e = blockIdx.x * blockDim.x + threadIdx.x;
    if (e >= N_EDGES) return;
    int icr = (rdir[e] * 16 + rtype[e]) * 4 + rring[e];
    int icp = (pdir[e] * 16 + ptype[e]) * 4 + pring[e];
    float xr = rlen[e] * TAB_SCALE;
    int   ir = min((int)xr, TAB_INTERVALS - 1);
    float fr = xr - (float)ir;
    float xp = plen[e] * TAB_SCALE;
    int   ip = min((int)xp, TAB_INTERVALS - 1);
    float fp_ = xp - (float)ip;
    int4 P;
    P.x = icr | (icp << 16);
    P.y = ir | (ip << 16);
    P.z = __float_as_int(fr);
    P.w = __float_as_int(fp_);
    g_pack[e] = P;
}

// ---------------------------------------------------------------------------
// Kernel 1: zero the aggregation buffer (we reuse d_out as agg scratch)
// ---------------------------------------------------------------------------
__global__ void zero_kernel(float4* __restrict__ p, int n4) {
    int i = blockIdx.x * blockDim.x + threadIdx.x;
    int stride = gridDim.x * blockDim.x;
    float4 z = make_float4(0.f, 0.f, 0.f, 0.f);
    for (; i < n4; i += stride) p[i] = z;
}

// ---------------------------------------------------------------------------
// Kernel 2: edge message + scatter. TWO edges per warp, lane m owns channels
// 4m..4m+3 (quad q = m&7 within each 32-ch half). Packed metadata (1 load),
// quad-layout tab (1 wavefront/group/load), 2-deep pipeline, 64-reg cap.
// ---------------------------------------------------------------------------
struct EdgeVals {
    float4 a;
    float ad0, ad1, ad2, ad3;
    long  qoff;
};

__device__ __forceinline__ void edge_compute(
    int e, int m, int q, bool upper,
    const float* __restrict__ atom,
    const int* __restrict__ src, const int* __restrict__ dst,
    EdgeVals& V)
{
    const int4 P = g_pack[e];
    const int s  = src[e];
    const int dn = dst[e];
    const int icr = P.x & 0xffff;
    const int icp = P.x >> 16;
    const int ir  = P.y & 0xffff;
    const int ip  = P.y >> 16;
    const float fr  = __int_as_float(P.z);
    const float fp_ = __int_as_float(P.w);

    float4 ctr = *reinterpret_cast<const float4*>(&g_ct[icr * 32 + 4 * q]);
    float4 ctp = *reinterpret_cast<const float4*>(&g_ct[icp * 32 + 4 * q]);
    float4 vr = g_tabv[ir * 8 + q];
    float4 dr = g_tabd[ir * 8 + q];
    float4 vp = g_tabv[ip * 8 + q];
    float4 dp = g_tabd[ip * 8 + q];

    V.a = *reinterpret_cast<const float4*>(&atom[(size_t)s * CD + 4 * m]);

    float re0 = ctr.x + fmaf(fr, dr.x, vr.x);
    float re1 = ctr.y + fmaf(fr, dr.y, vr.y);
    float re2 = ctr.z + fmaf(fr, dr.z, vr.z);
    float re3 = ctr.w + fmaf(fr, dr.w, vr.w);

    float pe0 = ctp.x + fmaf(fp_, dp.x, vp.x);
    float pe1 = ctp.y + fmaf(fp_, dp.y, vp.y);
    float pe2 = ctp.z + fmaf(fp_, dp.z, vp.z);
    float pe3 = ctp.w + fmaf(fp_, dp.w, vp.w);

    V.ad0 = upper ? (pe0 - re0) : re0;
    V.ad1 = upper ? (pe1 - re1) : re1;
    V.ad2 = upper ? (pe2 - re2) : re2;
    V.ad3 = upper ? (pe3 - re3) : re3;
    V.qoff = (long)dn * CD + 4 * m;
}

__device__ __forceinline__ void edge_commit(float* agg, const EdgeVals& V) {
    float v0 = V.a.x + V.ad0;
    float v1 = V.a.y + V.ad1;
    float v2 = V.a.z + V.ad2;
    float v3 = V.a.w + V.ad3;
    float* p = agg + V.qoff;
    asm volatile("red.global.add.v4.f32 [%0], {%1,%2,%3,%4};"
                 :: "l"(p), "f"(v0), "f"(v1), "f"(v2), "f"(v3));
}

__global__ __launch_bounds__(256, 4) void edge_kernel(
    const float* __restrict__ atom,
    const int*   __restrict__ src, const int* __restrict__ dst,
    float* __restrict__ agg)
{
    const int l = threadIdx.x & 31;
    const int g = l >> 4;                 // edge group within warp
    const int m = l & 15;                 // lane within group
    const int q = m & 7;                  // channel quad within 32-ch half
    const bool upper = (m >= 8);
    const int warp = (blockIdx.x * blockDim.x + threadIdx.x) >> 5;
    const int nwarps = (gridDim.x * blockDim.x) >> 5;
    const int stride = nwarps * 2;

    for (int e = warp * 2 + g; e < N_EDGES; e += 2 * stride) {
        int e1 = e + stride;
        EdgeVals V0, V1;
        edge_compute(e, m, q, upper, atom, src, dst, V0);
        bool has1 = (e1 < N_EDGES);
        if (has1) edge_compute(e1, m, q, upper, atom, src, dst, V1);
        edge_commit(agg, V0);
        if (has1) edge_commit(agg, V1);
    }
}

// ---------------------------------------------------------------------------
// Kernel 3: PERSISTENT node MLP on tensor cores (mma.sync m16n8k8 tf32).
// R10 config (measured ~135us): 148 blocks x 256 thr, weights staged once/SM,
// warp-private 16-row strips, register prefetch of the next strip.
// ---------------------------------------------------------------------------
#define SA_STRIDE 68
#define SH_STRIDE 132
#define SW1_STRIDE 136
#define SW2_STRIDE 72
#define NSTRIPS (N_NODES / 16)   // 31250, exact

__device__ __forceinline__ unsigned cvt_tf32(float x) {
    unsigned r;
    asm("cvt.rna.tf32.f32 %0, %1;" : "=r"(r) : "f"(x));
    return r;
}

__device__ __forceinline__ void mma_tf32(float c[4], const unsigned a[4],
                                         unsigned b0, unsigned b1) {
    asm("mma.sync.aligned.m16n8k8.row.col.f32.tf32.tf32.f32 "
        "{%0,%1,%2,%3}, {%4,%5,%6,%7}, {%8,%9}, {%0,%1,%2,%3};"
        : "+f"(c[0]), "+f"(c[1]), "+f"(c[2]), "+f"(c[3])
        : "r"(a[0]), "r"(a[1]), "r"(a[2]), "r"(a[3]), "r"(b0), "r"(b1));
}

__global__ __launch_bounds__(256) void mlp_kernel(
    float* __restrict__ inout,
    const float* __restrict__ W1, const float* __restrict__ b1,
    const float* __restrict__ W2, const float* __restrict__ b2)
{
    extern __shared__ unsigned smu[];
    unsigned* sW1 = smu;
    unsigned* sW2 = sW1 + CD * SW1_STRIDE;
    float*    sb1 = (float*)(sW2 + HID * SW2_STRIDE);
    float*    sb2 = sb1 + HID;
    float*    sA  = sb2 + CD;
    unsigned* sH  = (unsigned*)(sA + 8 * 16 * SA_STRIDE);

    const int tid  = threadIdx.x;
    const int w    = tid >> 5;
    const int lane = tid & 31;
    const int gid  = lane >> 2;
    const int tig  = lane & 3;

    for (int idx = tid; idx < CD * HID; idx += 256) {
        int k = idx >> 7, n = idx & 127;
        sW1[k * SW1_STRIDE + n] = cvt_tf32(W1[idx]);
    }
    for (int idx = tid; idx < HID * CD; idx += 256) {
        int i = idx >> 6, c = idx & 63;
        sW2[i * SW2_STRIDE + c] = cvt_tf32(W2[idx]);
    }
    if (tid < HID) sb1[tid] = b1[tid];
    if (tid < CD)  sb2[tid] = b2[tid];
    __syncthreads();

    float* sAw = sA + w * 16 * SA_STRIDE;
    unsigned* sHw = sH + w * 16 * SH_STRIDE;

    const int gwarp   = blockIdx.x * 8 + w;
    const int wstride = gridDim.x * 8;
    const int r0 = lane >> 4;
    const int c4 = lane & 15;

    long strip = gwarp;
    float4 pf[8];
    if (strip < NSTRIPS) {
        const float* base = inout + strip * 16 * CD;
#pragma unroll
        for (int it = 0; it < 8; it++)
            pf[it] = *reinterpret_cast<const float4*>(base + (it * 2 + r0) * CD + c4 * 4);
    }

    while (strip < NSTRIPS) {
#pragma unroll
        for (int it = 0; it < 8; it++)
            *reinterpret_cast<float4*>(sAw + (it * 2 + r0) * SA_STRIDE + c4 * 4) = pf[it];
        __syncwarp();

        unsigned afr[8][4];
#pragma unroll
        for (int k = 0; k < 8; k++) {
            int kc = k * 8;
            afr[k][0] = cvt_tf32(sAw[gid * SA_STRIDE + kc + tig]);
            afr[k][1] = cvt_tf32(sAw[(gid + 8) * SA_STRIDE + kc + tig]);
            afr[k][2] = cvt_tf32(sAw[gid * SA_STRIDE + kc + tig + 4]);
            afr[k][3] = cvt_tf32(sAw[(gid + 8) * SA_STRIDE + kc + tig + 4]);
        }

        long next = strip + wstride;
        if (next < NSTRIPS) {
            const float* base = inout + next * 16 * CD;
#pragma unroll
            for (int it = 0; it < 8; it++)
                pf[it] = *reinterpret_cast<const float4*>(base + (it * 2 + r0) * CD + c4 * 4);
        }

#pragma unroll
        for (int n0 = 0; n0 < 16; n0 += 2) {
            float cA[4] = {0.f, 0.f, 0.f, 0.f};
            float cB[4] = {0.f, 0.f, 0.f, 0.f};
            const int nbA = n0 * 8;
            const int nbB = nbA + 8;
#pragma unroll
            for (int k = 0; k < 8; k++) {
                const unsigned* wr0 = &sW1[(k * 8 + tig) * SW1_STRIDE];
                const unsigned* wr1 = &sW1[(k * 8 + tig + 4) * SW1_STRIDE];
                unsigned bA0 = wr0[nbA + gid];
                unsigned bA1 = wr1[nbA + gid];
                unsigned bB0 = wr0[nbB + gid];
                unsigned bB1 = wr1[nbB + gid];
                mma_tf32(cA, afr[k], bA0, bA1);
                mma_tf32(cB, afr[k], bB0, bB1);
            }
#pragma unroll
            for (int t = 0; t < 2; t++) {
                const float* c = t ? cB : cA;
                int col = (t ? nbB : nbA) + 2 * tig;
                float bia0 = sb1[col], bia1 = sb1[col + 1];
                sHw[gid * SH_STRIDE + col]           = cvt_tf32(fmaxf(c[0] + bia0, 0.f));
                sHw[gid * SH_STRIDE + col + 1]       = cvt_tf32(fmaxf(c[1] + bia1, 0.f));
                sHw[(gid + 8) * SH_STRIDE + col]     = cvt_tf32(fmaxf(c[2] + bia0, 0.f));
                sHw[(gid + 8) * SH_STRIDE + col + 1] = cvt_tf32(fmaxf(c[3] + bia1, 0.f));
            }
        }
        __syncwarp();

        unsigned ah[16][4];
#pragma unroll
        for (int k = 0; k < 16; k++) {
            int kc = k * 8;
            ah[k][0] = sHw[gid * SH_STRIDE + kc + tig];
            ah[k][1] = sHw[(gid + 8) * SH_STRIDE + kc + tig];
            ah[k][2] = sHw[gid * SH_STRIDE + kc + tig + 4];
            ah[k][3] = sHw[(gid + 8) * SH_STRIDE + kc + tig + 4];
        }

        const long rowBase = strip * 16;
        float* out0 = inout + (rowBase + gid) * CD;
        float* out1 = inout + (rowBase + gid + 8) * CD;
#pragma unroll
        for (int n0 = 0; n0 < 8; n0 += 2) {
            float cA[4] = {0.f, 0.f, 0.f, 0.f};
            float cB[4] = {0.f, 0.f, 0.f, 0.f};
            const int nbA = n0 * 8;
            const int nbB = nbA + 8;
#pragma unroll
            for (int k = 0; k < 16; k++) {
                const unsigned* wr0 = &sW2[(k * 8 + tig) * SW2_STRIDE];
                const unsigned* wr1 = &sW2[(k * 8 + tig + 4) * SW2_STRIDE];
                unsigned bA0 = wr0[nbA + gid];
                unsigned bA1 = wr1[nbA + gid];
                unsigned bB0 = wr0[nbB + gid];
                unsigned bB1 = wr1[nbB + gid];
                mma_tf32(cA, ah[k], bA0, bA1);
                mma_tf32(cB, ah[k], bB0, bB1);
            }
#pragma unroll
            for (int t = 0; t < 2; t++) {
                const float* c = t ? cB : cA;
                int col = (t ? nbB : nbA) + 2 * tig;
                float bia0 = sb2[col], bia1 = sb2[col + 1];
                float2 ra = make_float2(fmaxf(c[0] + bia0, 0.f),
                                        fmaxf(c[1] + bia1, 0.f));
                float2 rb = make_float2(fmaxf(c[2] + bia0, 0.f),
                                        fmaxf(c[3] + bia1, 0.f));
                *reinterpret_cast<float2*>(out0 + col) = ra;
                *reinterpret_cast<float2*>(out1 + col) = rb;
            }
        }

        strip = next;
    }
}

// ---------------------------------------------------------------------------
// Launch
// Inputs (metadata order):
//  0 atom_repr [N,64] f32     1 src [E] i32      2 dst [E] i32
//  3 r_dir     4 r_type       5 r_ring           6 p_dir
//  7 p_type    8 p_ring       9 r_len f32       10 p_len f32
// 11 emb_dir [8,32]          12 emb_type [16,32] 13 emb_ring [4,32]
// 14 rbf_W [20,32]           15 rbf_b [32]
// 16 W1 [64,128]             17 b1 [128]
// 18 W2 [128,64]             19 b2 [64]
// Output: [N,64] f32
// ---------------------------------------------------------------------------
extern "C" void kernel_launch(void* const* d_in, const int* in_sizes, int n_in,
                              void* d_out, int out_size) {
    const float* atom     = (const float*)d_in[0];
    const int*   src      = (const int*)d_in[1];
    const int*   dst      = (const int*)d_in[2];
    const int*   rdir     = (const int*)d_in[3];
    const int*   rtype    = (const int*)d_in[4];
    const int*   rring    = (const int*)d_in[5];
    const int*   pdir     = (const int*)d_in[6];
    const int*   ptype    = (const int*)d_in[7];
    const int*   pring    = (const int*)d_in[8];
    const float* rlen     = (const float*)d_in[9];
    const float* plen     = (const float*)d_in[10];
    const float* emb_dir  = (const float*)d_in[11];
    const float* emb_type = (const float*)d_in[12];
    const float* emb_ring = (const float*)d_in[13];
    const float* rbf_W    = (const float*)d_in[14];
    const float* rbf_b    = (const float*)d_in[15];
    const float* W1       = (const float*)d_in[16];
    const float* b1       = (const float*)d_in[17];
    const float* W2       = (const float*)d_in[18];
    const float* b2       = (const float*)d_in[19];
    float* out = (float*)d_out;

    // 0) build lookup tables + packed edge metadata
    build_ct_kernel<<<(512 * 32 + 255) / 256, 256>>>(emb_dir, emb_type, emb_ring);
    build_tab_kernel<<<(TAB_INTERVALS * 8 + 255) / 256, 256>>>(rbf_W, rbf_b);
    build_pack_kernel<<<(N_EDGES + 255) / 256, 256>>>(rdir, rtype, rring,
                                                      pdir, ptype, pring,
                                                      rlen, plen);

    // 1) zero the agg buffer (= d_out)
    int n4 = (N_NODES * CD) / 4;
    zero_kernel<<<4096, 256>>>((float4*)out, n4);

    // 2) edge scatter (packed metadata, quad tab layout)
    edge_kernel<<<2368, 256>>>(atom, src, dst, out);

    // 3) persistent node MLP on tensor cores
    size_t smem = (size_t)(CD * SW1_STRIDE + HID * SW2_STRIDE
                           + HID + CD
                           + 8 * 16 * SA_STRIDE
                           + 8 * 16 * SH_STRIDE) * 4;
    cudaFuncSetAttribute(mlp_kernel, cudaFuncAttributeMaxDynamicSharedMemorySize,
                         (int)smem);
    mlp_kernel<<<148, 256, smem>>>(out, W1, b1, W2, b2);
}

// round 12
// speedup vs baseline: 5.3154x; 1.0847x over previous
#include <cuda_runtime.h>
#include <cuda_bf16.h>
#include <cstdint>

// Problem constants (fixed by the reference)
#define N_NODES 500000
#define N_EDGES 1000000
#define D       32
#define CD      64
#define HID     128
#define NCEN    20
#define RBF_GAMMA 10.0f

#define TAB_INTERVALS 2048        // PWL intervals over len in [0,2)
#define TAB_SCALE     1024.0f     // intervals per unit length

#define FULLMASK 0xffffffffu

typedef unsigned long long ull;

// ---- device-global precomputed tables (allowed scratch) --------------------
__device__ float  g_ct[512 * 32];               // combined cat embedding
__device__ float4 g_tabv[TAB_INTERVALS * 8];    // PWL values, ch quad q
__device__ float4 g_tabd[TAB_INTERVALS * 8];    // PWL slopes
__device__ int4   g_pack[N_EDGES];              // {icr|icp<<16, ir|ip<<16, fr, fp}

// ---------------------------------------------------------------------------
// Fused prep kernel: zero agg + pack edge metadata + build ct/tab tables.
// One launch, grid-stride over disjoint index ranges (no interdependence).
// ---------------------------------------------------------------------------
__global__ void prep_kernel(
    float4* __restrict__ out4,
    const int* __restrict__ rdir, const int* __restrict__ rtype, const int* __restrict__ rring,
    const int* __restrict__ pdir, const int* __restrict__ ptype, const int* __restrict__ pring,
    const float* __restrict__ rlen, const float* __restrict__ plen,
    const float* __restrict__ emb_dir, const float* __restrict__ emb_type,
    const float* __restrict__ emb_ring,
    const float* __restrict__ rbf_W, const float* __restrict__ rbf_b)
{
    const int ZN = N_NODES * CD / 4;            // 8,000,000 zero items
    const int PN = ZN + N_EDGES;                // + pack items
    const int CN = PN + 512 * 32;               // + ct items
    const int TN = CN + TAB_INTERVALS * 8;      // + tab items
    const float4 z4 = make_float4(0.f, 0.f, 0.f, 0.f);

    for (int i = blockIdx.x * blockDim.x + threadIdx.x; i < TN;
         i += gridDim.x * blockDim.x) {
        if (i < ZN) {
            out4[i] = z4;
        } else if (i < PN) {
            int e = i - ZN;
            int icr = (rdir[e] * 16 + rtype[e]) * 4 + rring[e];
            int icp = (pdir[e] * 16 + ptype[e]) * 4 + pring[e];
            float xr = rlen[e] * TAB_SCALE;
            int   ir = min((int)xr, TAB_INTERVALS - 1);
            float fr = xr - (float)ir;
            float xp = plen[e] * TAB_SCALE;
            int   ip = min((int)xp, TAB_INTERVALS - 1);
            float fp_ = xp - (float)ip;
            int4 P;
            P.x = icr | (icp << 16);
            P.y = ir | (ip << 16);
            P.z = __float_as_int(fr);
            P.w = __float_as_int(fp_);
            g_pack[e] = P;
        } else if (i < CN) {
            int idx = i - PN;
            int l = idx & 31;
            int comb = idx >> 5;
            int ring = comb & 3;
            int type = (comb >> 2) & 15;
            int dir  = comb >> 6;
            g_ct[idx] = emb_dir[dir * 32 + l] + emb_type[type * 32 + l]
                      + emb_ring[ring * 32 + l];
        } else {
            int idx = i - CN;
            int q = idx & 7;
            int iv = idx >> 3;
            float x0 = (float)iv / TAB_SCALE;
            float x1 = (float)(iv + 1) / TAB_SCALE;
            float v0[4], v1[4];
#pragma unroll
            for (int c = 0; c < 4; c++) { v0[c] = rbf_b[4 * q + c]; v1[c] = v0[c]; }
#pragma unroll
            for (int k = 0; k < NCEN; k++) {
                float ctr = 0.1f * (float)k;
                float d0 = x0 - ctr, d1 = x1 - ctr;
                float e0 = expf(-RBF_GAMMA * d0 * d0);
                float e1 = expf(-RBF_GAMMA * d1 * d1);
#pragma unroll
                for (int c = 0; c < 4; c++) {
                    float wv = rbf_W[k * 32 + 4 * q + c];
                    v0[c] = fmaf(e0, wv, v0[c]);
                    v1[c] = fmaf(e1, wv, v1[c]);
                }
            }
            g_tabv[idx] = make_float4(v0[0], v0[1], v0[2], v0[3]);
            g_tabd[idx] = make_float4(v1[0] - v0[0], v1[1] - v0[1],
                                      v1[2] - v0[2], v1[3] - v0[3]);
        }
    }
}

// ---------------------------------------------------------------------------
// Kernel 2: edge message + scatter (R11 config, measured ~147us). TWO edges
// per warp, lane m owns channels 4m..4m+3, packed metadata, quad tab,
// 2-deep pipeline, 64-reg cap.
// ---------------------------------------------------------------------------
struct EdgeVals {
    float4 a;
    float ad0, ad1, ad2, ad3;
    long  qoff;
};

__device__ __forceinline__ void edge_compute(
    int e, int m, int q, bool upper,
    const float* __restrict__ atom,
    const int* __restrict__ src, const int* __restrict__ dst,
    EdgeVals& V)
{
    const int4 P = g_pack[e];
    const int s  = src[e];
    const int dn = dst[e];
    const int icr = P.x & 0xffff;
    const int icp = P.x >> 16;
    const int ir  = P.y & 0xffff;
    const int ip  = P.y >> 16;
    const float fr  = __int_as_float(P.z);
    const float fp_ = __int_as_float(P.w);

    float4 ctr = *reinterpret_cast<const float4*>(&g_ct[icr * 32 + 4 * q]);
    float4 ctp = *reinterpret_cast<const float4*>(&g_ct[icp * 32 + 4 * q]);
    float4 vr = g_tabv[ir * 8 + q];
    float4 dr = g_tabd[ir * 8 + q];
    float4 vp = g_tabv[ip * 8 + q];
    float4 dp = g_tabd[ip * 8 + q];

    V.a = *reinterpret_cast<const float4*>(&atom[(size_t)s * CD + 4 * m]);

    float re0 = ctr.x + fmaf(fr, dr.x, vr.x);
    float re1 = ctr.y + fmaf(fr, dr.y, vr.y);
    float re2 = ctr.z + fmaf(fr, dr.z, vr.z);
    float re3 = ctr.w + fmaf(fr, dr.w, vr.w);

    float pe0 = ctp.x + fmaf(fp_, dp.x, vp.x);
    float pe1 = ctp.y + fmaf(fp_, dp.y, vp.y);
    float pe2 = ctp.z + fmaf(fp_, dp.z, vp.z);
    float pe3 = ctp.w + fmaf(fp_, dp.w, vp.w);

    V.ad0 = upper ? (pe0 - re0) : re0;
    V.ad1 = upper ? (pe1 - re1) : re1;
    V.ad2 = upper ? (pe2 - re2) : re2;
    V.ad3 = upper ? (pe3 - re3) : re3;
    V.qoff = (long)dn * CD + 4 * m;
}

__device__ __forceinline__ void edge_commit(float* agg, const EdgeVals& V) {
    float v0 = V.a.x + V.ad0;
    float v1 = V.a.y + V.ad1;
    float v2 = V.a.z + V.ad2;
    float v3 = V.a.w + V.ad3;
    float* p = agg + V.qoff;
    asm volatile("red.global.add.v4.f32 [%0], {%1,%2,%3,%4};"
                 :: "l"(p), "f"(v0), "f"(v1), "f"(v2), "f"(v3));
}

__global__ __launch_bounds__(256, 4) void edge_kernel(
    const float* __restrict__ atom,
    const int*   __restrict__ src, const int* __restrict__ dst,
    float* __restrict__ agg)
{
    const int l = threadIdx.x & 31;
    const int g = l >> 4;
    const int m = l & 15;
    const int q = m & 7;
    const bool upper = (m >= 8);
    const int warp = (blockIdx.x * blockDim.x + threadIdx.x) >> 5;
    const int nwarps = (gridDim.x * blockDim.x) >> 5;
    const int stride = nwarps * 2;

    for (int e = warp * 2 + g; e < N_EDGES; e += 2 * stride) {
        int e1 = e + stride;
        EdgeVals V0, V1;
        edge_compute(e, m, q, upper, atom, src, dst, V0);
        bool has1 = (e1 < N_EDGES);
        if (has1) edge_compute(e1, m, q, upper, atom, src, dst, V1);
        edge_commit(agg, V0);
        if (has1) edge_commit(agg, V1);
    }
}

// ---------------------------------------------------------------------------
// Kernel 3: PERSISTENT node MLP on tensor cores, STRIP-PAIR version.
// Each warp processes TWO 16-row strips per iteration; every B-fragment LDS
// feeds two mmas (one per strip) -> B smem traffic per strip halves.
// Stage 2 runs in two k-halves accumulating in registers, so the H buffer is
// 64 cols (half) per strip. 148 blocks x 256 thr, 1 block/SM.
// ---------------------------------------------------------------------------
#define SA_STRIDE 68
#define SHH_STRIDE 68            // half-H (64 cols + pad)
#define SW1_STRIDE 136
#define SW2_STRIDE 72
#define NSTRIPS (N_NODES / 16)   // 31250
#define NPAIRS  (NSTRIPS / 2)    // 15625

__device__ __forceinline__ unsigned cvt_tf32(float x) {
    unsigned r;
    asm("cvt.rna.tf32.f32 %0, %1;" : "=r"(r) : "f"(x));
    return r;
}

__device__ __forceinline__ void mma_tf32(float c[4], const unsigned a[4],
                                         unsigned b0, unsigned b1) {
    asm("mma.sync.aligned.m16n8k8.row.col.f32.tf32.tf32.f32 "
        "{%0,%1,%2,%3}, {%4,%5,%6,%7}, {%8,%9}, {%0,%1,%2,%3};"
        : "+f"(c[0]), "+f"(c[1]), "+f"(c[2]), "+f"(c[3])
        : "r"(a[0]), "r"(a[1]), "r"(a[2]), "r"(a[3]), "r"(b0), "r"(b1));
}

__global__ __launch_bounds__(256) void mlp_kernel(
    float* __restrict__ inout,
    const float* __restrict__ W1, const float* __restrict__ b1,
    const float* __restrict__ W2, const float* __restrict__ b2)
{
    extern __shared__ unsigned smu[];
    unsigned* sW1 = smu;                                    // [64][136]
    unsigned* sW2 = sW1 + CD * SW1_STRIDE;                  // [128][72]
    float*    sb1 = (float*)(sW2 + HID * SW2_STRIDE);       // [128]
    float*    sb2 = sb1 + HID;                              // [64]
    float*    sA  = sb2 + CD;                               // 8 x [16][68]
    unsigned* sH0 = (unsigned*)(sA + 8 * 16 * SA_STRIDE);   // 8 x [16][68]
    unsigned* sH1 = sH0 + 8 * 16 * SHH_STRIDE;              // 8 x [16][68]

    const int tid  = threadIdx.x;
    const int w    = tid >> 5;
    const int lane = tid & 31;
    const int gid  = lane >> 2;
    const int tig  = lane & 3;

    for (int idx = tid; idx < CD * HID; idx += 256) {
        int k = idx >> 7, n = idx & 127;
        sW1[k * SW1_STRIDE + n] = cvt_tf32(W1[idx]);
    }
    for (int idx = tid; idx < HID * CD; idx += 256) {
        int i = idx >> 6, c = idx & 63;
        sW2[i * SW2_STRIDE + c] = cvt_tf32(W2[idx]);
    }
    if (tid < HID) sb1[tid] = b1[tid];
    if (tid < CD)  sb2[tid] = b2[tid];
    __syncthreads();

    float*    sAw  = sA  + w * 16 * SA_STRIDE;
    unsigned* sH0w = sH0 + w * 16 * SHH_STRIDE;
    unsigned* sH1w = sH1 + w * 16 * SHH_STRIDE;

    const int gwarp   = blockIdx.x * 8 + w;
    const int wstride = gridDim.x * 8;          // 1184
    const int r0 = lane >> 4;
    const int c4 = lane & 15;

    long pair = gwarp;
    float4 pf0[8], pf1[8];
    if (pair < NPAIRS) {
        const float* b0p = inout + (2 * pair) * 16 * CD;
        const float* b1p = inout + (2 * pair + 1) * 16 * CD;
#pragma unroll
        for (int it = 0; it < 8; it++) {
            pf0[it] = *reinterpret_cast<const float4*>(b0p + (it * 2 + r0) * CD + c4 * 4);
            pf1[it] = *reinterpret_cast<const float4*>(b1p + (it * 2 + r0) * CD + c4 * 4);
        }
    }

    while (pair < NPAIRS) {
        const long s0 = 2 * pair;
        const long s1 = s0 + 1;
        const long nextPair = pair + wstride;

        // ---- strip0: commit A, extract fragments ----
        __syncwarp();
#pragma unroll
        for (int it = 0; it < 8; it++)
            *reinterpret_cast<float4*>(sAw + (it * 2 + r0) * SA_STRIDE + c4 * 4) = pf0[it];
        __syncwarp();
        unsigned afr0[8][4];
#pragma unroll
        for (int k = 0; k < 8; k++) {
            int kc = k * 8;
            afr0[k][0] = cvt_tf32(sAw[gid * SA_STRIDE + kc + tig]);
            afr0[k][1] = cvt_tf32(sAw[(gid + 8) * SA_STRIDE + kc + tig]);
            afr0[k][2] = cvt_tf32(sAw[gid * SA_STRIDE + kc + tig + 4]);
            afr0[k][3] = cvt_tf32(sAw[(gid + 8) * SA_STRIDE + kc + tig + 4]);
        }
        __syncwarp();
        // ---- strip1: commit A, extract fragments ----
#pragma unroll
        for (int it = 0; it < 8; it++)
            *reinterpret_cast<float4*>(sAw + (it * 2 + r0) * SA_STRIDE + c4 * 4) = pf1[it];
        __syncwarp();
        unsigned afr1[8][4];
#pragma unroll
        for (int k = 0; k < 8; k++) {
            int kc = k * 8;
            afr1[k][0] = cvt_tf32(sAw[gid * SA_STRIDE + kc + tig]);
            afr1[k][1] = cvt_tf32(sAw[(gid + 8) * SA_STRIDE + kc + tig]);
            afr1[k][2] = cvt_tf32(sAw[gid * SA_STRIDE + kc + tig + 4]);
            afr1[k][3] = cvt_tf32(sAw[(gid + 8) * SA_STRIDE + kc + tig + 4]);
        }

        float acc0[8][4], acc1[8][4];
#pragma unroll
        for (int n0 = 0; n0 < 8; n0++)
#pragma unroll
            for (int t = 0; t < 4; t++) { acc0[n0][t] = 0.f; acc1[n0][t] = 0.f; }

#pragma unroll
        for (int half = 0; half < 2; half++) {
            // ---- stage 1 (this half's 64 H cols), B shared across strips ----
#pragma unroll
            for (int j = 0; j < 8; j++) {
                const int nb = (half * 8 + j) * 8;
                float cA[4] = {0.f, 0.f, 0.f, 0.f};
                float cB[4] = {0.f, 0.f, 0.f, 0.f};
#pragma unroll
                for (int k = 0; k < 8; k++) {
                    unsigned b0 = sW1[(k * 8 + tig) * SW1_STRIDE + nb + gid];
                    unsigned b1v = sW1[(k * 8 + tig + 4) * SW1_STRIDE + nb + gid];
                    mma_tf32(cA, afr0[k], b0, b1v);
                    mma_tf32(cB, afr1[k], b0, b1v);
                }
                const int colg = nb + 2 * tig;        // global H col
                const int coll = j * 8 + 2 * tig;     // local col in half buffer
                const float bi0 = sb1[colg], bi1 = sb1[colg + 1];
                sH0w[gid * SHH_STRIDE + coll]           = cvt_tf32(fmaxf(cA[0] + bi0, 0.f));
                sH0w[gid * SHH_STRIDE + coll + 1]       = cvt_tf32(fmaxf(cA[1] + bi1, 0.f));
                sH0w[(gid + 8) * SHH_STRIDE + coll]     = cvt_tf32(fmaxf(cA[2] + bi0, 0.f));
                sH0w[(gid + 8) * SHH_STRIDE + coll + 1] = cvt_tf32(fmaxf(cA[3] + bi1, 0.f));
                sH1w[gid * SHH_STRIDE + coll]           = cvt_tf32(fmaxf(cB[0] + bi0, 0.f));
                sH1w[gid * SHH_STRIDE + coll + 1]       = cvt_tf32(fmaxf(cB[1] + bi1, 0.f));
                sH1w[(gid + 8) * SHH_STRIDE + coll]     = cvt_tf32(fmaxf(cB[2] + bi0, 0.f));
                sH1w[(gid + 8) * SHH_STRIDE + coll + 1] = cvt_tf32(fmaxf(cB[3] + bi1, 0.f));
            }
            __syncwarp();

            // ---- load H fragments for this half ----
            unsigned ah0[8][4], ah1[8][4];
#pragma unroll
            for (int kt = 0; kt < 8; kt++) {
                int kc = kt * 8;
                ah0[kt][0] = sH0w[gid * SHH_STRIDE + kc + tig];
                ah0[kt][1] = sH0w[(gid + 8) * SHH_STRIDE + kc + tig];
                ah0[kt][2] = sH0w[gid * SHH_STRIDE + kc + tig + 4];
                ah0[kt][3] = sH0w[(gid + 8) * SHH_STRIDE + kc + tig + 4];
                ah1[kt][0] = sH1w[gid * SHH_STRIDE + kc + tig];
                ah1[kt][1] = sH1w[(gid + 8) * SHH_STRIDE + kc + tig];
                ah1[kt][2] = sH1w[gid * SHH_STRIDE + kc + tig + 4];
                ah1[kt][3] = sH1w[(gid + 8) * SHH_STRIDE + kc + tig + 4];
            }

            // ---- prefetch next pair (after last afr use) ----
            if (half == 1 && nextPair < NPAIRS) {
                const float* b0p = inout + (2 * nextPair) * 16 * CD;
                const float* b1p = inout + (2 * nextPair + 1) * 16 * CD;
#pragma unroll
                for (int it = 0; it < 8; it++) {
                    pf0[it] = *reinterpret_cast<const float4*>(b0p + (it * 2 + r0) * CD + c4 * 4);
                    pf1[it] = *reinterpret_cast<const float4*>(b1p + (it * 2 + r0) * CD + c4 * 4);
                }
            }

            // ---- stage 2 partial (k-tiles of this half), B shared ----
#pragma unroll
            for (int n0 = 0; n0 < 8; n0++) {
                const int nb = n0 * 8;
#pragma unroll
                for (int kt = 0; kt < 8; kt++) {
                    const int ktg = half * 8 + kt;
                    unsigned b0 = sW2[(ktg * 8 + tig) * SW2_STRIDE + nb + gid];
                    unsigned b1v = sW2[(ktg * 8 + tig + 4) * SW2_STRIDE + nb + gid];
                    mma_tf32(acc0[n0], ah0[kt], b0, b1v);
                    mma_tf32(acc1[n0], ah1[kt], b0, b1v);
                }
            }
            __syncwarp();   // H half consumed before next-half overwrite
        }

        // ---- epilogue: bias + relu + store both strips ----
        float* o00 = inout + (s0 * 16 + gid) * CD;
        float* o01 = inout + (s0 * 16 + gid + 8) * CD;
        float* o10 = inout + (s1 * 16 + gid) * CD;
        float* o11 = inout + (s1 * 16 + gid + 8) * CD;
#pragma unroll
        for (int n0 = 0; n0 < 8; n0++) {
            const int col = n0 * 8 + 2 * tig;
            const float bi0 = sb2[col], bi1 = sb2[col + 1];
            *reinterpret_cast<float2*>(o00 + col) =
                make_float2(fmaxf(acc0[n0][0] + bi0, 0.f), fmaxf(acc0[n0][1] + bi1, 0.f));
            *reinterpret_cast<float2*>(o01 + col) =
                make_float2(fmaxf(acc0[n0][2] + bi0, 0.f), fmaxf(acc0[n0][3] + bi1, 0.f));
            *reinterpret_cast<float2*>(o10 + col) =
                make_float2(fmaxf(acc1[n0][0] + bi0, 0.f), fmaxf(acc1[n0][1] + bi1, 0.f));
            *reinterpret_cast<float2*>(o11 + col) =
                make_float2(fmaxf(acc1[n0][2] + bi0, 0.f), fmaxf(acc1[n0][3] + bi1, 0.f));
        }

        pair = nextPair;
    }
}

// ---------------------------------------------------------------------------
// Launch
// Inputs (metadata order):
//  0 atom_repr [N,64] f32     1 src [E] i32      2 dst [E] i32
//  3 r_dir     4 r_type       5 r_ring           6 p_dir
//  7 p_type    8 p_ring       9 r_len f32       10 p_len f32
// 11 emb_dir [8,32]          12 emb_type [16,32] 13 emb_ring [4,32]
// 14 rbf_W [20,32]           15 rbf_b [32]
// 16 W1 [64,128]             17 b1 [128]
// 18 W2 [128,64]             19 b2 [64]
// Output: [N,64] f32
// ---------------------------------------------------------------------------
extern "C" void kernel_launch(void* const* d_in, const int* in_sizes, int n_in,
                              void* d_out, int out_size) {
    const float* atom     = (const float*)d_in[0];
    const int*   src      = (const int*)d_in[1];
    const int*   dst      = (const int*)d_in[2];
    const int*   rdir     = (const int*)d_in[3];
    const int*   rtype    = (const int*)d_in[4];
    const int*   rring    = (const int*)d_in[5];
    const int*   pdir     = (const int*)d_in[6];
    const int*   ptype    = (const int*)d_in[7];
    const int*   pring    = (const int*)d_in[8];
    const float* rlen     = (const float*)d_in[9];
    const float* plen     = (const float*)d_in[10];
    const float* emb_dir  = (const float*)d_in[11];
    const float* emb_type = (const float*)d_in[12];
    const float* emb_ring = (const float*)d_in[13];
    const float* rbf_W    = (const float*)d_in[14];
    const float* rbf_b    = (const float*)d_in[15];
    const float* W1       = (const float*)d_in[16];
    const float* b1       = (const float*)d_in[17];
    const float* W2       = (const float*)d_in[18];
    const float* b2       = (const float*)d_in[19];
    float* out = (float*)d_out;

    // 0) fused prep: zero agg + pack metadata + ct/tab tables (one launch)
    prep_kernel<<<2048, 256>>>((float4*)out,
                               rdir, rtype, rring, pdir, ptype, pring,
                               rlen, plen, emb_dir, emb_type, emb_ring,
                               rbf_W, rbf_b);

    // 1) edge scatter
    edge_kernel<<<2368, 256>>>(atom, src, dst, out);

    // 2) persistent strip-pair node MLP on tensor cores
    size_t smem = (size_t)(CD * SW1_STRIDE + HID * SW2_STRIDE
                           + HID + CD
                           + 8 * 16 * SA_STRIDE
                           + 2 * 8 * 16 * SHH_STRIDE) * 4;
    cudaFuncSetAttribute(mlp_kernel, cudaFuncAttributeMaxDynamicSharedMemorySize,
                         (int)smem);
    mlp_kernel<<<148, 256, smem>>>(out, W1, b1, W2, b2);
}

// round 13
// speedup vs baseline: 6.5419x; 1.2308x over previous
#include <cuda_runtime.h>
#include <cuda_fp16.h>
#include <cstdint>

// Problem constants (fixed by the reference)
#define N_NODES 500000
#define N_EDGES 1000000
#define D       32
#define CD      64
#define HID     128
#define NCEN    20
#define RBF_GAMMA 10.0f

#define TAB_INTERVALS 2048        // PWL intervals over len in [0,2)
#define TAB_SCALE     1024.0f     // intervals per unit length

#define FULLMASK 0xffffffffu

// ---- device-global precomputed tables (allowed scratch) --------------------
__device__ float  g_ct[512 * 32];               // combined cat embedding
__device__ float4 g_tabv[TAB_INTERVALS * 8];    // PWL values, ch quad q
__device__ float4 g_tabd[TAB_INTERVALS * 8];    // PWL slopes
__device__ int4   g_pack[N_EDGES];              // {icr|icp<<16, ir|ip<<16, fr, fp}

// ---------------------------------------------------------------------------
// Fused prep kernel: zero agg + pack edge metadata + build ct/tab tables.
// ---------------------------------------------------------------------------
__global__ void prep_kernel(
    float4* __restrict__ out4,
    const int* __restrict__ rdir, const int* __restrict__ rtype, const int* __restrict__ rring,
    const int* __restrict__ pdir, const int* __restrict__ ptype, const int* __restrict__ pring,
    const float* __restrict__ rlen, const float* __restrict__ plen,
    const float* __restrict__ emb_dir, const float* __restrict__ emb_type,
    const float* __restrict__ emb_ring,
    const float* __restrict__ rbf_W, const float* __restrict__ rbf_b)
{
    const int ZN = N_NODES * CD / 4;
    const int PN = ZN + N_EDGES;
    const int CN = PN + 512 * 32;
    const int TN = CN + TAB_INTERVALS * 8;
    const float4 z4 = make_float4(0.f, 0.f, 0.f, 0.f);

    for (int i = blockIdx.x * blockDim.x + threadIdx.x; i < TN;
         i += gridDim.x * blockDim.x) {
        if (i < ZN) {
            out4[i] = z4;
        } else if (i < PN) {
            int e = i - ZN;
            int icr = (rdir[e] * 16 + rtype[e]) * 4 + rring[e];
            int icp = (pdir[e] * 16 + ptype[e]) * 4 + pring[e];
            float xr = rlen[e] * TAB_SCALE;
            int   ir = min((int)xr, TAB_INTERVALS - 1);
            float fr = xr - (float)ir;
            float xp = plen[e] * TAB_SCALE;
            int   ip = min((int)xp, TAB_INTERVALS - 1);
            float fp_ = xp - (float)ip;
            int4 P;
            P.x = icr | (icp << 16);
            P.y = ir | (ip << 16);
            P.z = __float_as_int(fr);
            P.w = __float_as_int(fp_);
            g_pack[e] = P;
        } else if (i < CN) {
            int idx = i - PN;
            int l = idx & 31;
            int comb = idx >> 5;
            int ring = comb & 3;
            int type = (comb >> 2) & 15;
            int dir  = comb >> 6;
            g_ct[idx] = emb_dir[dir * 32 + l] + emb_type[type * 32 + l]
                      + emb_ring[ring * 32 + l];
        } else {
            int idx = i - CN;
            int q = idx & 7;
            int iv = idx >> 3;
            float x0 = (float)iv / TAB_SCALE;
            float x1 = (float)(iv + 1) / TAB_SCALE;
            float v0[4], v1[4];
#pragma unroll
            for (int c = 0; c < 4; c++) { v0[c] = rbf_b[4 * q + c]; v1[c] = v0[c]; }
#pragma unroll
            for (int k = 0; k < NCEN; k++) {
                float ctr = 0.1f * (float)k;
                float d0 = x0 - ctr, d1 = x1 - ctr;
                float e0 = expf(-RBF_GAMMA * d0 * d0);
                float e1 = expf(-RBF_GAMMA * d1 * d1);
#pragma unroll
                for (int c = 0; c < 4; c++) {
                    float wv = rbf_W[k * 32 + 4 * q + c];
                    v0[c] = fmaf(e0, wv, v0[c]);
                    v1[c] = fmaf(e1, wv, v1[c]);
                }
            }
            g_tabv[idx] = make_float4(v0[0], v0[1], v0[2], v0[3]);
            g_tabd[idx] = make_float4(v1[0] - v0[0], v1[1] - v0[1],
                                      v1[2] - v0[2], v1[3] - v0[3]);
        }
    }
}

// ---------------------------------------------------------------------------
// Kernel 2: edge message + scatter (R11 config, measured ~147us).
// ---------------------------------------------------------------------------
struct EdgeVals {
    float4 a;
    float ad0, ad1, ad2, ad3;
    long  qoff;
};

__device__ __forceinline__ void edge_compute(
    int e, int m, int q, bool upper,
    const float* __restrict__ atom,
    const int* __restrict__ src, const int* __restrict__ dst,
    EdgeVals& V)
{
    const int4 P = g_pack[e];
    const int s  = src[e];
    const int dn = dst[e];
    const int icr = P.x & 0xffff;
    const int icp = P.x >> 16;
    const int ir  = P.y & 0xffff;
    const int ip  = P.y >> 16;
    const float fr  = __int_as_float(P.z);
    const float fp_ = __int_as_float(P.w);

    float4 ctr = *reinterpret_cast<const float4*>(&g_ct[icr * 32 + 4 * q]);
    float4 ctp = *reinterpret_cast<const float4*>(&g_ct[icp * 32 + 4 * q]);
    float4 vr = g_tabv[ir * 8 + q];
    float4 dr = g_tabd[ir * 8 + q];
    float4 vp = g_tabv[ip * 8 + q];
    float4 dp = g_tabd[ip * 8 + q];

    V.a = *reinterpret_cast<const float4*>(&atom[(size_t)s * CD + 4 * m]);

    float re0 = ctr.x + fmaf(fr, dr.x, vr.x);
    float re1 = ctr.y + fmaf(fr, dr.y, vr.y);
    float re2 = ctr.z + fmaf(fr, dr.z, vr.z);
    float re3 = ctr.w + fmaf(fr, dr.w, vr.w);

    float pe0 = ctp.x + fmaf(fp_, dp.x, vp.x);
    float pe1 = ctp.y + fmaf(fp_, dp.y, vp.y);
    float pe2 = ctp.z + fmaf(fp_, dp.z, vp.z);
    float pe3 = ctp.w + fmaf(fp_, dp.w, vp.w);

    V.ad0 = upper ? (pe0 - re0) : re0;
    V.ad1 = upper ? (pe1 - re1) : re1;
    V.ad2 = upper ? (pe2 - re2) : re2;
    V.ad3 = upper ? (pe3 - re3) : re3;
    V.qoff = (long)dn * CD + 4 * m;
}

__device__ __forceinline__ void edge_commit(float* agg, const EdgeVals& V) {
    float v0 = V.a.x + V.ad0;
    float v1 = V.a.y + V.ad1;
    float v2 = V.a.z + V.ad2;
    float v3 = V.a.w + V.ad3;
    float* p = agg + V.qoff;
    asm volatile("red.global.add.v4.f32 [%0], {%1,%2,%3,%4};"
                 :: "l"(p), "f"(v0), "f"(v1), "f"(v2), "f"(v3));
}

__global__ __launch_bounds__(256, 4) void edge_kernel(
    const float* __restrict__ atom,
    const int*   __restrict__ src, const int* __restrict__ dst,
    float* __restrict__ agg)
{
    const int l = threadIdx.x & 31;
    const int g = l >> 4;
    const int m = l & 15;
    const int q = m & 7;
    const bool upper = (m >= 8);
    const int warp = (blockIdx.x * blockDim.x + threadIdx.x) >> 5;
    const int nwarps = (gridDim.x * blockDim.x) >> 5;
    const int stride = nwarps * 2;

    for (int e = warp * 2 + g; e < N_EDGES; e += 2 * stride) {
        int e1 = e + stride;
        EdgeVals V0, V1;
        edge_compute(e, m, q, upper, atom, src, dst, V0);
        bool has1 = (e1 < N_EDGES);
        if (has1) edge_compute(e1, m, q, upper, atom, src, dst, V1);
        edge_commit(agg, V0);
        if (has1) edge_commit(agg, V1);
    }
}

// ---------------------------------------------------------------------------
// Kernel 3: PERSISTENT node MLP on FP16 tensor cores (mma.sync m16n8k16,
// f32 accumulate). Strip-pair per warp (B fragments shared across 2 strips).
// Weights pre-swizzled into fragment order: one LDS.64 per (tile, kstep).
// A and H live in smem as half2. 148 blocks x 256 thr, 1 block/SM.
// ---------------------------------------------------------------------------
#define SA2_STRIDE 36            // half2 words per A row (32 + 4 pad)
#define SH2_STRIDE 68            // half2 words per H row (64 + 4 pad)
#define NSTRIPS (N_NODES / 16)   // 31250
#define NPAIRS  (NSTRIPS / 2)    // 15625

__device__ __forceinline__ void mma_f16(float c[4], const unsigned a[4],
                                        unsigned b0, unsigned b1) {
    asm("mma.sync.aligned.m16n8k16.row.col.f32.f16.f16.f32 "
        "{%0,%1,%2,%3}, {%4,%5,%6,%7}, {%8,%9}, {%0,%1,%2,%3};"
        : "+f"(c[0]), "+f"(c[1]), "+f"(c[2]), "+f"(c[3])
        : "r"(a[0]), "r"(a[1]), "r"(a[2]), "r"(a[3]), "r"(b0), "r"(b1));
}

__device__ __forceinline__ unsigned h2bits(float lo, float hi) {
    __half2 h = __floats2half2_rn(lo, hi);
    return *reinterpret_cast<unsigned*>(&h);
}

__global__ __launch_bounds__(256) void mlp_kernel(
    float* __restrict__ inout,
    const float* __restrict__ W1, const float* __restrict__ b1,
    const float* __restrict__ W2, const float* __restrict__ b2)
{
    extern __shared__ unsigned smu[];
    unsigned* sW1f = smu;                       // 4096 words: W1 fragment pairs
    unsigned* sW2f = sW1f + 4096;               // 4096 words: W2 fragment pairs
    float*    sb1  = (float*)(sW2f + 4096);     // [128]
    float*    sb2  = sb1 + HID;                 // [64]
    unsigned* sA   = (unsigned*)(sb2 + CD);     // 8 x [16][36] half2 words
    unsigned* sH   = sA + 8 * 16 * SA2_STRIDE;  // 8 x 2 x [16][68] half2 words

    const int tid  = threadIdx.x;
    const int w    = tid >> 5;
    const int lane = tid & 31;
    const int gid  = lane >> 2;
    const int tig  = lane & 3;

    // ---- stage weights ONCE per SM, pre-swizzled to fragment order ----
    // word idx: r = idx&1, lane_ = (idx>>1)&31, jk = idx>>6
    for (int idx = tid; idx < 4096; idx += 256) {
        int r = idx & 1;
        int ln = (idx >> 1) & 31;
        int jk = idx >> 6;                 // [0,64)
        int kk = jk & 3, j = jk >> 2;      // W1: 16 ntiles x 4 ksteps
        int g_ = ln >> 2, t_ = ln & 3;
        int n = j * 8 + g_;
        int k0 = kk * 16 + 2 * t_ + r * 8;
        sW1f[idx] = h2bits(W1[k0 * HID + n], W1[(k0 + 1) * HID + n]);
    }
    for (int idx = tid; idx < 4096; idx += 256) {
        int r = idx & 1;
        int ln = (idx >> 1) & 31;
        int jk = idx >> 6;                 // [0,64)
        int kk = jk & 7, j = jk >> 3;      // W2: 8 ntiles x 8 ksteps
        int g_ = ln >> 2, t_ = ln & 3;
        int n = j * 8 + g_;
        int k0 = kk * 16 + 2 * t_ + r * 8;
        sW2f[idx] = h2bits(W2[k0 * CD + n], W2[(k0 + 1) * CD + n]);
    }
    if (tid < HID) sb1[tid] = b1[tid];
    if (tid < CD)  sb2[tid] = b2[tid];
    __syncthreads();

    unsigned* sAw  = sA + w * 16 * SA2_STRIDE;
    unsigned* sH0w = sH + (2 * w) * 16 * SH2_STRIDE;
    unsigned* sH1w = sH0w + 16 * SH2_STRIDE;

    const int gwarp   = blockIdx.x * 8 + w;
    const int wstride = gridDim.x * 8;
    const int r0 = lane >> 4;
    const int c4 = lane & 15;

    long pair = gwarp;
    float4 pf0[8], pf1[8];
    if (pair < NPAIRS) {
        const float* b0p = inout + (2 * pair) * 16 * CD;
        const float* b1p = inout + (2 * pair + 1) * 16 * CD;
#pragma unroll
        for (int it = 0; it < 8; it++) {
            pf0[it] = *reinterpret_cast<const float4*>(b0p + (it * 2 + r0) * CD + c4 * 4);
            pf1[it] = *reinterpret_cast<const float4*>(b1p + (it * 2 + r0) * CD + c4 * 4);
        }
    }

    while (pair < NPAIRS) {
        const long s0 = 2 * pair;
        const long nextPair = pair + wstride;

        // ---- strip0: commit A (as half2), extract fragments ----
        __syncwarp();
#pragma unroll
        for (int it = 0; it < 8; it++) {
            uint2 pk;
            pk.x = h2bits(pf0[it].x, pf0[it].y);
            pk.y = h2bits(pf0[it].z, pf0[it].w);
            *reinterpret_cast<uint2*>(&sAw[(it * 2 + r0) * SA2_STRIDE + 2 * c4]) = pk;
        }
        __syncwarp();
        unsigned afr0[4][4];
#pragma unroll
        for (int kk = 0; kk < 4; kk++) {
            int kc = kk * 8;
            afr0[kk][0] = sAw[gid * SA2_STRIDE + kc + tig];
            afr0[kk][1] = sAw[(gid + 8) * SA2_STRIDE + kc + tig];
            afr0[kk][2] = sAw[gid * SA2_STRIDE + kc + tig + 4];
            afr0[kk][3] = sAw[(gid + 8) * SA2_STRIDE + kc + tig + 4];
        }
        __syncwarp();
        // ---- strip1 ----
#pragma unroll
        for (int it = 0; it < 8; it++) {
            uint2 pk;
            pk.x = h2bits(pf1[it].x, pf1[it].y);
            pk.y = h2bits(pf1[it].z, pf1[it].w);
            *reinterpret_cast<uint2*>(&sAw[(it * 2 + r0) * SA2_STRIDE + 2 * c4]) = pk;
        }
        __syncwarp();
        unsigned afr1[4][4];
#pragma unroll
        for (int kk = 0; kk < 4; kk++) {
            int kc = kk * 8;
            afr1[kk][0] = sAw[gid * SA2_STRIDE + kc + tig];
            afr1[kk][1] = sAw[(gid + 8) * SA2_STRIDE + kc + tig];
            afr1[kk][2] = sAw[gid * SA2_STRIDE + kc + tig + 4];
            afr1[kk][3] = sAw[(gid + 8) * SA2_STRIDE + kc + tig + 4];
        }

        // ---- prefetch next pair under compute ----
        if (nextPair < NPAIRS) {
            const float* b0p = inout + (2 * nextPair) * 16 * CD;
            const float* b1p = inout + (2 * nextPair + 1) * 16 * CD;
#pragma unroll
            for (int it = 0; it < 8; it++) {
                pf0[it] = *reinterpret_cast<const float4*>(b0p + (it * 2 + r0) * CD + c4 * 4);
                pf1[it] = *reinterpret_cast<const float4*>(b1p + (it * 2 + r0) * CD + c4 * 4);
            }
        }

        // ---- stage 1: H = relu(A @ W1 + b1), B shared across strips ----
#pragma unroll
        for (int j = 0; j < 16; j++) {
            float cA[4] = {0.f, 0.f, 0.f, 0.f};
            float cB[4] = {0.f, 0.f, 0.f, 0.f};
#pragma unroll
            for (int kk = 0; kk < 4; kk++) {
                uint2 b = *reinterpret_cast<const uint2*>(
                    &sW1f[((j * 4 + kk) * 32 + lane) * 2]);
                mma_f16(cA, afr0[kk], b.x, b.y);
                mma_f16(cB, afr1[kk], b.x, b.y);
            }
            const int colg = j * 8 + 2 * tig;
            const int cp   = j * 4 + tig;
            const float bi0 = sb1[colg], bi1 = sb1[colg + 1];
            sH0w[gid * SH2_STRIDE + cp] =
                h2bits(fmaxf(cA[0] + bi0, 0.f), fmaxf(cA[1] + bi1, 0.f));
            sH0w[(gid + 8) * SH2_STRIDE + cp] =
                h2bits(fmaxf(cA[2] + bi0, 0.f), fmaxf(cA[3] + bi1, 0.f));
            sH1w[gid * SH2_STRIDE + cp] =
                h2bits(fmaxf(cB[0] + bi0, 0.f), fmaxf(cB[1] + bi1, 0.f));
            sH1w[(gid + 8) * SH2_STRIDE + cp] =
                h2bits(fmaxf(cB[2] + bi0, 0.f), fmaxf(cB[3] + bi1, 0.f));
        }
        __syncwarp();

        // ---- load H fragments (8 ksteps of K=16) ----
        unsigned ah0[8][4], ah1[8][4];
#pragma unroll
        for (int kk = 0; kk < 8; kk++) {
            int kc = kk * 8;
            ah0[kk][0] = sH0w[gid * SH2_STRIDE + kc + tig];
            ah0[kk][1] = sH0w[(gid + 8) * SH2_STRIDE + kc + tig];
            ah0[kk][2] = sH0w[gid * SH2_STRIDE + kc + tig + 4];
            ah0[kk][3] = sH0w[(gid + 8) * SH2_STRIDE + kc + tig + 4];
            ah1[kk][0] = sH1w[gid * SH2_STRIDE + kc + tig];
            ah1[kk][1] = sH1w[(gid + 8) * SH2_STRIDE + kc + tig];
            ah1[kk][2] = sH1w[gid * SH2_STRIDE + kc + tig + 4];
            ah1[kk][3] = sH1w[(gid + 8) * SH2_STRIDE + kc + tig + 4];
        }

        // ---- stage 2: O = relu(H @ W2 + b2), B shared; store to gmem ----
        float* o00 = inout + (s0 * 16 + gid) * CD;
        float* o01 = inout + (s0 * 16 + gid + 8) * CD;
        float* o10 = inout + ((s0 + 1) * 16 + gid) * CD;
        float* o11 = inout + ((s0 + 1) * 16 + gid + 8) * CD;
#pragma unroll
        for (int j = 0; j < 8; j++) {
            float cA[4] = {0.f, 0.f, 0.f, 0.f};
            float cB[4] = {0.f, 0.f, 0.f, 0.f};
#pragma unroll
            for (int kk = 0; kk < 8; kk++) {
                uint2 b = *reinterpret_cast<const uint2*>(
                    &sW2f[((j * 8 + kk) * 32 + lane) * 2]);
                mma_f16(cA, ah0[kk], b.x, b.y);
                mma_f16(cB, ah1[kk], b.x, b.y);
            }
            const int col = j * 8 + 2 * tig;
            const float bi0 = sb2[col], bi1 = sb2[col + 1];
            *reinterpret_cast<float2*>(o00 + col) =
                make_float2(fmaxf(cA[0] + bi0, 0.f), fmaxf(cA[1] + bi1, 0.f));
            *reinterpret_cast<float2*>(o01 + col) =
                make_float2(fmaxf(cA[2] + bi0, 0.f), fmaxf(cA[3] + bi1, 0.f));
            *reinterpret_cast<float2*>(o10 + col) =
                make_float2(fmaxf(cB[0] + bi0, 0.f), fmaxf(cB[1] + bi1, 0.f));
            *reinterpret_cast<float2*>(o11 + col) =
                make_float2(fmaxf(cB[2] + bi0, 0.f), fmaxf(cB[3] + bi1, 0.f));
        }

        pair = nextPair;
    }
}

// ---------------------------------------------------------------------------
// Launch
// Inputs (metadata order):
//  0 atom_repr [N,64] f32     1 src [E] i32      2 dst [E] i32
//  3 r_dir     4 r_type       5 r_ring           6 p_dir
//  7 p_type    8 p_ring       9 r_len f32       10 p_len f32
// 11 emb_dir [8,32]          12 emb_type [16,32] 13 emb_ring [4,32]
// 14 rbf_W [20,32]           15 rbf_b [32]
// 16 W1 [64,128]             17 b1 [128]
// 18 W2 [128,64]             19 b2 [64]
// Output: [N,64] f32
// ---------------------------------------------------------------------------
extern "C" void kernel_launch(void* const* d_in, const int* in_sizes, int n_in,
                              void* d_out, int out_size) {
    const float* atom     = (const float*)d_in[0];
    const int*   src      = (const int*)d_in[1];
    const int*   dst      = (const int*)d_in[2];
    const int*   rdir     = (const int*)d_in[3];
    const int*   rtype    = (const int*)d_in[4];
    const int*   rring    = (const int*)d_in[5];
    const int*   pdir     = (const int*)d_in[6];
    const int*   ptype    = (const int*)d_in[7];
    const int*   pring    = (const int*)d_in[8];
    const float* rlen     = (const float*)d_in[9];
    const float* plen     = (const float*)d_in[10];
    const float* emb_dir  = (const float*)d_in[11];
    const float* emb_type = (const float*)d_in[12];
    const float* emb_ring = (const float*)d_in[13];
    const float* rbf_W    = (const float*)d_in[14];
    const float* rbf_b    = (const float*)d_in[15];
    const float* W1       = (const float*)d_in[16];
    const float* b1       = (const float*)d_in[17];
    const float* W2       = (const float*)d_in[18];
    const float* b2       = (const float*)d_in[19];
    float* out = (float*)d_out;

    // 0) fused prep: zero agg + pack metadata + ct/tab tables
    prep_kernel<<<2048, 256>>>((float4*)out,
                               rdir, rtype, rring, pdir, ptype, pring,
                               rlen, plen, emb_dir, emb_type, emb_ring,
                               rbf_W, rbf_b);

    // 1) edge scatter
    edge_kernel<<<2368, 256>>>(atom, src, dst, out);

    // 2) persistent strip-pair FP16 tensor-core MLP
    size_t smem = (size_t)(4096 + 4096 + HID + CD
                           + 8 * 16 * SA2_STRIDE
                           + 8 * 2 * 16 * SH2_STRIDE) * 4;
    cudaFuncSetAttribute(mlp_kernel, cudaFuncAttributeMaxDynamicSharedMemorySize,
                         (int)smem);
    mlp_kernel<<<148, 256, smem>>>(out, W1, b1, W2, b2);
}

// round 14
// speedup vs baseline: 6.6112x; 1.0106x over previous
#include <cuda_runtime.h>
#include <cuda_fp16.h>
#include <cstdint>

// Problem constants (fixed by the reference)
#define N_NODES 500000
#define N_EDGES 1000000
#define D       32
#define CD      64
#define HID     128
#define NCEN    20
#define RBF_GAMMA 10.0f

#define TAB_INTERVALS 256         // PWL intervals over len in [0,2) — L1-resident
#define TAB_SCALE     128.0f      // intervals per unit length

#define FULLMASK 0xffffffffu

// ---- device-global precomputed tables (allowed scratch) --------------------
__device__ float  g_ct[512 * 32];               // combined cat embedding (64KB)
__device__ float4 g_tabv[TAB_INTERVALS * 8];    // PWL values (32KB)
__device__ float4 g_tabd[TAB_INTERVALS * 8];    // PWL slopes (32KB)
__device__ int4   g_pack[N_EDGES];              // {icr|icp<<16, ir|ip<<16, fr, fp}

// ---------------------------------------------------------------------------
// Fused prep kernel: zero agg + pack edge metadata + build ct/tab tables.
// ---------------------------------------------------------------------------
__global__ void prep_kernel(
    float4* __restrict__ out4,
    const int* __restrict__ rdir, const int* __restrict__ rtype, const int* __restrict__ rring,
    const int* __restrict__ pdir, const int* __restrict__ ptype, const int* __restrict__ pring,
    const float* __restrict__ rlen, const float* __restrict__ plen,
    const float* __restrict__ emb_dir, const float* __restrict__ emb_type,
    const float* __restrict__ emb_ring,
    const float* __restrict__ rbf_W, const float* __restrict__ rbf_b)
{
    const int ZN = N_NODES * CD / 4;
    const int PN = ZN + N_EDGES;
    const int CN = PN + 512 * 32;
    const int TN = CN + TAB_INTERVALS * 8;
    const float4 z4 = make_float4(0.f, 0.f, 0.f, 0.f);

    for (int i = blockIdx.x * blockDim.x + threadIdx.x; i < TN;
         i += gridDim.x * blockDim.x) {
        if (i < ZN) {
            out4[i] = z4;
        } else if (i < PN) {
            int e = i - ZN;
            int icr = (rdir[e] * 16 + rtype[e]) * 4 + rring[e];
            int icp = (pdir[e] * 16 + ptype[e]) * 4 + pring[e];
            float xr = rlen[e] * TAB_SCALE;
            int   ir = min((int)xr, TAB_INTERVALS - 1);
            float fr = xr - (float)ir;
            float xp = plen[e] * TAB_SCALE;
            int   ip = min((int)xp, TAB_INTERVALS - 1);
            float fp_ = xp - (float)ip;
            int4 P;
            P.x = icr | (icp << 16);
            P.y = ir | (ip << 16);
            P.z = __float_as_int(fr);
            P.w = __float_as_int(fp_);
            g_pack[e] = P;
        } else if (i < CN) {
            int idx = i - PN;
            int l = idx & 31;
            int comb = idx >> 5;
            int ring = comb & 3;
            int type = (comb >> 2) & 15;
            int dir  = comb >> 6;
            g_ct[idx] = emb_dir[dir * 32 + l] + emb_type[type * 32 + l]
                      + emb_ring[ring * 32 + l];
        } else {
            int idx = i - CN;
            int q = idx & 7;
            int iv = idx >> 3;
            float x0 = (float)iv / TAB_SCALE;
            float x1 = (float)(iv + 1) / TAB_SCALE;
            float v0[4], v1[4];
#pragma unroll
            for (int c = 0; c < 4; c++) { v0[c] = rbf_b[4 * q + c]; v1[c] = v0[c]; }
#pragma unroll
            for (int k = 0; k < NCEN; k++) {
                float ctr = 0.1f * (float)k;
                float d0 = x0 - ctr, d1 = x1 - ctr;
                float e0 = expf(-RBF_GAMMA * d0 * d0);
                float e1 = expf(-RBF_GAMMA * d1 * d1);
#pragma unroll
                for (int c = 0; c < 4; c++) {
                    float wv = rbf_W[k * 32 + 4 * q + c];
                    v0[c] = fmaf(e0, wv, v0[c]);
                    v1[c] = fmaf(e1, wv, v1[c]);
                }
            }
            g_tabv[idx] = make_float4(v0[0], v0[1], v0[2], v0[3]);
            g_tabd[idx] = make_float4(v1[0] - v0[0], v1[1] - v0[1],
                                      v1[2] - v0[2], v1[3] - v0[3]);
        }
    }
}

// ---------------------------------------------------------------------------
// Kernel 2: edge message + scatter. TWO edges per warp, lane m owns channels
// 4m..4m+3. Tables (ct 64KB + tab 64KB) are fully L1-resident now.
// ---------------------------------------------------------------------------
struct EdgeVals {
    float4 a;
    float ad0, ad1, ad2, ad3;
    long  qoff;
};

__device__ __forceinline__ void edge_compute(
    int e, int m, int q, bool upper,
    const float* __restrict__ atom,
    const int* __restrict__ src, const int* __restrict__ dst,
    EdgeVals& V)
{
    const int4 P = g_pack[e];
    const int s  = src[e];
    const int dn = dst[e];
    const int icr = P.x & 0xffff;
    const int icp = P.x >> 16;
    const int ir  = P.y & 0xffff;
    const int ip  = P.y >> 16;
    const float fr  = __int_as_float(P.z);
    const float fp_ = __int_as_float(P.w);

    float4 ctr = *reinterpret_cast<const float4*>(&g_ct[icr * 32 + 4 * q]);
    float4 ctp = *reinterpret_cast<const float4*>(&g_ct[icp * 32 + 4 * q]);
    float4 vr = g_tabv[ir * 8 + q];
    float4 dr = g_tabd[ir * 8 + q];
    float4 vp = g_tabv[ip * 8 + q];
    float4 dp = g_tabd[ip * 8 + q];

    V.a = *reinterpret_cast<const float4*>(&atom[(size_t)s * CD + 4 * m]);

    float re0 = ctr.x + fmaf(fr, dr.x, vr.x);
    float re1 = ctr.y + fmaf(fr, dr.y, vr.y);
    float re2 = ctr.z + fmaf(fr, dr.z, vr.z);
    float re3 = ctr.w + fmaf(fr, dr.w, vr.w);

    float pe0 = ctp.x + fmaf(fp_, dp.x, vp.x);
    float pe1 = ctp.y + fmaf(fp_, dp.y, vp.y);
    float pe2 = ctp.z + fmaf(fp_, dp.z, vp.z);
    float pe3 = ctp.w + fmaf(fp_, dp.w, vp.w);

    V.ad0 = upper ? (pe0 - re0) : re0;
    V.ad1 = upper ? (pe1 - re1) : re1;
    V.ad2 = upper ? (pe2 - re2) : re2;
    V.ad3 = upper ? (pe3 - re3) : re3;
    V.qoff = (long)dn * CD + 4 * m;
}

__device__ __forceinline__ void edge_commit(float* agg, const EdgeVals& V) {
    float v0 = V.a.x + V.ad0;
    float v1 = V.a.y + V.ad1;
    float v2 = V.a.z + V.ad2;
    float v3 = V.a.w + V.ad3;
    float* p = agg + V.qoff;
    asm volatile("red.global.add.v4.f32 [%0], {%1,%2,%3,%4};"
                 :: "l"(p), "f"(v0), "f"(v1), "f"(v2), "f"(v3));
}

__global__ __launch_bounds__(256, 4) void edge_kernel(
    const float* __restrict__ atom,
    const int*   __restrict__ src, const int* __restrict__ dst,
    float* __restrict__ agg)
{
    const int l = threadIdx.x & 31;
    const int g = l >> 4;
    const int m = l & 15;
    const int q = m & 7;
    const bool upper = (m >= 8);
    const int warp = (blockIdx.x * blockDim.x + threadIdx.x) >> 5;
    const int nwarps = (gridDim.x * blockDim.x) >> 5;
    const int stride = nwarps * 2;

    for (int e = warp * 2 + g; e < N_EDGES; e += 2 * stride) {
        int e1 = e + stride;
        EdgeVals V0, V1;
        edge_compute(e, m, q, upper, atom, src, dst, V0);
        bool has1 = (e1 < N_EDGES);
        if (has1) edge_compute(e1, m, q, upper, atom, src, dst, V1);
        edge_commit(agg, V0);
        if (has1) edge_commit(agg, V1);
    }
}

// ---------------------------------------------------------------------------
// Kernel 3: PERSISTENT node MLP on FP16 tensor cores (R13 config, ~55us).
// ---------------------------------------------------------------------------
#define SA2_STRIDE 36            // half2 words per A row (32 + 4 pad)
#define SH2_STRIDE 68            // half2 words per H row (64 + 4 pad)
#define NSTRIPS (N_NODES / 16)   // 31250
#define NPAIRS  (NSTRIPS / 2)    // 15625

__device__ __forceinline__ void mma_f16(float c[4], const unsigned a[4],
                                        unsigned b0, unsigned b1) {
    asm("mma.sync.aligned.m16n8k16.row.col.f32.f16.f16.f32 "
        "{%0,%1,%2,%3}, {%4,%5,%6,%7}, {%8,%9}, {%0,%1,%2,%3};"
        : "+f"(c[0]), "+f"(c[1]), "+f"(c[2]), "+f"(c[3])
        : "r"(a[0]), "r"(a[1]), "r"(a[2]), "r"(a[3]), "r"(b0), "r"(b1));
}

__device__ __forceinline__ unsigned h2bits(float lo, float hi) {
    __half2 h = __floats2half2_rn(lo, hi);
    return *reinterpret_cast<unsigned*>(&h);
}

__global__ __launch_bounds__(256) void mlp_kernel(
    float* __restrict__ inout,
    const float* __restrict__ W1, const float* __restrict__ b1,
    const float* __restrict__ W2, const float* __restrict__ b2)
{
    extern __shared__ unsigned smu[];
    unsigned* sW1f = smu;                       // 4096 words: W1 fragment pairs
    unsigned* sW2f = sW1f + 4096;               // 4096 words: W2 fragment pairs
    float*    sb1  = (float*)(sW2f + 4096);     // [128]
    float*    sb2  = sb1 + HID;                 // [64]
    unsigned* sA   = (unsigned*)(sb2 + CD);     // 8 x [16][36] half2 words
    unsigned* sH   = sA + 8 * 16 * SA2_STRIDE;  // 8 x 2 x [16][68] half2 words

    const int tid  = threadIdx.x;
    const int w    = tid >> 5;
    const int lane = tid & 31;
    const int gid  = lane >> 2;
    const int tig  = lane & 3;

    for (int idx = tid; idx < 4096; idx += 256) {
        int r = idx & 1;
        int ln = (idx >> 1) & 31;
        int jk = idx >> 6;
        int kk = jk & 3, j = jk >> 2;
        int g_ = ln >> 2, t_ = ln & 3;
        int n = j * 8 + g_;
        int k0 = kk * 16 + 2 * t_ + r * 8;
        sW1f[idx] = h2bits(W1[k0 * HID + n], W1[(k0 + 1) * HID + n]);
    }
    for (int idx = tid; idx < 4096; idx += 256) {
        int r = idx & 1;
        int ln = (idx >> 1) & 31;
        int jk = idx >> 6;
        int kk = jk & 7, j = jk >> 3;
        int g_ = ln >> 2, t_ = ln & 3;
        int n = j * 8 + g_;
        int k0 = kk * 16 + 2 * t_ + r * 8;
        sW2f[idx] = h2bits(W2[k0 * CD + n], W2[(k0 + 1) * CD + n]);
    }
    if (tid < HID) sb1[tid] = b1[tid];
    if (tid < CD)  sb2[tid] = b2[tid];
    __syncthreads();

    unsigned* sAw  = sA + w * 16 * SA2_STRIDE;
    unsigned* sH0w = sH + (2 * w) * 16 * SH2_STRIDE;
    unsigned* sH1w = sH0w + 16 * SH2_STRIDE;

    const int gwarp   = blockIdx.x * 8 + w;
    const int wstride = gridDim.x * 8;
    const int r0 = lane >> 4;
    const int c4 = lane & 15;

    long pair = gwarp;
    float4 pf0[8], pf1[8];
    if (pair < NPAIRS) {
        const float* b0p = inout + (2 * pair) * 16 * CD;
        const float* b1p = inout + (2 * pair + 1) * 16 * CD;
#pragma unroll
        for (int it = 0; it < 8; it++) {
            pf0[it] = *reinterpret_cast<const float4*>(b0p + (it * 2 + r0) * CD + c4 * 4);
            pf1[it] = *reinterpret_cast<const float4*>(b1p + (it * 2 + r0) * CD + c4 * 4);
        }
    }

    while (pair < NPAIRS) {
        const long s0 = 2 * pair;
        const long nextPair = pair + wstride;

        __syncwarp();
#pragma unroll
        for (int it = 0; it < 8; it++) {
            uint2 pk;
            pk.x = h2bits(pf0[it].x, pf0[it].y);
            pk.y = h2bits(pf0[it].z, pf0[it].w);
            *reinterpret_cast<uint2*>(&sAw[(it * 2 + r0) * SA2_STRIDE + 2 * c4]) = pk;
        }
        __syncwarp();
        unsigned afr0[4][4];
#pragma unroll
        for (int kk = 0; kk < 4; kk++) {
            int kc = kk * 8;
            afr0[kk][0] = sAw[gid * SA2_STRIDE + kc + tig];
            afr0[kk][1] = sAw[(gid + 8) * SA2_STRIDE + kc + tig];
            afr0[kk][2] = sAw[gid * SA2_STRIDE + kc + tig + 4];
            afr0[kk][3] = sAw[(gid + 8) * SA2_STRIDE + kc + tig + 4];
        }
        __syncwarp();
#pragma unroll
        for (int it = 0; it < 8; it++) {
            uint2 pk;
            pk.x = h2bits(pf1[it].x, pf1[it].y);
            pk.y = h2bits(pf1[it].z, pf1[it].w);
            *reinterpret_cast<uint2*>(&sAw[(it * 2 + r0) * SA2_STRIDE + 2 * c4]) = pk;
        }
        __syncwarp();
        unsigned afr1[4][4];
#pragma unroll
        for (int kk = 0; kk < 4; kk++) {
            int kc = kk * 8;
            afr1[kk][0] = sAw[gid * SA2_STRIDE + kc + tig];
            afr1[kk][1] = sAw[(gid + 8) * SA2_STRIDE + kc + tig];
            afr1[kk][2] = sAw[gid * SA2_STRIDE + kc + tig + 4];
            afr1[kk][3] = sAw[(gid + 8) * SA2_STRIDE + kc + tig + 4];
        }

        if (nextPair < NPAIRS) {
            const float* b0p = inout + (2 * nextPair) * 16 * CD;
            const float* b1p = inout + (2 * nextPair + 1) * 16 * CD;
#pragma unroll
            for (int it = 0; it < 8; it++) {
                pf0[it] = *reinterpret_cast<const float4*>(b0p + (it * 2 + r0) * CD + c4 * 4);
                pf1[it] = *reinterpret_cast<const float4*>(b1p + (it * 2 + r0) * CD + c4 * 4);
            }
        }

#pragma unroll
        for (int j = 0; j < 16; j++) {
            float cA[4] = {0.f, 0.f, 0.f, 0.f};
            float cB[4] = {0.f, 0.f, 0.f, 0.f};
#pragma unroll
            for (int kk = 0; kk < 4; kk++) {
                uint2 b = *reinterpret_cast<const uint2*>(
                    &sW1f[((j * 4 + kk) * 32 + lane) * 2]);
                mma_f16(cA, afr0[kk], b.x, b.y);
                mma_f16(cB, afr1[kk], b.x, b.y);
            }
            const int colg = j * 8 + 2 * tig;
            const int cp   = j * 4 + tig;
            const float bi0 = sb1[colg], bi1 = sb1[colg + 1];
            sH0w[gid * SH2_STRIDE + cp] =
                h2bits(fmaxf(cA[0] + bi0, 0.f), fmaxf(cA[1] + bi1, 0.f));
            sH0w[(gid + 8) * SH2_STRIDE + cp] =
                h2bits(fmaxf(cA[2] + bi0, 0.f), fmaxf(cA[3] + bi1, 0.f));
            sH1w[gid * SH2_STRIDE + cp] =
                h2bits(fmaxf(cB[0] + bi0, 0.f), fmaxf(cB[1] + bi1, 0.f));
            sH1w[(gid + 8) * SH2_STRIDE + cp] =
                h2bits(fmaxf(cB[2] + bi0, 0.f), fmaxf(cB[3] + bi1, 0.f));
        }
        __syncwarp();

        unsigned ah0[8][4], ah1[8][4];
#pragma unroll
        for (int kk = 0; kk < 8; kk++) {
            int kc = kk * 8;
            ah0[kk][0] = sH0w[gid * SH2_STRIDE + kc + tig];
            ah0[kk][1] = sH0w[(gid + 8) * SH2_STRIDE + kc + tig];
            ah0[kk][2] = sH0w[gid * SH2_STRIDE + kc + tig + 4];
            ah0[kk][3] = sH0w[(gid + 8) * SH2_STRIDE + kc + tig + 4];
            ah1[kk][0] = sH1w[gid * SH2_STRIDE + kc + tig];
            ah1[kk][1] = sH1w[(gid + 8) * SH2_STRIDE + kc + tig];
            ah1[kk][2] = sH1w[gid * SH2_STRIDE + kc + tig + 4];
            ah1[kk][3] = sH1w[(gid + 8) * SH2_STRIDE + kc + tig + 4];
        }

        float* o00 = inout + (s0 * 16 + gid) * CD;
        float* o01 = inout + (s0 * 16 + gid + 8) * CD;
        float* o10 = inout + ((s0 + 1) * 16 + gid) * CD;
        float* o11 = inout + ((s0 + 1) * 16 + gid + 8) * CD;
#pragma unroll
        for (int j = 0; j < 8; j++) {
            float cA[4] = {0.f, 0.f, 0.f, 0.f};
            float cB[4] = {0.f, 0.f, 0.f, 0.f};
#pragma unroll
            for (int kk = 0; kk < 8; kk++) {
                uint2 b = *reinterpret_cast<const uint2*>(
                    &sW2f[((j * 8 + kk) * 32 + lane) * 2]);
                mma_f16(cA, ah0[kk], b.x, b.y);
                mma_f16(cB, ah1[kk], b.x, b.y);
            }
            const int col = j * 8 + 2 * tig;
            const float bi0 = sb2[col], bi1 = sb2[col + 1];
            *reinterpret_cast<float2*>(o00 + col) =
                make_float2(fmaxf(cA[0] + bi0, 0.f), fmaxf(cA[1] + bi1, 0.f));
            *reinterpret_cast<float2*>(o01 + col) =
                make_float2(fmaxf(cA[2] + bi0, 0.f), fmaxf(cA[3] + bi1, 0.f));
            *reinterpret_cast<float2*>(o10 + col) =
                make_float2(fmaxf(cB[0] + bi0, 0.f), fmaxf(cB[1] + bi1, 0.f));
            *reinterpret_cast<float2*>(o11 + col) =
                make_float2(fmaxf(cB[2] + bi0, 0.f), fmaxf(cB[3] + bi1, 0.f));
        }

        pair = nextPair;
    }
}

// ---------------------------------------------------------------------------
// Launch
// Inputs (metadata order):
//  0 atom_repr [N,64] f32     1 src [E] i32      2 dst [E] i32
//  3 r_dir     4 r_type       5 r_ring           6 p_dir
//  7 p_type    8 p_ring       9 r_len f32       10 p_len f32
// 11 emb_dir [8,32]          12 emb_type [16,32] 13 emb_ring [4,32]
// 14 rbf_W [20,32]           15 rbf_b [32]
// 16 W1 [64,128]             17 b1 [128]
// 18 W2 [128,64]             19 b2 [64]
// Output: [N,64] f32
// ---------------------------------------------------------------------------
extern "C" void kernel_launch(void* const* d_in, const int* in_sizes, int n_in,
                              void* d_out, int out_size) {
    const float* atom     = (const float*)d_in[0];
    const int*   src      = (const int*)d_in[1];
    const int*   dst      = (const int*)d_in[2];
    const int*   rdir     = (const int*)d_in[3];
    const int*   rtype    = (const int*)d_in[4];
    const int*   rring    = (const int*)d_in[5];
    const int*   pdir     = (const int*)d_in[6];
    const int*   ptype    = (const int*)d_in[7];
    const int*   pring    = (const int*)d_in[8];
    const float* rlen     = (const float*)d_in[9];
    const float* plen     = (const float*)d_in[10];
    const float* emb_dir  = (const float*)d_in[11];
    const float* emb_type = (const float*)d_in[12];
    const float* emb_ring = (const float*)d_in[13];
    const float* rbf_W    = (const float*)d_in[14];
    const float* rbf_b    = (const float*)d_in[15];
    const float* W1       = (const float*)d_in[16];
    const float* b1       = (const float*)d_in[17];
    const float* W2       = (const float*)d_in[18];
    const float* b2       = (const float*)d_in[19];
    float* out = (float*)d_out;

    // 0) fused prep: zero agg + pack metadata + ct/tab tables
    prep_kernel<<<2048, 256>>>((float4*)out,
                               rdir, rtype, rring, pdir, ptype, pring,
                               rlen, plen, emb_dir, emb_type, emb_ring,
                               rbf_W, rbf_b);

    // 1) edge scatter (tables L1-resident)
    edge_kernel<<<2368, 256>>>(atom, src, dst, out);

    // 2) persistent strip-pair FP16 tensor-core MLP
    size_t smem = (size_t)(4096 + 4096 + HID + CD
                           + 8 * 16 * SA2_STRIDE
                           + 8 * 2 * 16 * SH2_STRIDE) * 4;
    cudaFuncSetAttribute(mlp_kernel, cudaFuncAttributeMaxDynamicSharedMemorySize,
                         (int)smem);
    mlp_kernel<<<148, 256, smem>>>(out, W1, b1, W2, b2);
}

// round 15
// speedup vs baseline: 7.1938x; 1.0881x over previous
#include <cuda_runtime.h>
#include <cuda_fp16.h>
#include <cstdint>

// Problem constants (fixed by the reference)
#define N_NODES 500000
#define N_EDGES 1000000
#define D       32
#define CD      64
#define HID     128
#define NCEN    20
#define RBF_GAMMA 10.0f

#define TAB_INTERVALS 256         // PWL intervals over len in [0,2)
#define TAB_SCALE     128.0f      // intervals per unit length

#define FULLMASK 0xffffffffu

// ---- device-global precomputed tables / scratch (allowed) ------------------
__device__ float  g_ct[512 * 32];               // combined cat embedding (64KB)
__device__ float4 g_tabv[TAB_INTERVALS * 8];    // PWL values (32KB)
__device__ float4 g_tabd[TAB_INTERVALS * 8];    // PWL slopes (32KB)
__device__ int4   g_pack[N_EDGES];              // {icr|icp<<16, ir|ip<<16, fr, fp}
__device__ unsigned g_hagg2[N_NODES * 32];      // fp16 aggregation (half2 words, 64MB)

__device__ __forceinline__ unsigned h2bits(float lo, float hi) {
    __half2 h = __floats2half2_rn(lo, hi);
    return *reinterpret_cast<unsigned*>(&h);
}

// ---------------------------------------------------------------------------
// Fused prep kernel: zero g_hagg2 + pack edge metadata + build ct/tab tables.
// (d_out no longer needs zeroing — MLP writes every row.)
// ---------------------------------------------------------------------------
__global__ void prep_kernel(
    const int* __restrict__ rdir, const int* __restrict__ rtype, const int* __restrict__ rring,
    const int* __restrict__ pdir, const int* __restrict__ ptype, const int* __restrict__ pring,
    const float* __restrict__ rlen, const float* __restrict__ plen,
    const float* __restrict__ emb_dir, const float* __restrict__ emb_type,
    const float* __restrict__ emb_ring,
    const float* __restrict__ rbf_W, const float* __restrict__ rbf_b)
{
    const int ZN = N_NODES * 32 / 4;            // 4,000,000 uint4 zero items
    const int PN = ZN + N_EDGES;
    const int CN = PN + 512 * 32;
    const int TN = CN + TAB_INTERVALS * 8;
    uint4* hz = reinterpret_cast<uint4*>(g_hagg2);
    const uint4 z4 = make_uint4(0u, 0u, 0u, 0u);

    for (int i = blockIdx.x * blockDim.x + threadIdx.x; i < TN;
         i += gridDim.x * blockDim.x) {
        if (i < ZN) {
            hz[i] = z4;
        } else if (i < PN) {
            int e = i - ZN;
            int icr = (rdir[e] * 16 + rtype[e]) * 4 + rring[e];
            int icp = (pdir[e] * 16 + ptype[e]) * 4 + pring[e];
            float xr = rlen[e] * TAB_SCALE;
            int   ir = min((int)xr, TAB_INTERVALS - 1);
            float fr = xr - (float)ir;
            float xp = plen[e] * TAB_SCALE;
            int   ip = min((int)xp, TAB_INTERVALS - 1);
            float fp_ = xp - (float)ip;
            int4 P;
            P.x = icr | (icp << 16);
            P.y = ir | (ip << 16);
            P.z = __float_as_int(fr);
            P.w = __float_as_int(fp_);
            g_pack[e] = P;
        } else if (i < CN) {
            int idx = i - PN;
            int l = idx & 31;
            int comb = idx >> 5;
            int ring = comb & 3;
            int type = (comb >> 2) & 15;
            int dir  = comb >> 6;
            g_ct[idx] = emb_dir[dir * 32 + l] + emb_type[type * 32 + l]
                      + emb_ring[ring * 32 + l];
        } else {
            int idx = i - CN;
            int q = idx & 7;
            int iv = idx >> 3;
            float x0 = (float)iv / TAB_SCALE;
            float x1 = (float)(iv + 1) / TAB_SCALE;
            float v0[4], v1[4];
#pragma unroll
            for (int c = 0; c < 4; c++) { v0[c] = rbf_b[4 * q + c]; v1[c] = v0[c]; }
#pragma unroll
            for (int k = 0; k < NCEN; k++) {
                float ctr = 0.1f * (float)k;
                float d0 = x0 - ctr, d1 = x1 - ctr;
                float e0 = expf(-RBF_GAMMA * d0 * d0);
                float e1 = expf(-RBF_GAMMA * d1 * d1);
#pragma unroll
                for (int c = 0; c < 4; c++) {
                    float wv = rbf_W[k * 32 + 4 * q + c];
                    v0[c] = fmaf(e0, wv, v0[c]);
                    v1[c] = fmaf(e1, wv, v1[c]);
                }
            }
            g_tabv[idx] = make_float4(v0[0], v0[1], v0[2], v0[3]);
            g_tabd[idx] = make_float4(v1[0] - v0[0], v1[1] - v0[1],
                                      v1[2] - v0[2], v1[3] - v0[3]);
        }
    }
}

// ---------------------------------------------------------------------------
// Kernel 2: edge message + FP16 scatter. TWO edges per warp, lane m computes
// channels 4m..4m+3 in f32, packs to half2, then 4 shuffles repack so lanes
// m<8 issue ONE red.global.add.noftz.v4.f16x2 (128B/edge total, was 256B).
// ---------------------------------------------------------------------------
struct EdgeVals {
    float4 a;
    float ad0, ad1, ad2, ad3;
    long  qoff;                   // half2-word base = dn*32
};

__device__ __forceinline__ void edge_compute(
    int e, int m, int q, bool upper,
    const float* __restrict__ atom,
    const int* __restrict__ src, const int* __restrict__ dst,
    EdgeVals& V)
{
    const int4 P = g_pack[e];
    const int s  = src[e];
    const int dn = dst[e];
    const int icr = P.x & 0xffff;
    const int icp = P.x >> 16;
    const int ir  = P.y & 0xffff;
    const int ip  = P.y >> 16;
    const float fr  = __int_as_float(P.z);
    const float fp_ = __int_as_float(P.w);

    float4 ctr = *reinterpret_cast<const float4*>(&g_ct[icr * 32 + 4 * q]);
    float4 ctp = *reinterpret_cast<const float4*>(&g_ct[icp * 32 + 4 * q]);
    float4 vr = g_tabv[ir * 8 + q];
    float4 dr = g_tabd[ir * 8 + q];
    float4 vp = g_tabv[ip * 8 + q];
    float4 dp = g_tabd[ip * 8 + q];

    V.a = *reinterpret_cast<const float4*>(&atom[(size_t)s * CD + 4 * m]);

    float re0 = ctr.x + fmaf(fr, dr.x, vr.x);
    float re1 = ctr.y + fmaf(fr, dr.y, vr.y);
    float re2 = ctr.z + fmaf(fr, dr.z, vr.z);
    float re3 = ctr.w + fmaf(fr, dr.w, vr.w);

    float pe0 = ctp.x + fmaf(fp_, dp.x, vp.x);
    float pe1 = ctp.y + fmaf(fp_, dp.y, vp.y);
    float pe2 = ctp.z + fmaf(fp_, dp.z, vp.z);
    float pe3 = ctp.w + fmaf(fp_, dp.w, vp.w);

    V.ad0 = upper ? (pe0 - re0) : re0;
    V.ad1 = upper ? (pe1 - re1) : re1;
    V.ad2 = upper ? (pe2 - re2) : re2;
    V.ad3 = upper ? (pe3 - re3) : re3;
    V.qoff = (long)dn * 32;
}

__device__ __forceinline__ void edge_commit(const EdgeVals& V, int l, int m) {
    float v0 = V.a.x + V.ad0;
    float v1 = V.a.y + V.ad1;
    float v2 = V.a.z + V.ad2;
    float v3 = V.a.w + V.ad3;
    unsigned hlo = h2bits(v0, v1);       // channels 4m, 4m+1
    unsigned hhi = h2bits(v2, v3);       // channels 4m+2, 4m+3
    // target lane m<8 gathers channels 8m..8m+7 from group lanes 2m, 2m+1
    int sl0 = (l & 16) | ((m & 7) << 1);
    unsigned w0 = __shfl_sync(FULLMASK, hlo, sl0);
    unsigned w1 = __shfl_sync(FULLMASK, hhi, sl0);
    unsigned w2 = __shfl_sync(FULLMASK, hlo, sl0 + 1);
    unsigned w3 = __shfl_sync(FULLMASK, hhi, sl0 + 1);
    if (m < 8) {
        unsigned* p = g_hagg2 + V.qoff + 4 * m;
        asm volatile("red.global.add.noftz.v4.f16x2 [%0], {%1,%2,%3,%4};"
                     :: "l"(p), "r"(w0), "r"(w1), "r"(w2), "r"(w3));
    }
}

__global__ __launch_bounds__(256, 4) void edge_kernel(
    const float* __restrict__ atom,
    const int*   __restrict__ src, const int* __restrict__ dst)
{
    const int l = threadIdx.x & 31;
    const int g = l >> 4;
    const int m = l & 15;
    const int q = m & 7;
    const bool upper = (m >= 8);
    const int warp = (blockIdx.x * blockDim.x + threadIdx.x) >> 5;
    const int nwarps = (gridDim.x * blockDim.x) >> 5;
    const int stride = nwarps * 2;

    for (int e = warp * 2 + g; e < N_EDGES; e += 2 * stride) {
        int e1 = e + stride;
        EdgeVals V0, V1;
        edge_compute(e, m, q, upper, atom, src, dst, V0);
        bool has1 = (e1 < N_EDGES);
        if (has1) edge_compute(e1, m, q, upper, atom, src, dst, V1);
        edge_commit(V0, l, m);
        if (has1) edge_commit(V1, l, m);
    }
}

// ---------------------------------------------------------------------------
// Kernel 3: PERSISTENT FP16 tensor-core MLP. Reads A directly from g_hagg2
// (already fp16, no conversion), writes f32 to d_out. Strip-pair per warp,
// pre-swizzled weight fragments, 148 blocks x 256 thr.
// ---------------------------------------------------------------------------
#define SA2_STRIDE 36            // half2 words per A row (32 + 4 pad)
#define SH2_STRIDE 68            // half2 words per H row (64 + 4 pad)
#define NSTRIPS (N_NODES / 16)   // 31250
#define NPAIRS  (NSTRIPS / 2)    // 15625

__device__ __forceinline__ void mma_f16(float c[4], const unsigned a[4],
                                        unsigned b0, unsigned b1) {
    asm("mma.sync.aligned.m16n8k16.row.col.f32.f16.f16.f32 "
        "{%0,%1,%2,%3}, {%4,%5,%6,%7}, {%8,%9}, {%0,%1,%2,%3};"
        : "+f"(c[0]), "+f"(c[1]), "+f"(c[2]), "+f"(c[3])
        : "r"(a[0]), "r"(a[1]), "r"(a[2]), "r"(a[3]), "r"(b0), "r"(b1));
}

__global__ __launch_bounds__(256) void mlp_kernel(
    float* __restrict__ outp,
    const float* __restrict__ W1, const float* __restrict__ b1,
    const float* __restrict__ W2, const float* __restrict__ b2)
{
    extern __shared__ unsigned smu[];
    unsigned* sW1f = smu;                       // 4096 words: W1 fragment pairs
    unsigned* sW2f = sW1f + 4096;               // 4096 words: W2 fragment pairs
    float*    sb1  = (float*)(sW2f + 4096);     // [128]
    float*    sb2  = sb1 + HID;                 // [64]
    unsigned* sA   = (unsigned*)(sb2 + CD);     // 8 x [16][36] half2 words
    unsigned* sH   = sA + 8 * 16 * SA2_STRIDE;  // 8 x 2 x [16][68] half2 words

    const int tid  = threadIdx.x;
    const int w    = tid >> 5;
    const int lane = tid & 31;
    const int gid  = lane >> 2;
    const int tig  = lane & 3;

    for (int idx = tid; idx < 4096; idx += 256) {
        int r = idx & 1;
        int ln = (idx >> 1) & 31;
        int jk = idx >> 6;
        int kk = jk & 3, j = jk >> 2;
        int g_ = ln >> 2, t_ = ln & 3;
        int n = j * 8 + g_;
        int k0 = kk * 16 + 2 * t_ + r * 8;
        sW1f[idx] = h2bits(W1[k0 * HID + n], W1[(k0 + 1) * HID + n]);
    }
    for (int idx = tid; idx < 4096; idx += 256) {
        int r = idx & 1;
        int ln = (idx >> 1) & 31;
        int jk = idx >> 6;
        int kk = jk & 7, j = jk >> 3;
        int g_ = ln >> 2, t_ = ln & 3;
        int n = j * 8 + g_;
        int k0 = kk * 16 + 2 * t_ + r * 8;
        sW2f[idx] = h2bits(W2[k0 * CD + n], W2[(k0 + 1) * CD + n]);
    }
    if (tid < HID) sb1[tid] = b1[tid];
    if (tid < CD)  sb2[tid] = b2[tid];
    __syncthreads();

    unsigned* sAw  = sA + w * 16 * SA2_STRIDE;
    unsigned* sH0w = sH + (2 * w) * 16 * SH2_STRIDE;
    unsigned* sH1w = sH0w + 16 * SH2_STRIDE;

    const int gwarp   = blockIdx.x * 8 + w;
    const int wstride = gridDim.x * 8;
    const int rA = lane >> 3;            // A-load row group (0..3)
    const int cA = lane & 7;             // uint4 col within 128B row

    const uint4* hagg4 = reinterpret_cast<const uint4*>(g_hagg2);

    long pair = gwarp;
    uint4 pf0[4], pf1[4];
    if (pair < NPAIRS) {
        const uint4* b0p = hagg4 + (2 * pair) * 128;       // 16 rows x 8 uint4
        const uint4* b1p = hagg4 + (2 * pair + 1) * 128;
#pragma unroll
        for (int it = 0; it < 4; it++) {
            pf0[it] = b0p[(it * 4 + rA) * 8 + cA];
            pf1[it] = b1p[(it * 4 + rA) * 8 + cA];
        }
    }

    while (pair < NPAIRS) {
        const long s0 = 2 * pair;
        const long nextPair = pair + wstride;

        // ---- strip0: commit A (already half2), extract fragments ----
        __syncwarp();
#pragma unroll
        for (int it = 0; it < 4; it++)
            *reinterpret_cast<uint4*>(&sAw[(it * 4 + rA) * SA2_STRIDE + 4 * cA]) = pf0[it];
        __syncwarp();
        unsigned afr0[4][4];
#pragma unroll
        for (int kk = 0; kk < 4; kk++) {
            int kc = kk * 8;
            afr0[kk][0] = sAw[gid * SA2_STRIDE + kc + tig];
            afr0[kk][1] = sAw[(gid + 8) * SA2_STRIDE + kc + tig];
            afr0[kk][2] = sAw[gid * SA2_STRIDE + kc + tig + 4];
            afr0[kk][3] = sAw[(gid + 8) * SA2_STRIDE + kc + tig + 4];
        }
        __syncwarp();
        // ---- strip1 ----
#pragma unroll
        for (int it = 0; it < 4; it++)
            *reinterpret_cast<uint4*>(&sAw[(it * 4 + rA) * SA2_STRIDE + 4 * cA]) = pf1[it];
        __syncwarp();
        unsigned afr1[4][4];
#pragma unroll
        for (int kk = 0; kk < 4; kk++) {
            int kc = kk * 8;
            afr1[kk][0] = sAw[gid * SA2_STRIDE + kc + tig];
            afr1[kk][1] = sAw[(gid + 8) * SA2_STRIDE + kc + tig];
            afr1[kk][2] = sAw[gid * SA2_STRIDE + kc + tig + 4];
            afr1[kk][3] = sAw[(gid + 8) * SA2_STRIDE + kc + tig + 4];
        }

        // ---- prefetch next pair under compute ----
        if (nextPair < NPAIRS) {
            const uint4* b0p = hagg4 + (2 * nextPair) * 128;
            const uint4* b1p = hagg4 + (2 * nextPair + 1) * 128;
#pragma unroll
            for (int it = 0; it < 4; it++) {
                pf0[it] = b0p[(it * 4 + rA) * 8 + cA];
                pf1[it] = b1p[(it * 4 + rA) * 8 + cA];
            }
        }

        // ---- stage 1: H = relu(A @ W1 + b1), B shared across strips ----
#pragma unroll
        for (int j = 0; j < 16; j++) {
            float cAc[4] = {0.f, 0.f, 0.f, 0.f};
            float cBc[4] = {0.f, 0.f, 0.f, 0.f};
#pragma unroll
            for (int kk = 0; kk < 4; kk++) {
                uint2 b = *reinterpret_cast<const uint2*>(
                    &sW1f[((j * 4 + kk) * 32 + lane) * 2]);
                mma_f16(cAc, afr0[kk], b.x, b.y);
                mma_f16(cBc, afr1[kk], b.x, b.y);
            }
            const int colg = j * 8 + 2 * tig;
            const int cp   = j * 4 + tig;
            const float bi0 = sb1[colg], bi1 = sb1[colg + 1];
            sH0w[gid * SH2_STRIDE + cp] =
                h2bits(fmaxf(cAc[0] + bi0, 0.f), fmaxf(cAc[1] + bi1, 0.f));
            sH0w[(gid + 8) * SH2_STRIDE + cp] =
                h2bits(fmaxf(cAc[2] + bi0, 0.f), fmaxf(cAc[3] + bi1, 0.f));
            sH1w[gid * SH2_STRIDE + cp] =
                h2bits(fmaxf(cBc[0] + bi0, 0.f), fmaxf(cBc[1] + bi1, 0.f));
            sH1w[(gid + 8) * SH2_STRIDE + cp] =
                h2bits(fmaxf(cBc[2] + bi0, 0.f), fmaxf(cBc[3] + bi1, 0.f));
        }
        __syncwarp();

        // ---- load H fragments ----
        unsigned ah0[8][4], ah1[8][4];
#pragma unroll
        for (int kk = 0; kk < 8; kk++) {
            int kc = kk * 8;
            ah0[kk][0] = sH0w[gid * SH2_STRIDE + kc + tig];
            ah0[kk][1] = sH0w[(gid + 8) * SH2_STRIDE + kc + tig];
            ah0[kk][2] = sH0w[gid * SH2_STRIDE + kc + tig + 4];
            ah0[kk][3] = sH0w[(gid + 8) * SH2_STRIDE + kc + tig + 4];
            ah1[kk][0] = sH1w[gid * SH2_STRIDE + kc + tig];
            ah1[kk][1] = sH1w[(gid + 8) * SH2_STRIDE + kc + tig];
            ah1[kk][2] = sH1w[gid * SH2_STRIDE + kc + tig + 4];
            ah1[kk][3] = sH1w[(gid + 8) * SH2_STRIDE + kc + tig + 4];
        }

        // ---- stage 2: O = relu(H @ W2 + b2) -> f32 d_out ----
        float* o00 = outp + (s0 * 16 + gid) * CD;
        float* o01 = outp + (s0 * 16 + gid + 8) * CD;
        float* o10 = outp + ((s0 + 1) * 16 + gid) * CD;
        float* o11 = outp + ((s0 + 1) * 16 + gid + 8) * CD;
#pragma unroll
        for (int j = 0; j < 8; j++) {
            float cAc[4] = {0.f, 0.f, 0.f, 0.f};
            float cBc[4] = {0.f, 0.f, 0.f, 0.f};
#pragma unroll
            for (int kk = 0; kk < 8; kk++) {
                uint2 b = *reinterpret_cast<const uint2*>(
                    &sW2f[((j * 8 + kk) * 32 + lane) * 2]);
                mma_f16(cAc, ah0[kk], b.x, b.y);
                mma_f16(cBc, ah1[kk], b.x, b.y);
            }
            const int col = j * 8 + 2 * tig;
            const float bi0 = sb2[col], bi1 = sb2[col + 1];
            *reinterpret_cast<float2*>(o00 + col) =
                make_float2(fmaxf(cAc[0] + bi0, 0.f), fmaxf(cAc[1] + bi1, 0.f));
            *reinterpret_cast<float2*>(o01 + col) =
                make_float2(fmaxf(cAc[2] + bi0, 0.f), fmaxf(cAc[3] + bi1, 0.f));
            *reinterpret_cast<float2*>(o10 + col) =
                make_float2(fmaxf(cBc[0] + bi0, 0.f), fmaxf(cBc[1] + bi1, 0.f));
            *reinterpret_cast<float2*>(o11 + col) =
                make_float2(fmaxf(cBc[2] + bi0, 0.f), fmaxf(cBc[3] + bi1, 0.f));
        }

        pair = nextPair;
    }
}

// ---------------------------------------------------------------------------
// Launch
// Inputs (metadata order):
//  0 atom_repr [N,64] f32     1 src [E] i32      2 dst [E] i32
//  3 r_dir     4 r_type       5 r_ring           6 p_dir
//  7 p_type    8 p_ring       9 r_len f32       10 p_len f32
// 11 emb_dir [8,32]          12 emb_type [16,32] 13 emb_ring [4,32]
// 14 rbf_W [20,32]           15 rbf_b [32]
// 16 W1 [64,128]             17 b1 [128]
// 18 W2 [128,64]             19 b2 [64]
// Output: [N,64] f32
// ---------------------------------------------------------------------------
extern "C" void kernel_launch(void* const* d_in, const int* in_sizes, int n_in,
                              void* d_out, int out_size) {
    const float* atom     = (const float*)d_in[0];
    const int*   src      = (const int*)d_in[1];
    const int*   dst      = (const int*)d_in[2];
    const int*   rdir     = (const int*)d_in[3];
    const int*   rtype    = (const int*)d_in[4];
    const int*   rring    = (const int*)d_in[5];
    const int*   pdir     = (const int*)d_in[6];
    const int*   ptype    = (const int*)d_in[7];
    const int*   pring    = (const int*)d_in[8];
    const float* rlen     = (const float*)d_in[9];
    const float* plen     = (const float*)d_in[10];
    const float* emb_dir  = (const float*)d_in[11];
    const float* emb_type = (const float*)d_in[12];
    const float* emb_ring = (const float*)d_in[13];
    const float* rbf_W    = (const float*)d_in[14];
    const float* rbf_b    = (const float*)d_in[15];
    const float* W1       = (const float*)d_in[16];
    const float* b1       = (const float*)d_in[17];
    const float* W2       = (const float*)d_in[18];
    const float* b2       = (const float*)d_in[19];
    float* out = (float*)d_out;

    // 0) fused prep: zero fp16 agg + pack metadata + ct/tab tables
    prep_kernel<<<2048, 256>>>(rdir, rtype, rring, pdir, ptype, pring,
                               rlen, plen, emb_dir, emb_type, emb_ring,
                               rbf_W, rbf_b);

    // 1) edge scatter (fp16 vector atomics)
    edge_kernel<<<2368, 256>>>(atom, src, dst);

    // 2) persistent strip-pair FP16 tensor-core MLP (hagg -> d_out)
    size_t smem = (size_t)(4096 + 4096 + HID + CD
                           + 8 * 16 * SA2_STRIDE
                           + 8 * 2 * 16 * SH2_STRIDE) * 4;
    cudaFuncSetAttribute(mlp_kernel, cudaFuncAttributeMaxDynamicSharedMemorySize,
                         (int)smem);
    mlp_kernel<<<148, 256, smem>>>(out, W1, b1, W2, b2);
}

// round 16
// speedup vs baseline: 8.1228x; 1.1291x over previous
#include <cuda_runtime.h>
#include <cuda_fp16.h>
#include <cstdint>

// Problem constants (fixed by the reference)
#define N_NODES 500000
#define N_EDGES 1000000
#define D       32
#define CD      64
#define HID     128
#define NCEN    20
#define RBF_GAMMA 10.0f

#define TAB_INTERVALS 256         // PWL intervals over len in [0,2)
#define TAB_SCALE     128.0f      // intervals per unit length

#define FULLMASK 0xffffffffu

// ---- device-global precomputed tables / scratch (allowed) ------------------
__device__ float  g_ct[512 * 32];               // combined cat embedding (64KB)
__device__ float4 g_tabv[TAB_INTERVALS * 8];    // PWL values (32KB)
__device__ float4 g_tabd[TAB_INTERVALS * 8];    // PWL slopes (32KB)
__device__ int4   g_pack[N_EDGES];              // {icr|icp<<16, ir|ip<<16, fr, fp}
__device__ unsigned g_hagg2[N_NODES * 32];      // fp16 aggregation (half2 words, 64MB)

__device__ __forceinline__ unsigned h2bits(float lo, float hi) {
    __half2 h = __floats2half2_rn(lo, hi);
    return *reinterpret_cast<unsigned*>(&h);
}

// ---------------------------------------------------------------------------
// Fused prep kernel: zero g_hagg2 + pack edge metadata + build ct/tab tables.
// ---------------------------------------------------------------------------
__global__ void prep_kernel(
    const int* __restrict__ rdir, const int* __restrict__ rtype, const int* __restrict__ rring,
    const int* __restrict__ pdir, const int* __restrict__ ptype, const int* __restrict__ pring,
    const float* __restrict__ rlen, const float* __restrict__ plen,
    const float* __restrict__ emb_dir, const float* __restrict__ emb_type,
    const float* __restrict__ emb_ring,
    const float* __restrict__ rbf_W, const float* __restrict__ rbf_b)
{
    const int ZN = N_NODES * 32 / 4;            // 4,000,000 uint4 zero items
    const int PN = ZN + N_EDGES;
    const int CN = PN + 512 * 32;
    const int TN = CN + TAB_INTERVALS * 8;
    uint4* hz = reinterpret_cast<uint4*>(g_hagg2);
    const uint4 z4 = make_uint4(0u, 0u, 0u, 0u);

    for (int i = blockIdx.x * blockDim.x + threadIdx.x; i < TN;
         i += gridDim.x * blockDim.x) {
        if (i < ZN) {
            hz[i] = z4;
        } else if (i < PN) {
            int e = i - ZN;
            int icr = (rdir[e] * 16 + rtype[e]) * 4 + rring[e];
            int icp = (pdir[e] * 16 + ptype[e]) * 4 + pring[e];
            float xr = rlen[e] * TAB_SCALE;
            int   ir = min((int)xr, TAB_INTERVALS - 1);
            float fr = xr - (float)ir;
            float xp = plen[e] * TAB_SCALE;
            int   ip = min((int)xp, TAB_INTERVALS - 1);
            float fp_ = xp - (float)ip;
            int4 P;
            P.x = icr | (icp << 16);
            P.y = ir | (ip << 16);
            P.z = __float_as_int(fr);
            P.w = __float_as_int(fp_);
            g_pack[e] = P;
        } else if (i < CN) {
            int idx = i - PN;
            int l = idx & 31;
            int comb = idx >> 5;
            int ring = comb & 3;
            int type = (comb >> 2) & 15;
            int dir  = comb >> 6;
            g_ct[idx] = emb_dir[dir * 32 + l] + emb_type[type * 32 + l]
                      + emb_ring[ring * 32 + l];
        } else {
            int idx = i - CN;
            int q = idx & 7;
            int iv = idx >> 3;
            float x0 = (float)iv / TAB_SCALE;
            float x1 = (float)(iv + 1) / TAB_SCALE;
            float v0[4], v1[4];
#pragma unroll
            for (int c = 0; c < 4; c++) { v0[c] = rbf_b[4 * q + c]; v1[c] = v0[c]; }
#pragma unroll
            for (int k = 0; k < NCEN; k++) {
                float ctr = 0.1f * (float)k;
                float d0 = x0 - ctr, d1 = x1 - ctr;
                float e0 = expf(-RBF_GAMMA * d0 * d0);
                float e1 = expf(-RBF_GAMMA * d1 * d1);
#pragma unroll
                for (int c = 0; c < 4; c++) {
                    float wv = rbf_W[k * 32 + 4 * q + c];
                    v0[c] = fmaf(e0, wv, v0[c]);
                    v1[c] = fmaf(e1, wv, v1[c]);
                }
            }
            g_tabv[idx] = make_float4(v0[0], v0[1], v0[2], v0[3]);
            g_tabd[idx] = make_float4(v1[0] - v0[0], v1[1] - v0[1],
                                      v1[2] - v0[2], v1[3] - v0[3]);
        }
    }
}

// ---------------------------------------------------------------------------
// Kernel 2: edge message + FP16 scatter. ONE edge per 8 lanes (4 edges/warp).
// Lane j owns global channels 8j..8j+7 (both quads in the same embed half),
// producing 4 half2 words -> one red.global.add.noftz.v4.f16x2 per lane.
// Zero shuffles; consecutive e per warp keeps pack/src/dst sector-coalesced.
// ---------------------------------------------------------------------------
__global__ __launch_bounds__(256, 4) void edge_kernel(
    const float* __restrict__ atom,
    const int*   __restrict__ src, const int* __restrict__ dst)
{
    const int l  = threadIdx.x & 31;
    const int g2 = l >> 3;               // edge group within warp (0..3)
    const int j  = l & 7;                // lane within group
    const bool upper = (j >= 4);         // channels 32..63 -> (p - r) half
    const int qb = (2 * j) & 7;          // first quad within 32-ch embed
    const int cb = 4 * qb;               // within-embed channel base
    const int warp = (blockIdx.x * blockDim.x + threadIdx.x) >> 5;
    const int nwarps = (gridDim.x * blockDim.x) >> 5;

    for (int e = warp * 4 + g2; e < N_EDGES; e += nwarps * 4) {
        const int4 P = g_pack[e];
        const int s  = src[e];
        const int dn = dst[e];
        const int icr = P.x & 0xffff;
        const int icp = P.x >> 16;
        const int ir  = P.y & 0xffff;
        const int ip  = P.y >> 16;
        const float fr  = __int_as_float(P.z);
        const float fp_ = __int_as_float(P.w);

        const float* arow = atom + (size_t)s * CD + 8 * j;
        float4 a0 = *reinterpret_cast<const float4*>(arow);
        float4 a1 = *reinterpret_cast<const float4*>(arow + 4);

        // ---- quad A (channels cb..cb+3) ----
        float4 cr0 = *reinterpret_cast<const float4*>(&g_ct[icr * 32 + cb]);
        float4 cp0 = *reinterpret_cast<const float4*>(&g_ct[icp * 32 + cb]);
        float4 vr0 = g_tabv[ir * 8 + qb];
        float4 dr0 = g_tabd[ir * 8 + qb];
        float4 vp0 = g_tabv[ip * 8 + qb];
        float4 dp0 = g_tabd[ip * 8 + qb];

        float reA0 = cr0.x + fmaf(fr, dr0.x, vr0.x);
        float reA1 = cr0.y + fmaf(fr, dr0.y, vr0.y);
        float reA2 = cr0.z + fmaf(fr, dr0.z, vr0.z);
        float reA3 = cr0.w + fmaf(fr, dr0.w, vr0.w);
        float peA0 = cp0.x + fmaf(fp_, dp0.x, vp0.x);
        float peA1 = cp0.y + fmaf(fp_, dp0.y, vp0.y);
        float peA2 = cp0.z + fmaf(fp_, dp0.z, vp0.z);
        float peA3 = cp0.w + fmaf(fp_, dp0.w, vp0.w);

        float m0 = a0.x + (upper ? (peA0 - reA0) : reA0);
        float m1 = a0.y + (upper ? (peA1 - reA1) : reA1);
        float m2 = a0.z + (upper ? (peA2 - reA2) : reA2);
        float m3 = a0.w + (upper ? (peA3 - reA3) : reA3);
        unsigned w0 = h2bits(m0, m1);
        unsigned w1 = h2bits(m2, m3);

        // ---- quad B (channels cb+4..cb+7) ----
        float4 cr1 = *reinterpret_cast<const float4*>(&g_ct[icr * 32 + cb + 4]);
        float4 cp1 = *reinterpret_cast<const float4*>(&g_ct[icp * 32 + cb + 4]);
        float4 vr1 = g_tabv[ir * 8 + qb + 1];
        float4 dr1 = g_tabd[ir * 8 + qb + 1];
        float4 vp1 = g_tabv[ip * 8 + qb + 1];
        float4 dp1 = g_tabd[ip * 8 + qb + 1];

        float reB0 = cr1.x + fmaf(fr, dr1.x, vr1.x);
        float reB1 = cr1.y + fmaf(fr, dr1.y, vr1.y);
        float reB2 = cr1.z + fmaf(fr, dr1.z, vr1.z);
        float reB3 = cr1.w + fmaf(fr, dr1.w, vr1.w);
        float peB0 = cp1.x + fmaf(fp_, dp1.x, vp1.x);
        float peB1 = cp1.y + fmaf(fp_, dp1.y, vp1.y);
        float peB2 = cp1.z + fmaf(fp_, dp1.z, vp1.z);
        float peB3 = cp1.w + fmaf(fp_, dp1.w, vp1.w);

        float n0 = a1.x + (upper ? (peB0 - reB0) : reB0);
        float n1 = a1.y + (upper ? (peB1 - reB1) : reB1);
        float n2 = a1.z + (upper ? (peB2 - reB2) : reB2);
        float n3 = a1.w + (upper ? (peB3 - reB3) : reB3);
        unsigned w2 = h2bits(n0, n1);
        unsigned w3 = h2bits(n2, n3);

        unsigned* p = g_hagg2 + (long)dn * 32 + 4 * j;
        asm volatile("red.global.add.noftz.v4.f16x2 [%0], {%1,%2,%3,%4};"
                     :: "l"(p), "r"(w0), "r"(w1), "r"(w2), "r"(w3));
    }
}

// ---------------------------------------------------------------------------
// Kernel 3: PERSISTENT FP16 tensor-core MLP (R15 config, ~50us).
// ---------------------------------------------------------------------------
#define SA2_STRIDE 36            // half2 words per A row (32 + 4 pad)
#define SH2_STRIDE 68            // half2 words per H row (64 + 4 pad)
#define NSTRIPS (N_NODES / 16)   // 31250
#define NPAIRS  (NSTRIPS / 2)    // 15625

__device__ __forceinline__ void mma_f16(float c[4], const unsigned a[4],
                                        unsigned b0, unsigned b1) {
    asm("mma.sync.aligned.m16n8k16.row.col.f32.f16.f16.f32 "
        "{%0,%1,%2,%3}, {%4,%5,%6,%7}, {%8,%9}, {%0,%1,%2,%3};"
        : "+f"(c[0]), "+f"(c[1]), "+f"(c[2]), "+f"(c[3])
        : "r"(a[0]), "r"(a[1]), "r"(a[2]), "r"(a[3]), "r"(b0), "r"(b1));
}

__global__ __launch_bounds__(256) void mlp_kernel(
    float* __restrict__ outp,
    const float* __restrict__ W1, const float* __restrict__ b1,
    const float* __restrict__ W2, const float* __restrict__ b2)
{
    extern __shared__ unsigned smu[];
    unsigned* sW1f = smu;                       // 4096 words: W1 fragment pairs
    unsigned* sW2f = sW1f + 4096;               // 4096 words: W2 fragment pairs
    float*    sb1  = (float*)(sW2f + 4096);     // [128]
    float*    sb2  = sb1 + HID;                 // [64]
    unsigned* sA   = (unsigned*)(sb2 + CD);     // 8 x [16][36] half2 words
    unsigned* sH   = sA + 8 * 16 * SA2_STRIDE;  // 8 x 2 x [16][68] half2 words

    const int tid  = threadIdx.x;
    const int w    = tid >> 5;
    const int lane = tid & 31;
    const int gid  = lane >> 2;
    const int tig  = lane & 3;

    for (int idx = tid; idx < 4096; idx += 256) {
        int r = idx & 1;
        int ln = (idx >> 1) & 31;
        int jk = idx >> 6;
        int kk = jk & 3, j = jk >> 2;
        int g_ = ln >> 2, t_ = ln & 3;
        int n = j * 8 + g_;
        int k0 = kk * 16 + 2 * t_ + r * 8;
        sW1f[idx] = h2bits(W1[k0 * HID + n], W1[(k0 + 1) * HID + n]);
    }
    for (int idx = tid; idx < 4096; idx += 256) {
        int r = idx & 1;
        int ln = (idx >> 1) & 31;
        int jk = idx >> 6;
        int kk = jk & 7, j = jk >> 3;
        int g_ = ln >> 2, t_ = ln & 3;
        int n = j * 8 + g_;
        int k0 = kk * 16 + 2 * t_ + r * 8;
        sW2f[idx] = h2bits(W2[k0 * CD + n], W2[(k0 + 1) * CD + n]);
    }
    if (tid < HID) sb1[tid] = b1[tid];
    if (tid < CD)  sb2[tid] = b2[tid];
    __syncthreads();

    unsigned* sAw  = sA + w * 16 * SA2_STRIDE;
    unsigned* sH0w = sH + (2 * w) * 16 * SH2_STRIDE;
    unsigned* sH1w = sH0w + 16 * SH2_STRIDE;

    const int gwarp   = blockIdx.x * 8 + w;
    const int wstride = gridDim.x * 8;
    const int rA = lane >> 3;            // A-load row group (0..3)
    const int cA = lane & 7;             // uint4 col within 128B row

    const uint4* hagg4 = reinterpret_cast<const uint4*>(g_hagg2);

    long pair = gwarp;
    uint4 pf0[4], pf1[4];
    if (pair < NPAIRS) {
        const uint4* b0p = hagg4 + (2 * pair) * 128;       // 16 rows x 8 uint4
        const uint4* b1p = hagg4 + (2 * pair + 1) * 128;
#pragma unroll
        for (int it = 0; it < 4; it++) {
            pf0[it] = b0p[(it * 4 + rA) * 8 + cA];
            pf1[it] = b1p[(it * 4 + rA) * 8 + cA];
        }
    }

    while (pair < NPAIRS) {
        const long s0 = 2 * pair;
        const long nextPair = pair + wstride;

        __syncwarp();
#pragma unroll
        for (int it = 0; it < 4; it++)
            *reinterpret_cast<uint4*>(&sAw[(it * 4 + rA) * SA2_STRIDE + 4 * cA]) = pf0[it];
        __syncwarp();
        unsigned afr0[4][4];
#pragma unroll
        for (int kk = 0; kk < 4; kk++) {
            int kc = kk * 8;
            afr0[kk][0] = sAw[gid * SA2_STRIDE + kc + tig];
            afr0[kk][1] = sAw[(gid + 8) * SA2_STRIDE + kc + tig];
            afr0[kk][2] = sAw[gid * SA2_STRIDE + kc + tig + 4];
            afr0[kk][3] = sAw[(gid + 8) * SA2_STRIDE + kc + tig + 4];
        }
        __syncwarp();
#pragma unroll
        for (int it = 0; it < 4; it++)
            *reinterpret_cast<uint4*>(&sAw[(it * 4 + rA) * SA2_STRIDE + 4 * cA]) = pf1[it];
        __syncwarp();
        unsigned afr1[4][4];
#pragma unroll
        for (int kk = 0; kk < 4; kk++) {
            int kc = kk * 8;
            afr1[kk][0] = sAw[gid * SA2_STRIDE + kc + tig];
            afr1[kk][1] = sAw[(gid + 8) * SA2_STRIDE + kc + tig];
            afr1[kk][2] = sAw[gid * SA2_STRIDE + kc + tig + 4];
            afr1[kk][3] = sAw[(gid + 8) * SA2_STRIDE + kc + tig + 4];
        }

        if (nextPair < NPAIRS) {
            const uint4* b0p = hagg4 + (2 * nextPair) * 128;
            const uint4* b1p = hagg4 + (2 * nextPair + 1) * 128;
#pragma unroll
            for (int it = 0; it < 4; it++) {
                pf0[it] = b0p[(it * 4 + rA) * 8 + cA];
                pf1[it] = b1p[(it * 4 + rA) * 8 + cA];
            }
        }

#pragma unroll
        for (int j = 0; j < 16; j++) {
            float cAc[4] = {0.f, 0.f, 0.f, 0.f};
            float cBc[4] = {0.f, 0.f, 0.f, 0.f};
#pragma unroll
            for (int kk = 0; kk < 4; kk++) {
                uint2 b = *reinterpret_cast<const uint2*>(
                    &sW1f[((j * 4 + kk) * 32 + lane) * 2]);
                mma_f16(cAc, afr0[kk], b.x, b.y);
                mma_f16(cBc, afr1[kk], b.x, b.y);
            }
            const int colg = j * 8 + 2 * tig;
            const int cp   = j * 4 + tig;
            const float bi0 = sb1[colg], bi1 = sb1[colg + 1];
            sH0w[gid * SH2_STRIDE + cp] =
                h2bits(fmaxf(cAc[0] + bi0, 0.f), fmaxf(cAc[1] + bi1, 0.f));
            sH0w[(gid + 8) * SH2_STRIDE + cp] =
                h2bits(fmaxf(cAc[2] + bi0, 0.f), fmaxf(cAc[3] + bi1, 0.f));
            sH1w[gid * SH2_STRIDE + cp] =
                h2bits(fmaxf(cBc[0] + bi0, 0.f), fmaxf(cBc[1] + bi1, 0.f));
            sH1w[(gid + 8) * SH2_STRIDE + cp] =
                h2bits(fmaxf(cBc[2] + bi0, 0.f), fmaxf(cBc[3] + bi1, 0.f));
        }
        __syncwarp();

        unsigned ah0[8][4], ah1[8][4];
#pragma unroll
        for (int kk = 0; kk < 8; kk++) {
            int kc = kk * 8;
            ah0[kk][0] = sH0w[gid * SH2_STRIDE + kc + tig];
            ah0[kk][1] = sH0w[(gid + 8) * SH2_STRIDE + kc + tig];
            ah0[kk][2] = sH0w[gid * SH2_STRIDE + kc + tig + 4];
            ah0[kk][3] = sH0w[(gid + 8) * SH2_STRIDE + kc + tig + 4];
            ah1[kk][0] = sH1w[gid * SH2_STRIDE + kc + tig];
            ah1[kk][1] = sH1w[(gid + 8) * SH2_STRIDE + kc + tig];
            ah1[kk][2] = sH1w[gid * SH2_STRIDE + kc + tig + 4];
            ah1[kk][3] = sH1w[(gid + 8) * SH2_STRIDE + kc + tig + 4];
        }

        float* o00 = outp + (s0 * 16 + gid) * CD;
        float* o01 = outp + (s0 * 16 + gid + 8) * CD;
        float* o10 = outp + ((s0 + 1) * 16 + gid) * CD;
        float* o11 = outp + ((s0 + 1) * 16 + gid + 8) * CD;
#pragma unroll
        for (int j = 0; j < 8; j++) {
            float cAc[4] = {0.f, 0.f, 0.f, 0.f};
            float cBc[4] = {0.f, 0.f, 0.f, 0.f};
#pragma unroll
            for (int kk = 0; kk < 8; kk++) {
                uint2 b = *reinterpret_cast<const uint2*>(
                    &sW2f[((j * 8 + kk) * 32 + lane) * 2]);
                mma_f16(cAc, ah0[kk], b.x, b.y);
                mma_f16(cBc, ah1[kk], b.x, b.y);
            }
            const int col = j * 8 + 2 * tig;
            const float bi0 = sb2[col], bi1 = sb2[col + 1];
            *reinterpret_cast<float2*>(o00 + col) =
                make_float2(fmaxf(cAc[0] + bi0, 0.f), fmaxf(cAc[1] + bi1, 0.f));
            *reinterpret_cast<float2*>(o01 + col) =
                make_float2(fmaxf(cAc[2] + bi0, 0.f), fmaxf(cAc[3] + bi1, 0.f));
            *reinterpret_cast<float2*>(o10 + col) =
                make_float2(fmaxf(cBc[0] + bi0, 0.f), fmaxf(cBc[1] + bi1, 0.f));
            *reinterpret_cast<float2*>(o11 + col) =
                make_float2(fmaxf(cBc[2] + bi0, 0.f), fmaxf(cBc[3] + bi1, 0.f));
        }

        pair = nextPair;
    }
}

// ---------------------------------------------------------------------------
// Launch
// Inputs (metadata order):
//  0 atom_repr [N,64] f32     1 src [E] i32      2 dst [E] i32
//  3 r_dir     4 r_type       5 r_ring           6 p_dir
//  7 p_type    8 p_ring       9 r_len f32       10 p_len f32
// 11 emb_dir [8,32]          12 emb_type [16,32] 13 emb_ring [4,32]
// 14 rbf_W [20,32]           15 rbf_b [32]
// 16 W1 [64,128]             17 b1 [128]
// 18 W2 [128,64]             19 b2 [64]
// Output: [N,64] f32
// ---------------------------------------------------------------------------
extern "C" void kernel_launch(void* const* d_in, const int* in_sizes, int n_in,
                              void* d_out, int out_size) {
    const float* atom     = (const float*)d_in[0];
    const int*   src      = (const int*)d_in[1];
    const int*   dst      = (const int*)d_in[2];
    const int*   rdir     = (const int*)d_in[3];
    const int*   rtype    = (const int*)d_in[4];
    const int*   rring    = (const int*)d_in[5];
    const int*   pdir     = (const int*)d_in[6];
    const int*   ptype    = (const int*)d_in[7];
    const int*   pring    = (const int*)d_in[8];
    const float* rlen     = (const float*)d_in[9];
    const float* plen     = (const float*)d_in[10];
    const float* emb_dir  = (const float*)d_in[11];
    const float* emb_type = (const float*)d_in[12];
    const float* emb_ring = (const float*)d_in[13];
    const float* rbf_W    = (const float*)d_in[14];
    const float* rbf_b    = (const float*)d_in[15];
    const float* W1       = (const float*)d_in[16];
    const float* b1       = (const float*)d_in[17];
    const float* W2       = (const float*)d_in[18];
    const float* b2       = (const float*)d_in[19];
    float* out = (float*)d_out;

    // 0) fused prep: zero fp16 agg + pack metadata + ct/tab tables
    prep_kernel<<<2048, 256>>>(rdir, rtype, rring, pdir, ptype, pring,
                               rlen, plen, emb_dir, emb_type, emb_ring,
                               rbf_W, rbf_b);

    // 1) edge scatter (8 lanes/edge, shuffle-free fp16 vector atomics)
    edge_kernel<<<2368, 256>>>(atom, src, dst);

    // 2) persistent strip-pair FP16 tensor-core MLP (hagg -> d_out)
    size_t smem = (size_t)(4096 + 4096 + HID + CD
                           + 8 * 16 * SA2_STRIDE
                           + 8 * 2 * 16 * SH2_STRIDE) * 4;
    cudaFuncSetAttribute(mlp_kernel, cudaFuncAttributeMaxDynamicSharedMemorySize,
                         (int)smem);
    mlp_kernel<<<148, 256, smem>>>(out, W1, b1, W2, b2);
}

// round 17
// speedup vs baseline: 8.2889x; 1.0204x over previous
#include <cuda_runtime.h>
#include <cuda_fp16.h>
#include <cstdint>

// Problem constants (fixed by the reference)
#define N_NODES 500000
#define N_EDGES 1000000
#define D       32
#define CD      64
#define HID     128
#define NCEN    20
#define RBF_GAMMA 10.0f

#define TAB_INTERVALS 256         // PWL intervals over len in [0,2)
#define TAB_SCALE     128.0f      // intervals per unit length

#define FULLMASK 0xffffffffu

// ---- device-global precomputed tables / scratch (allowed) ------------------
__device__ float  g_ct[512 * 32];               // combined cat embedding (64KB)
__device__ float4 g_tabv[TAB_INTERVALS * 8];    // PWL values (32KB)
__device__ float4 g_tabd[TAB_INTERVALS * 8];    // PWL slopes (32KB)
__device__ int4   g_pack[N_EDGES];              // {icr|icp<<16, ir|ip<<16, fr, fp}
__device__ unsigned g_hagg2[N_NODES * 32];      // fp16 aggregation (half2 words, 64MB)

__device__ __forceinline__ unsigned h2bits(float lo, float hi) {
    __half2 h = __floats2half2_rn(lo, hi);
    return *reinterpret_cast<unsigned*>(&h);
}

// ---------------------------------------------------------------------------
// Fused prep kernel: zero g_hagg2 + pack edge metadata + build ct/tab tables.
// ---------------------------------------------------------------------------
__global__ void prep_kernel(
    const int* __restrict__ rdir, const int* __restrict__ rtype, const int* __restrict__ rring,
    const int* __restrict__ pdir, const int* __restrict__ ptype, const int* __restrict__ pring,
    const float* __restrict__ rlen, const float* __restrict__ plen,
    const float* __restrict__ emb_dir, const float* __restrict__ emb_type,
    const float* __restrict__ emb_ring,
    const float* __restrict__ rbf_W, const float* __restrict__ rbf_b)
{
    const int ZN = N_NODES * 32 / 4;            // 4,000,000 uint4 zero items
    const int PN = ZN + N_EDGES;
    const int CN = PN + 512 * 32;
    const int TN = CN + TAB_INTERVALS * 8;
    uint4* hz = reinterpret_cast<uint4*>(g_hagg2);
    const uint4 z4 = make_uint4(0u, 0u, 0u, 0u);

    for (int i = blockIdx.x * blockDim.x + threadIdx.x; i < TN;
         i += gridDim.x * blockDim.x) {
        if (i < ZN) {
            hz[i] = z4;
        } else if (i < PN) {
            int e = i - ZN;
            int icr = (rdir[e] * 16 + rtype[e]) * 4 + rring[e];
            int icp = (pdir[e] * 16 + ptype[e]) * 4 + pring[e];
            float xr = rlen[e] * TAB_SCALE;
            int   ir = min((int)xr, TAB_INTERVALS - 1);
            float fr = xr - (float)ir;
            float xp = plen[e] * TAB_SCALE;
            int   ip = min((int)xp, TAB_INTERVALS - 1);
            float fp_ = xp - (float)ip;
            int4 P;
            P.x = icr | (icp << 16);
            P.y = ir | (ip << 16);
            P.z = __float_as_int(fr);
            P.w = __float_as_int(fp_);
            g_pack[e] = P;
        } else if (i < CN) {
            int idx = i - PN;
            int l = idx & 31;
            int comb = idx >> 5;
            int ring = comb & 3;
            int type = (comb >> 2) & 15;
            int dir  = comb >> 6;
            g_ct[idx] = emb_dir[dir * 32 + l] + emb_type[type * 32 + l]
                      + emb_ring[ring * 32 + l];
        } else {
            int idx = i - CN;
            int q = idx & 7;
            int iv = idx >> 3;
            float x0 = (float)iv / TAB_SCALE;
            float x1 = (float)(iv + 1) / TAB_SCALE;
            float v0[4], v1[4];
#pragma unroll
            for (int c = 0; c < 4; c++) { v0[c] = rbf_b[4 * q + c]; v1[c] = v0[c]; }
#pragma unroll
            for (int k = 0; k < NCEN; k++) {
                float ctr = 0.1f * (float)k;
                float d0 = x0 - ctr, d1 = x1 - ctr;
                float e0 = expf(-RBF_GAMMA * d0 * d0);
                float e1 = expf(-RBF_GAMMA * d1 * d1);
#pragma unroll
                for (int c = 0; c < 4; c++) {
                    float wv = rbf_W[k * 32 + 4 * q + c];
                    v0[c] = fmaf(e0, wv, v0[c]);
                    v1[c] = fmaf(e1, wv, v1[c]);
                }
            }
            g_tabv[idx] = make_float4(v0[0], v0[1], v0[2], v0[3]);
            g_tabd[idx] = make_float4(v1[0] - v0[0], v1[1] - v0[1],
                                      v1[2] - v0[2], v1[3] - v0[3]);
        }
    }
}

// ---------------------------------------------------------------------------
// Kernel 2: edge message + FP16 scatter. ONE edge per 8 lanes (4 edges/warp),
// lane j owns channels 8j..8j+7, one red.v4.f16x2 per lane, zero shuffles.
// 2-stage software pipeline: next iteration's pack/src/dst/gather loads are
// issued BEFORE the current RED (which, being volatile asm, blocks compiler
// hoisting) so the ~600-cyc DRAM gather overlaps current compute.
// ---------------------------------------------------------------------------
__global__ __launch_bounds__(256, 4) void edge_kernel(
    const float* __restrict__ atom,
    const int*   __restrict__ src, const int* __restrict__ dst)
{
    const int l  = threadIdx.x & 31;
    const int g2 = l >> 3;               // edge group within warp (0..3)
    const int j  = l & 7;                // lane within group
    const bool upper = (j >= 4);         // channels 32..63 -> (p - r) half
    const int qb = (2 * j) & 7;          // first quad within 32-ch embed
    const int cb = 4 * qb;               // within-embed channel base
    const int warp = (blockIdx.x * blockDim.x + threadIdx.x) >> 5;
    const int nwarps = (gridDim.x * blockDim.x) >> 5;
    const int estep = nwarps * 4;

    int e = warp * 4 + g2;
    if (e >= N_EDGES) return;

    // ---- stage-in first edge's long-latency data ----
    int4 P = g_pack[e];
    int  s  = src[e];
    int  dn = dst[e];
    const float* arow = atom + (size_t)s * CD + 8 * j;
    float4 a0 = *reinterpret_cast<const float4*>(arow);
    float4 a1 = *reinterpret_cast<const float4*>(arow + 4);

    while (true) {
        const int e1 = e + estep;
        const bool has = (e1 < N_EDGES);

        const int icr = P.x & 0xffff;
        const int icp = P.x >> 16;
        const int ir  = P.y & 0xffff;
        const int ip  = P.y >> 16;
        const float fr  = __int_as_float(P.z);
        const float fp_ = __int_as_float(P.w);

        // table loads for current edge (L1-resident, short latency)
        float4 cr0 = *reinterpret_cast<const float4*>(&g_ct[icr * 32 + cb]);
        float4 cp0 = *reinterpret_cast<const float4*>(&g_ct[icp * 32 + cb]);
        float4 vr0 = g_tabv[ir * 8 + qb];
        float4 dr0 = g_tabd[ir * 8 + qb];
        float4 vp0 = g_tabv[ip * 8 + qb];
        float4 dp0 = g_tabd[ip * 8 + qb];
        float4 cr1 = *reinterpret_cast<const float4*>(&g_ct[icr * 32 + cb + 4]);
        float4 cp1 = *reinterpret_cast<const float4*>(&g_ct[icp * 32 + cb + 4]);
        float4 vr1 = g_tabv[ir * 8 + qb + 1];
        float4 dr1 = g_tabd[ir * 8 + qb + 1];
        float4 vp1 = g_tabv[ip * 8 + qb + 1];
        float4 dp1 = g_tabd[ip * 8 + qb + 1];

        // ---- prefetch NEXT edge's long-latency data (before the RED) ----
        int4 Pn;
        int  sn = 0, dnn = 0;
        float4 a0n, a1n;
        if (has) {
            Pn  = g_pack[e1];
            sn  = src[e1];
            dnn = dst[e1];
            const float* arown = atom + (size_t)sn * CD + 8 * j;
            a0n = *reinterpret_cast<const float4*>(arown);
            a1n = *reinterpret_cast<const float4*>(arown + 4);
        }

        // ---- compute current messages ----
        float reA0 = cr0.x + fmaf(fr, dr0.x, vr0.x);
        float reA1 = cr0.y + fmaf(fr, dr0.y, vr0.y);
        float reA2 = cr0.z + fmaf(fr, dr0.z, vr0.z);
        float reA3 = cr0.w + fmaf(fr, dr0.w, vr0.w);
        float peA0 = cp0.x + fmaf(fp_, dp0.x, vp0.x);
        float peA1 = cp0.y + fmaf(fp_, dp0.y, vp0.y);
        float peA2 = cp0.z + fmaf(fp_, dp0.z, vp0.z);
        float peA3 = cp0.w + fmaf(fp_, dp0.w, vp0.w);

        float m0 = a0.x + (upper ? (peA0 - reA0) : reA0);
        float m1 = a0.y + (upper ? (peA1 - reA1) : reA1);
        float m2 = a0.z + (upper ? (peA2 - reA2) : reA2);
        float m3 = a0.w + (upper ? (peA3 - reA3) : reA3);
        unsigned w0 = h2bits(m0, m1);
        unsigned w1 = h2bits(m2, m3);

        float reB0 = cr1.x + fmaf(fr, dr1.x, vr1.x);
        float reB1 = cr1.y + fmaf(fr, dr1.y, vr1.y);
        float reB2 = cr1.z + fmaf(fr, dr1.z, vr1.z);
        float reB3 = cr1.w + fmaf(fr, dr1.w, vr1.w);
        float peB0 = cp1.x + fmaf(fp_, dp1.x, vp1.x);
        float peB1 = cp1.y + fmaf(fp_, dp1.y, vp1.y);
        float peB2 = cp1.z + fmaf(fp_, dp1.z, vp1.z);
        float peB3 = cp1.w + fmaf(fp_, dp1.w, vp1.w);

        float n0 = a1.x + (upper ? (peB0 - reB0) : reB0);
        float n1 = a1.y + (upper ? (peB1 - reB1) : reB1);
        float n2 = a1.z + (upper ? (peB2 - reB2) : reB2);
        float n3 = a1.w + (upper ? (peB3 - reB3) : reB3);
        unsigned w2 = h2bits(n0, n1);
        unsigned w3 = h2bits(n2, n3);

        unsigned* p = g_hagg2 + (long)dn * 32 + 4 * j;
        asm volatile("red.global.add.noftz.v4.f16x2 [%0], {%1,%2,%3,%4};"
                     :: "l"(p), "r"(w0), "r"(w1), "r"(w2), "r"(w3));

        if (!has) break;
        P = Pn; s = sn; dn = dnn; a0 = a0n; a1 = a1n; e = e1;
    }
}

// ---------------------------------------------------------------------------
// Kernel 3: PERSISTENT FP16 tensor-core MLP (R15/16 config, ~50us).
// ---------------------------------------------------------------------------
#define SA2_STRIDE 36            // half2 words per A row (32 + 4 pad)
#define SH2_STRIDE 68            // half2 words per H row (64 + 4 pad)
#define NSTRIPS (N_NODES / 16)   // 31250
#define NPAIRS  (NSTRIPS / 2)    // 15625

__device__ __forceinline__ void mma_f16(float c[4], const unsigned a[4],
                                        unsigned b0, unsigned b1) {
    asm("mma.sync.aligned.m16n8k16.row.col.f32.f16.f16.f32 "
        "{%0,%1,%2,%3}, {%4,%5,%6,%7}, {%8,%9}, {%0,%1,%2,%3};"
        : "+f"(c[0]), "+f"(c[1]), "+f"(c[2]), "+f"(c[3])
        : "r"(a[0]), "r"(a[1]), "r"(a[2]), "r"(a[3]), "r"(b0), "r"(b1));
}

__global__ __launch_bounds__(256) void mlp_kernel(
    float* __restrict__ outp,
    const float* __restrict__ W1, const float* __restrict__ b1,
    const float* __restrict__ W2, const float* __restrict__ b2)
{
    extern __shared__ unsigned smu[];
    unsigned* sW1f = smu;                       // 4096 words: W1 fragment pairs
    unsigned* sW2f = sW1f + 4096;               // 4096 words: W2 fragment pairs
    float*    sb1  = (float*)(sW2f + 4096);     // [128]
    float*    sb2  = sb1 + HID;                 // [64]
    unsigned* sA   = (unsigned*)(sb2 + CD);     // 8 x [16][36] half2 words
    unsigned* sH   = sA + 8 * 16 * SA2_STRIDE;  // 8 x 2 x [16][68] half2 words

    const int tid  = threadIdx.x;
    const int w    = tid >> 5;
    const int lane = tid & 31;
    const int gid  = lane >> 2;
    const int tig  = lane & 3;

    for (int idx = tid; idx < 4096; idx += 256) {
        int r = idx & 1;
        int ln = (idx >> 1) & 31;
        int jk = idx >> 6;
        int kk = jk & 3, j = jk >> 2;
        int g_ = ln >> 2, t_ = ln & 3;
        int n = j * 8 + g_;
        int k0 = kk * 16 + 2 * t_ + r * 8;
        sW1f[idx] = h2bits(W1[k0 * HID + n], W1[(k0 + 1) * HID + n]);
    }
    for (int idx = tid; idx < 4096; idx += 256) {
        int r = idx & 1;
        int ln = (idx >> 1) & 31;
        int jk = idx >> 6;
        int kk = jk & 7, j = jk >> 3;
        int g_ = ln >> 2, t_ = ln & 3;
        int n = j * 8 + g_;
        int k0 = kk * 16 + 2 * t_ + r * 8;
        sW2f[idx] = h2bits(W2[k0 * CD + n], W2[(k0 + 1) * CD + n]);
    }
    if (tid < HID) sb1[tid] = b1[tid];
    if (tid < CD)  sb2[tid] = b2[tid];
    __syncthreads();

    unsigned* sAw  = sA + w * 16 * SA2_STRIDE;
    unsigned* sH0w = sH + (2 * w) * 16 * SH2_STRIDE;
    unsigned* sH1w = sH0w + 16 * SH2_STRIDE;

    const int gwarp   = blockIdx.x * 8 + w;
    const int wstride = gridDim.x * 8;
    const int rA = lane >> 3;            // A-load row group (0..3)
    const int cA = lane & 7;             // uint4 col within 128B row

    const uint4* hagg4 = reinterpret_cast<const uint4*>(g_hagg2);

    long pair = gwarp;
    uint4 pf0[4], pf1[4];
    if (pair < NPAIRS) {
        const uint4* b0p = hagg4 + (2 * pair) * 128;       // 16 rows x 8 uint4
        const uint4* b1p = hagg4 + (2 * pair + 1) * 128;
#pragma unroll
        for (int it = 0; it < 4; it++) {
            pf0[it] = b0p[(it * 4 + rA) * 8 + cA];
            pf1[it] = b1p[(it * 4 + rA) * 8 + cA];
        }
    }

    while (pair < NPAIRS) {
        const long s0 = 2 * pair;
        const long nextPair = pair + wstride;

        __syncwarp();
#pragma unroll
        for (int it = 0; it < 4; it++)
            *reinterpret_cast<uint4*>(&sAw[(it * 4 + rA) * SA2_STRIDE + 4 * cA]) = pf0[it];
        __syncwarp();
        unsigned afr0[4][4];
#pragma unroll
        for (int kk = 0; kk < 4; kk++) {
            int kc = kk * 8;
            afr0[kk][0] = sAw[gid * SA2_STRIDE + kc + tig];
            afr0[kk][1] = sAw[(gid + 8) * SA2_STRIDE + kc + tig];
            afr0[kk][2] = sAw[gid * SA2_STRIDE + kc + tig + 4];
            afr0[kk][3] = sAw[(gid + 8) * SA2_STRIDE + kc + tig + 4];
        }
        __syncwarp();
#pragma unroll
        for (int it = 0; it < 4; it++)
            *reinterpret_cast<uint4*>(&sAw[(it * 4 + rA) * SA2_STRIDE + 4 * cA]) = pf1[it];
        __syncwarp();
        unsigned afr1[4][4];
#pragma unroll
        for (int kk = 0; kk < 4; kk++) {
            int kc = kk * 8;
            afr1[kk][0] = sAw[gid * SA2_STRIDE + kc + tig];
            afr1[kk][1] = sAw[(gid + 8) * SA2_STRIDE + kc + tig];
            afr1[kk][2] = sAw[gid * SA2_STRIDE + kc + tig + 4];
            afr1[kk][3] = sAw[(gid + 8) * SA2_STRIDE + kc + tig + 4];
        }

        if (nextPair < NPAIRS) {
            const uint4* b0p = hagg4 + (2 * nextPair) * 128;
            const uint4* b1p = hagg4 + (2 * nextPair + 1) * 128;
#pragma unroll
            for (int it = 0; it < 4; it++) {
                pf0[it] = b0p[(it * 4 + rA) * 8 + cA];
                pf1[it] = b1p[(it * 4 + rA) * 8 + cA];
            }
        }

#pragma unroll
        for (int j = 0; j < 16; j++) {
            float cAc[4] = {0.f, 0.f, 0.f, 0.f};
            float cBc[4] = {0.f, 0.f, 0.f, 0.f};
#pragma unroll
            for (int kk = 0; kk < 4; kk++) {
                uint2 b = *reinterpret_cast<const uint2*>(
                    &sW1f[((j * 4 + kk) * 32 + lane) * 2]);
                mma_f16(cAc, afr0[kk], b.x, b.y);
                mma_f16(cBc, afr1[kk], b.x, b.y);
            }
            const int colg = j * 8 + 2 * tig;
            const int cp   = j * 4 + tig;
            const float bi0 = sb1[colg], bi1 = sb1[colg + 1];
            sH0w[gid * SH2_STRIDE + cp] =
                h2bits(fmaxf(cAc[0] + bi0, 0.f), fmaxf(cAc[1] + bi1, 0.f));
            sH0w[(gid + 8) * SH2_STRIDE + cp] =
                h2bits(fmaxf(cAc[2] + bi0, 0.f), fmaxf(cAc[3] + bi1, 0.f));
            sH1w[gid * SH2_STRIDE + cp] =
                h2bits(fmaxf(cBc[0] + bi0, 0.f), fmaxf(cBc[1] + bi1, 0.f));
            sH1w[(gid + 8) * SH2_STRIDE + cp] =
                h2bits(fmaxf(cBc[2] + bi0, 0.f), fmaxf(cBc[3] + bi1, 0.f));
        }
        __syncwarp();

        unsigned ah0[8][4], ah1[8][4];
#pragma unroll
        for (int kk = 0; kk < 8; kk++) {
            int kc = kk * 8;
            ah0[kk][0] = sH0w[gid * SH2_STRIDE + kc + tig];
            ah0[kk][1] = sH0w[(gid + 8) * SH2_STRIDE + kc + tig];
            ah0[kk][2] = sH0w[gid * SH2_STRIDE + kc + tig + 4];
            ah0[kk][3] = sH0w[(gid + 8) * SH2_STRIDE + kc + tig + 4];
            ah1[kk][0] = sH1w[gid * SH2_STRIDE + kc + tig];
            ah1[kk][1] = sH1w[(gid + 8) * SH2_STRIDE + kc + tig];
            ah1[kk][2] = sH1w[gid * SH2_STRIDE + kc + tig + 4];
            ah1[kk][3] = sH1w[(gid + 8) * SH2_STRIDE + kc + tig + 4];
        }

        float* o00 = outp + (s0 * 16 + gid) * CD;
        float* o01 = outp + (s0 * 16 + gid + 8) * CD;
        float* o10 = outp + ((s0 + 1) * 16 + gid) * CD;
        float* o11 = outp + ((s0 + 1) * 16 + gid + 8) * CD;
#pragma unroll
        for (int j = 0; j < 8; j++) {
            float cAc[4] = {0.f, 0.f, 0.f, 0.f};
            float cBc[4] = {0.f, 0.f, 0.f, 0.f};
#pragma unroll
            for (int kk = 0; kk < 8; kk++) {
                uint2 b = *reinterpret_cast<const uint2*>(
                    &sW2f[((j * 8 + kk) * 32 + lane) * 2]);
                mma_f16(cAc, ah0[kk], b.x, b.y);
                mma_f16(cBc, ah1[kk], b.x, b.y);
            }
            const int col = j * 8 + 2 * tig;
            const float bi0 = sb2[col], bi1 = sb2[col + 1];
            *reinterpret_cast<float2*>(o00 + col) =
                make_float2(fmaxf(cAc[0] + bi0, 0.f), fmaxf(cAc[1] + bi1, 0.f));
            *reinterpret_cast<float2*>(o01 + col) =
                make_float2(fmaxf(cAc[2] + bi0, 0.f), fmaxf(cAc[3] + bi1, 0.f));
            *reinterpret_cast<float2*>(o10 + col) =
                make_float2(fmaxf(cBc[0] + bi0, 0.f), fmaxf(cBc[1] + bi1, 0.f));
            *reinterpret_cast<float2*>(o11 + col) =
                make_float2(fmaxf(cBc[2] + bi0, 0.f), fmaxf(cBc[3] + bi1, 0.f));
        }

        pair = nextPair;
    }
}

// ---------------------------------------------------------------------------
// Launch
// Inputs (metadata order):
//  0 atom_repr [N,64] f32     1 src [E] i32      2 dst [E] i32
//  3 r_dir     4 r_type       5 r_ring           6 p_dir
//  7 p_type    8 p_ring       9 r_len f32       10 p_len f32
// 11 emb_dir [8,32]          12 emb_type [16,32] 13 emb_ring [4,32]
// 14 rbf_W [20,32]           15 rbf_b [32]
// 16 W1 [64,128]             17 b1 [128]
// 18 W2 [128,64]             19 b2 [64]
// Output: [N,64] f32
// ---------------------------------------------------------------------------
extern "C" void kernel_launch(void* const* d_in, const int* in_sizes, int n_in,
                              void* d_out, int out_size) {
    const float* atom     = (const float*)d_in[0];
    const int*   src      = (const int*)d_in[1];
    const int*   dst      = (const int*)d_in[2];
    const int*   rdir     = (const int*)d_in[3];
    const int*   rtype    = (const int*)d_in[4];
    const int*   rring    = (const int*)d_in[5];
    const int*   pdir     = (const int*)d_in[6];
    const int*   ptype    = (const int*)d_in[7];
    const int*   pring    = (const int*)d_in[8];
    const float* rlen     = (const float*)d_in[9];
    const float* plen     = (const float*)d_in[10];
    const float* emb_dir  = (const float*)d_in[11];
    const float* emb_type = (const float*)d_in[12];
    const float* emb_ring = (const float*)d_in[13];
    const float* rbf_W    = (const float*)d_in[14];
    const float* rbf_b    = (const float*)d_in[15];
    const float* W1       = (const float*)d_in[16];
    const float* b1       = (const float*)d_in[17];
    const float* W2       = (const float*)d_in[18];
    const float* b2       = (const float*)d_in[19];
    float* out = (float*)d_out;

    // 0) fused prep: zero fp16 agg + pack metadata + ct/tab tables
    prep_kernel<<<2048, 256>>>(rdir, rtype, rring, pdir, ptype, pring,
                               rlen, plen, emb_dir, emb_type, emb_ring,
                               rbf_W, rbf_b);

    // 1) edge scatter (8 lanes/edge, 2-stage pipelined fp16 vector atomics)
    edge_kernel<<<2368, 256>>>(atom, src, dst);

    // 2) persistent strip-pair FP16 tensor-core MLP (hagg -> d_out)
    size_t smem = (size_t)(4096 + 4096 + HID + CD
                           + 8 * 16 * SA2_STRIDE
                           + 8 * 2 * 16 * SH2_STRIDE) * 4;
    cudaFuncSetAttribute(mlp_kernel, cudaFuncAttributeMaxDynamicSharedMemorySize,
                         (int)smem);
    mlp_kernel<<<148, 256, smem>>>(out, W1, b1, W2, b2);
}